// round 3
// baseline (speedup 1.0000x reference)
#include <cuda_runtime.h>
#include <cuda_bf16.h>
#include <cstdint>

// ---------------------------------------------------------------------------
// Problem constants
// ---------------------------------------------------------------------------
#define BATCH 2
#define SEQ   4096
#define DIM   1024
#define NHEAD 16
#define HDIM  64
#define NBLK  64          // SEQ / 64
#define QKV_N 3072        // 3 * DIM

// Scratch (no cudaMalloc allowed)
__device__ float g_qkv[(size_t)BATCH * SEQ * QKV_N];   // 100 MB
__device__ float g_attn[(size_t)BATCH * SEQ * DIM];    // 32 MB

// ---------------------------------------------------------------------------
// SGEMM: C[M,N] = A[M,K] * B[K,N] + bias[N]   (row-major, fp32)
// 128x128 tile, BK=8, 256 threads, 8x8 micro-tile, reg-prefetch pipeline.
// ---------------------------------------------------------------------------
__global__ __launch_bounds__(256) void sgemm_bias(
    const float* __restrict__ A, const float* __restrict__ B,
    const float* __restrict__ bias, float* __restrict__ C,
    int M, int N, int K)
{
    __shared__ float As[8][128];
    __shared__ float Bs[8][128];

    const int tid  = threadIdx.x;
    const int brow = blockIdx.y;
    const int bcol = blockIdx.x;

    const float* Ab = A + (size_t)brow * 128 * K;
    const float* Bb = B + (size_t)bcol * 128;

    const int arow   = tid >> 1;          // 0..127
    const int acol   = (tid & 1) * 4;     // 0 or 4
    const int brow_l = tid >> 5;          // 0..7
    const int bcol_l = (tid & 31) * 4;    // 0..124

    const int tr = tid >> 4;              // 0..15
    const int tc = tid & 15;              // 0..15

    float acc[8][8];
    #pragma unroll
    for (int i = 0; i < 8; i++)
        #pragma unroll
        for (int j = 0; j < 8; j++)
            acc[i][j] = 0.0f;

    // Prologue: load first K-slice into registers
    float4 av = *(const float4*)(Ab + (size_t)arow * K + acol);
    float4 bv = *(const float4*)(Bb + (size_t)brow_l * N + bcol_l);

    for (int k0 = 0; k0 < K; k0 += 8) {
        // Commit prefetched slice to smem
        As[acol + 0][arow] = av.x;
        As[acol + 1][arow] = av.y;
        As[acol + 2][arow] = av.z;
        As[acol + 3][arow] = av.w;
        *(float4*)(&Bs[brow_l][bcol_l]) = bv;
        __syncthreads();

        // Prefetch next slice (registers) while computing on current
        if (k0 + 8 < K) {
            av = *(const float4*)(Ab + (size_t)arow * K + k0 + 8 + acol);
            bv = *(const float4*)(Bb + (size_t)(k0 + 8 + brow_l) * N + bcol_l);
        }

        #pragma unroll
        for (int k = 0; k < 8; k++) {
            float ra[8], rb[8];
            *(float4*)(ra)     = *(const float4*)(&As[k][tr * 8]);
            *(float4*)(ra + 4) = *(const float4*)(&As[k][tr * 8 + 4]);
            *(float4*)(rb)     = *(const float4*)(&Bs[k][tc * 8]);
            *(float4*)(rb + 4) = *(const float4*)(&Bs[k][tc * 8 + 4]);
            #pragma unroll
            for (int i = 0; i < 8; i++)
                #pragma unroll
                for (int j = 0; j < 8; j++)
                    acc[i][j] += ra[i] * rb[j];
        }
        __syncthreads();
    }

    // Epilogue: add bias, vectorized stores
    float4 bz0 = *(const float4*)(bias + (size_t)bcol * 128 + tc * 8);
    float4 bz1 = *(const float4*)(bias + (size_t)bcol * 128 + tc * 8 + 4);
    #pragma unroll
    for (int i = 0; i < 8; i++) {
        size_t row = (size_t)brow * 128 + tr * 8 + i;
        float* Cp = C + row * N + (size_t)bcol * 128 + tc * 8;
        float4 v0, v1;
        v0.x = acc[i][0] + bz0.x; v0.y = acc[i][1] + bz0.y;
        v0.z = acc[i][2] + bz0.z; v0.w = acc[i][3] + bz0.w;
        v1.x = acc[i][4] + bz1.x; v1.y = acc[i][5] + bz1.y;
        v1.z = acc[i][6] + bz1.z; v1.w = acc[i][7] + bz1.w;
        *(float4*)(Cp)     = v0;
        *(float4*)(Cp + 4) = v1;
    }
}

// ---------------------------------------------------------------------------
// Attention kernel: one block per (n, h, b).
// 64 queries (rows mapping[n*64+m]) x 64 keys (rows mapping[seg*256+4s]).
// NOTE the reference's nonstandard softmax: the max is over the QUERY axis
// (per key-column), and it does NOT cancel in the row normalization:
//   e[m,s] = exp(score[m,s] - max_m' score[m',s])
//   out[m] = (e @ V) / (1e-6 + sum_s e[m,s])
// Padded smem (stride 65) => conflict-free.
// ---------------------------------------------------------------------------
#define TILE_STRIDE 65
#define TILE_FLOATS (64 * TILE_STRIDE)
#define ATTN_SMEM_BYTES ((4 * TILE_FLOATS + 128) * 4)

__global__ __launch_bounds__(256) void attn_kernel(
    const float* __restrict__ qkv, const int* __restrict__ mapping,
    float* __restrict__ attn_out)
{
    extern __shared__ float sm[];
    float* Qs   = sm;
    float* Ks   = sm + TILE_FLOATS;
    float* Vs   = sm + 2 * TILE_FLOATS;
    float* Ss   = sm + 3 * TILE_FLOATS;
    float* cmax = sm + 4 * TILE_FLOATS;        // [64] per-key column max
    float* lsum = sm + 4 * TILE_FLOATS + 64;   // [64] per-query row sum

    __shared__ int qrow[64];
    __shared__ int krow[64];

    const int t = threadIdx.x;
    const int n = blockIdx.x;
    const int h = blockIdx.y;
    const int b = blockIdx.z;

    if (t < 64) qrow[t] = mapping[n * 64 + t];
    __syncthreads();
    if (t < 64) {
        int seg = qrow[0] >> 8;                 // mapping[n*64] / 256
        krow[t] = mapping[seg * 256 + t * 4];   // DIL = 4
    }
    __syncthreads();

    const float scale = 0.125f;                 // 1/sqrt(64)
    const size_t base_b = (size_t)b * SEQ * QKV_N;
    const int hoff = h * HDIM;

    // Load Q (prescaled), K, V tiles (coalesced over d)
    for (int i = t; i < 64 * 64; i += 256) {
        int m = i >> 6, d = i & 63;
        Qs[m * TILE_STRIDE + d] = qkv[base_b + (size_t)qrow[m] * QKV_N + hoff + d] * scale;
        Ks[m * TILE_STRIDE + d] = qkv[base_b + (size_t)krow[m] * QKV_N + 1024 + hoff + d];
        Vs[m * TILE_STRIDE + d] = qkv[base_b + (size_t)krow[m] * QKV_N + 2048 + hoff + d];
    }
    __syncthreads();

    // Scores: thread t handles row m = t/4, 16 keys starting at (t%4)*16
    {
        int m = t >> 2, s0 = (t & 3) * 16;
        float sc[16];
        #pragma unroll
        for (int s = 0; s < 16; s++) {
            float a = 0.0f;
            #pragma unroll
            for (int d = 0; d < 64; d++)
                a += Qs[m * TILE_STRIDE + d] * Ks[(s0 + s) * TILE_STRIDE + d];
            sc[s] = a;
        }
        #pragma unroll
        for (int s = 0; s < 16; s++)
            Ss[m * TILE_STRIDE + s0 + s] = sc[s];
    }
    __syncthreads();

    // Column max over queries: thread t<64 handles key column s=t
    if (t < 64) {
        float mx = -1e30f;
        #pragma unroll
        for (int m = 0; m < 64; m++)
            mx = fmaxf(mx, Ss[m * TILE_STRIDE + t]);
        cmax[t] = mx;
    }
    __syncthreads();

    // Row-wise exp against COLUMN max, plus row sum: thread t<64 = row m=t
    if (t < 64) {
        float sum = 0.0f;
        #pragma unroll
        for (int s = 0; s < 64; s++) {
            float e = __expf(Ss[t * TILE_STRIDE + s] - cmax[s]);
            Ss[t * TILE_STRIDE + s] = e;
            sum += e;
        }
        lsum[t] = 1e-6f + sum;
    }
    __syncthreads();

    // Output: thread t handles row m = t/4, 16 dims starting at (t%4)*16
    {
        int m = t >> 2, d0 = (t & 3) * 16;
        float acc[16];
        #pragma unroll
        for (int j = 0; j < 16; j++) acc[j] = 0.0f;
        #pragma unroll
        for (int s = 0; s < 64; s++) {
            float p = Ss[m * TILE_STRIDE + s];
            #pragma unroll
            for (int j = 0; j < 16; j++)
                acc[j] += p * Vs[s * TILE_STRIDE + d0 + j];
        }
        float inv = 1.0f / lsum[m];
        size_t orow = ((size_t)b * SEQ + n * 64 + m) * DIM + hoff + d0;
        #pragma unroll
        for (int j = 0; j < 16; j++)
            attn_out[orow + j] = acc[j] * inv;
    }
}

// ---------------------------------------------------------------------------
// Launch
// ---------------------------------------------------------------------------
extern "C" void kernel_launch(void* const* d_in, const int* in_sizes, int n_in,
                              void* d_out, int out_size)
{
    const float* x     = (const float*)d_in[0];
    const float* Wqkv  = (const float*)d_in[1];
    const float* bqkv  = (const float*)d_in[2];
    const float* Wproj = (const float*)d_in[3];
    const float* bproj = (const float*)d_in[4];
    const int*   mapping = (const int*)d_in[5];
    float* out = (float*)d_out;

    float *qkv, *attn;
    cudaGetSymbolAddress((void**)&qkv, g_qkv);
    cudaGetSymbolAddress((void**)&attn, g_attn);
    cudaFuncSetAttribute(attn_kernel,
                         cudaFuncAttributeMaxDynamicSharedMemorySize,
                         ATTN_SMEM_BYTES);

    // 1) QKV projection: (8192 x 1024) @ (1024 x 3072) + bqkv
    sgemm_bias<<<dim3(QKV_N / 128, (BATCH * SEQ) / 128), 256>>>(
        x, Wqkv, bqkv, qkv, BATCH * SEQ, QKV_N, DIM);

    // 2) Hilbert block attention
    attn_kernel<<<dim3(NBLK, NHEAD, BATCH), 256, ATTN_SMEM_BYTES>>>(
        qkv, mapping, attn);

    // 3) Output projection: (8192 x 1024) @ (1024 x 1024) + bproj
    sgemm_bias<<<dim3(DIM / 128, (BATCH * SEQ) / 128), 256>>>(
        attn, Wproj, bproj, out, BATCH * SEQ, DIM, DIM);
}

// round 6
// speedup vs baseline: 1.7796x; 1.7796x over previous
#include <cuda_runtime.h>
#include <cuda_bf16.h>
#include <cstdint>

// ---------------------------------------------------------------------------
// Problem constants
// ---------------------------------------------------------------------------
#define BATCH 2
#define SEQ   4096
#define DIM   1024
#define NHEAD 16
#define HDIM  64
#define NBLK  64
#define QKV_N 3072
#define MROWS (BATCH * SEQ)          // 8192

// ---------------------------------------------------------------------------
// Scratch (static device globals; no cudaMalloc allowed)
// ---------------------------------------------------------------------------
__device__ float g_qkv[(size_t)MROWS * QKV_N];            // 100 MB
__device__ float g_attn[(size_t)MROWS * DIM];             // 32 MB
__device__ __nv_bfloat16 g_ahi[(size_t)MROWS * DIM];      // x / attn split hi
__device__ __nv_bfloat16 g_alo[(size_t)MROWS * DIM];      // x / attn split lo
__device__ __nv_bfloat16 g_wqT_hi[(size_t)QKV_N * DIM];   // Wqkv^T hi  [N][K]
__device__ __nv_bfloat16 g_wqT_lo[(size_t)QKV_N * DIM];
__device__ __nv_bfloat16 g_wpT_hi[(size_t)DIM * DIM];     // Wproj^T hi [N][K]
__device__ __nv_bfloat16 g_wpT_lo[(size_t)DIM * DIM];

// ---------------------------------------------------------------------------
// Warp-MMA helpers (baseline compute_100-safe PTX: ldmatrix + mma.sync)
// ---------------------------------------------------------------------------
__device__ __forceinline__ uint32_t smem_u32(const void* p) {
    uint32_t a;
    asm("{ .reg .u64 t; cvta.to.shared.u64 t, %1; cvt.u32.u64 %0, t; }"
        : "=r"(a) : "l"(p));
    return a;
}

#define LDSM_X4(r0, r1, r2, r3, addr)                                         \
    asm volatile("ldmatrix.sync.aligned.m8n8.x4.shared.b16 {%0,%1,%2,%3}, [%4];" \
                 : "=r"(r0), "=r"(r1), "=r"(r2), "=r"(r3) : "r"(addr))

#define MMA16816(c, a0, a1, a2, a3, b0, b1)                                   \
    asm volatile("mma.sync.aligned.m16n8k16.row.col.f32.bf16.bf16.f32 "       \
                 "{%0,%1,%2,%3}, {%4,%5,%6,%7}, {%8,%9}, {%0,%1,%2,%3};"      \
                 : "+f"((c)[0]), "+f"((c)[1]), "+f"((c)[2]), "+f"((c)[3])     \
                 : "r"(a0), "r"(a1), "r"(a2), "r"(a3), "r"(b0), "r"(b1))

// ---------------------------------------------------------------------------
// bf16x3 tensor-core GEMM:
//   C[M,N] = (Ahi+Alo)[M,K] * (BThi+BTlo)[N,K]^T + bias[N]
//   3 MMA passes per chunk: Ah*Bh + Ah*Bl + Al*Bh (fp32 accumulators).
// Block 128x128, BK=32, 8 warps (4 x 2), warp tile 32x64.
// Smem tiles padded to 40 bf16 (80 B) row stride -> conflict-free ldmatrix.
// ---------------------------------------------------------------------------
#define GBM 128
#define GBN 128
#define GBK 32
#define SP 40                       // padded row stride in bf16
#define TILE_B (128 * SP * 2)       // 10240 bytes per tile
#define BUF_B  (4 * TILE_B)         // Ah, Al, Bh, Bl
#define GEMM_SMEM (2 * BUF_B)       // 81920 bytes

__global__ __launch_bounds__(256, 1) void gemm_bf16x3(
    const __nv_bfloat16* __restrict__ Ahi, const __nv_bfloat16* __restrict__ Alo,
    const __nv_bfloat16* __restrict__ BThi, const __nv_bfloat16* __restrict__ BTlo,
    const float* __restrict__ bias, float* __restrict__ C,
    int M, int N, int K)
{
    extern __shared__ char smem[];
    const uint32_t sb = smem_u32(smem);

    const int tid  = threadIdx.x;
    const int wid  = tid >> 5;
    const int lane = tid & 31;
    const int warp_m = wid & 3;          // 0..3  (32 rows each)
    const int warp_n = wid >> 2;         // 0..1  (64 cols each)
    const int m0 = blockIdx.y * GBM;
    const int n0 = blockIdx.x * GBN;

    const __nv_bfloat16* bases[4] = { Ahi, Alo, BThi, BTlo };

    float acc[2][8][4];
    #pragma unroll
    for (int i = 0; i < 2; i++)
        #pragma unroll
        for (int j = 0; j < 8; j++)
            #pragma unroll
            for (int q = 0; q < 4; q++)
                acc[i][j][q] = 0.0f;

    // per-thread load map: for each tile, 2 x uint4 (8 bf16 along k)
    // idx = tid*2+u in [0,512): row = idx>>2, c4 = idx&3
    uint4 v[4][2];

#define LOADR(k0) do {                                                        \
    _Pragma("unroll")                                                         \
    for (int arr = 0; arr < 4; arr++) {                                       \
        _Pragma("unroll")                                                     \
        for (int u = 0; u < 2; u++) {                                         \
            int idx = tid * 2 + u;                                            \
            int r = idx >> 2, c4 = idx & 3;                                   \
            int row0 = (arr < 2) ? m0 : n0;                                   \
            v[arr][u] = *(const uint4*)(bases[arr] +                          \
                (size_t)(row0 + r) * K + (k0) + c4 * 8);                      \
        }                                                                     \
    } } while (0)

#define STORES(buf) do {                                                      \
    _Pragma("unroll")                                                         \
    for (int arr = 0; arr < 4; arr++) {                                       \
        _Pragma("unroll")                                                     \
        for (int u = 0; u < 2; u++) {                                         \
            int idx = tid * 2 + u;                                            \
            int r = idx >> 2, c4 = idx & 3;                                   \
            *(uint4*)(smem + (buf) * BUF_B + arr * TILE_B + r * (SP * 2) +    \
                      c4 * 16) = v[arr][u];                                   \
        }                                                                     \
    } } while (0)

    // ldmatrix lane addressing (within current buffer)
    const int a_lrow = (lane & 7) + ((lane >> 3) & 1) * 8;  // row within 16
    const int a_lcol = ((lane >> 4) & 1) * 8;               // k offset within 16
    const int b_lrow = (lane & 7) + ((lane >> 4) & 1) * 8;  // n within 16
    const int b_lcol = ((lane >> 3) & 1) * 8;               // k offset within 16

    const int niter = K / GBK;

    LOADR(0);
    STORES(0);
    __syncthreads();

    for (int it = 0; it < niter; it++) {
        const uint32_t bufb = sb + (it & 1) * BUF_B;

        if (it + 1 < niter) LOADR((it + 1) * GBK);

        #pragma unroll
        for (int ks = 0; ks < 2; ks++) {
            uint32_t ah[2][4], al[2][4], bh[8][2], bl[8][2];

            // A fragments (hi)
            #pragma unroll
            for (int i = 0; i < 2; i++) {
                int arow = warp_m * 32 + i * 16 + a_lrow;
                uint32_t ad = bufb + 0 * TILE_B +
                              arow * (SP * 2) + (ks * 16 + a_lcol) * 2;
                LDSM_X4(ah[i][0], ah[i][1], ah[i][2], ah[i][3], ad);
            }
            // B fragments (hi): x4 covers 2 n-tiles
            #pragma unroll
            for (int jp = 0; jp < 4; jp++) {
                int nrow = warp_n * 64 + jp * 16 + b_lrow;
                uint32_t bd = bufb + 2 * TILE_B +
                              nrow * (SP * 2) + (ks * 16 + b_lcol) * 2;
                LDSM_X4(bh[jp * 2][0], bh[jp * 2][1],
                        bh[jp * 2 + 1][0], bh[jp * 2 + 1][1], bd);
            }
            // pass 1: Ah * Bh
            #pragma unroll
            for (int i = 0; i < 2; i++)
                #pragma unroll
                for (int j = 0; j < 8; j++)
                    MMA16816(acc[i][j], ah[i][0], ah[i][1], ah[i][2], ah[i][3],
                             bh[j][0], bh[j][1]);

            // B fragments (lo)
            #pragma unroll
            for (int jp = 0; jp < 4; jp++) {
                int nrow = warp_n * 64 + jp * 16 + b_lrow;
                uint32_t bd = bufb + 3 * TILE_B +
                              nrow * (SP * 2) + (ks * 16 + b_lcol) * 2;
                LDSM_X4(bl[jp * 2][0], bl[jp * 2][1],
                        bl[jp * 2 + 1][0], bl[jp * 2 + 1][1], bd);
            }
            // pass 2: Ah * Bl
            #pragma unroll
            for (int i = 0; i < 2; i++)
                #pragma unroll
                for (int j = 0; j < 8; j++)
                    MMA16816(acc[i][j], ah[i][0], ah[i][1], ah[i][2], ah[i][3],
                             bl[j][0], bl[j][1]);

            // A fragments (lo)
            #pragma unroll
            for (int i = 0; i < 2; i++) {
                int arow = warp_m * 32 + i * 16 + a_lrow;
                uint32_t ad = bufb + 1 * TILE_B +
                              arow * (SP * 2) + (ks * 16 + a_lcol) * 2;
                LDSM_X4(al[i][0], al[i][1], al[i][2], al[i][3], ad);
            }
            // pass 3: Al * Bh
            #pragma unroll
            for (int i = 0; i < 2; i++)
                #pragma unroll
                for (int j = 0; j < 8; j++)
                    MMA16816(acc[i][j], al[i][0], al[i][1], al[i][2], al[i][3],
                             bh[j][0], bh[j][1]);
        }

        if (it + 1 < niter) {
            STORES((it + 1) & 1);
            __syncthreads();
        }
    }

    // Epilogue: bias + store (fragment layout: c0,c1 row g cols t*2,t*2+1; c2,c3 row g+8)
    const int g  = lane >> 2;
    const int tq = lane & 3;
    #pragma unroll
    for (int i = 0; i < 2; i++) {
        #pragma unroll
        for (int j = 0; j < 8; j++) {
            int col = n0 + warp_n * 64 + j * 8 + tq * 2;
            float2 bz = *(const float2*)(bias + col);
            int row_a = m0 + warp_m * 32 + i * 16 + g;
            float2 o0 = { acc[i][j][0] + bz.x, acc[i][j][1] + bz.y };
            float2 o1 = { acc[i][j][2] + bz.x, acc[i][j][3] + bz.y };
            *(float2*)(C + (size_t)row_a * N + col) = o0;
            *(float2*)(C + (size_t)(row_a + 8) * N + col) = o1;
        }
    }
#undef LOADR
#undef STORES
}

// ---------------------------------------------------------------------------
// Prepass: elementwise fp32 -> (hi, lo) bf16 split
// ---------------------------------------------------------------------------
__global__ __launch_bounds__(256) void split_bf16(
    const float* __restrict__ in, __nv_bfloat16* __restrict__ hi,
    __nv_bfloat16* __restrict__ lo, int n4)
{
    int i = blockIdx.x * 256 + threadIdx.x;
    if (i >= n4) return;
    float4 x = ((const float4*)in)[i];
    __nv_bfloat16 hx = __float2bfloat16(x.x), hy = __float2bfloat16(x.y);
    __nv_bfloat16 hz = __float2bfloat16(x.z), hw = __float2bfloat16(x.w);
    __nv_bfloat16 lx = __float2bfloat16(x.x - __bfloat162float(hx));
    __nv_bfloat16 ly = __float2bfloat16(x.y - __bfloat162float(hy));
    __nv_bfloat16 lz = __float2bfloat16(x.z - __bfloat162float(hz));
    __nv_bfloat16 lw = __float2bfloat16(x.w - __bfloat162float(hw));
    ((__nv_bfloat162*)hi)[i * 2]     = __nv_bfloat162(hx, hy);
    ((__nv_bfloat162*)hi)[i * 2 + 1] = __nv_bfloat162(hz, hw);
    ((__nv_bfloat162*)lo)[i * 2]     = __nv_bfloat162(lx, ly);
    ((__nv_bfloat162*)lo)[i * 2 + 1] = __nv_bfloat162(lz, lw);
}

// ---------------------------------------------------------------------------
// Prepass: W[K][N] fp32 -> W^T hi/lo [N][K] bf16 (32x32 smem transpose)
// ---------------------------------------------------------------------------
__global__ __launch_bounds__(256) void transpose_split(
    const float* __restrict__ W, __nv_bfloat16* __restrict__ hiT,
    __nv_bfloat16* __restrict__ loT, int K, int N)
{
    __shared__ float t[32][33];
    const int kb = blockIdx.y * 32, nb = blockIdx.x * 32;
    const int tx = threadIdx.x, ty = threadIdx.y;
    #pragma unroll
    for (int s = 0; s < 32; s += 8)
        t[ty + s][tx] = W[(size_t)(kb + ty + s) * N + nb + tx];
    __syncthreads();
    #pragma unroll
    for (int s = 0; s < 32; s += 8) {
        int nn = nb + ty + s, kk = kb + tx;
        float vv = t[tx][ty + s];
        __nv_bfloat16 h = __float2bfloat16(vv);
        hiT[(size_t)nn * K + kk] = h;
        loT[(size_t)nn * K + kk] = __float2bfloat16(vv - __bfloat162float(h));
    }
}

// ---------------------------------------------------------------------------
// Attention kernel (column-max softmax; validated Round 3)
// ---------------------------------------------------------------------------
#define TILE_STRIDE 65
#define TILE_FLOATS (64 * TILE_STRIDE)
#define ATTN_SMEM_BYTES ((4 * TILE_FLOATS + 128) * 4)

__global__ __launch_bounds__(256) void attn_kernel(
    const float* __restrict__ qkv, const int* __restrict__ mapping,
    float* __restrict__ attn_out)
{
    extern __shared__ float sm[];
    float* Qs   = sm;
    float* Ks   = sm + TILE_FLOATS;
    float* Vs   = sm + 2 * TILE_FLOATS;
    float* Ss   = sm + 3 * TILE_FLOATS;
    float* cmax = sm + 4 * TILE_FLOATS;
    float* lsum = sm + 4 * TILE_FLOATS + 64;

    __shared__ int qrow[64];
    __shared__ int krow[64];

    const int t = threadIdx.x;
    const int n = blockIdx.x;
    const int h = blockIdx.y;
    const int b = blockIdx.z;

    if (t < 64) qrow[t] = mapping[n * 64 + t];
    __syncthreads();
    if (t < 64) {
        int seg = qrow[0] >> 8;
        krow[t] = mapping[seg * 256 + t * 4];
    }
    __syncthreads();

    const float scale = 0.125f;
    const size_t base_b = (size_t)b * SEQ * QKV_N;
    const int hoff = h * HDIM;

    for (int i = t; i < 64 * 64; i += 256) {
        int m = i >> 6, d = i & 63;
        Qs[m * TILE_STRIDE + d] = qkv[base_b + (size_t)qrow[m] * QKV_N + hoff + d] * scale;
        Ks[m * TILE_STRIDE + d] = qkv[base_b + (size_t)krow[m] * QKV_N + 1024 + hoff + d];
        Vs[m * TILE_STRIDE + d] = qkv[base_b + (size_t)krow[m] * QKV_N + 2048 + hoff + d];
    }
    __syncthreads();

    {
        int m = t >> 2, s0 = (t & 3) * 16;
        float sc[16];
        #pragma unroll
        for (int s = 0; s < 16; s++) {
            float a = 0.0f;
            #pragma unroll
            for (int d = 0; d < 64; d++)
                a += Qs[m * TILE_STRIDE + d] * Ks[(s0 + s) * TILE_STRIDE + d];
            sc[s] = a;
        }
        #pragma unroll
        for (int s = 0; s < 16; s++)
            Ss[m * TILE_STRIDE + s0 + s] = sc[s];
    }
    __syncthreads();

    if (t < 64) {
        float mx = -1e30f;
        #pragma unroll
        for (int m = 0; m < 64; m++)
            mx = fmaxf(mx, Ss[m * TILE_STRIDE + t]);
        cmax[t] = mx;
    }
    __syncthreads();

    if (t < 64) {
        float sum = 0.0f;
        #pragma unroll
        for (int s = 0; s < 64; s++) {
            float e = __expf(Ss[t * TILE_STRIDE + s] - cmax[s]);
            Ss[t * TILE_STRIDE + s] = e;
            sum += e;
        }
        lsum[t] = 1e-6f + sum;
    }
    __syncthreads();

    {
        int m = t >> 2, d0 = (t & 3) * 16;
        float acc[16];
        #pragma unroll
        for (int j = 0; j < 16; j++) acc[j] = 0.0f;
        #pragma unroll
        for (int s = 0; s < 64; s++) {
            float p = Ss[m * TILE_STRIDE + s];
            #pragma unroll
            for (int j = 0; j < 16; j++)
                acc[j] += p * Vs[s * TILE_STRIDE + d0 + j];
        }
        float inv = 1.0f / lsum[m];
        size_t orow = ((size_t)b * SEQ + n * 64 + m) * DIM + hoff + d0;
        #pragma unroll
        for (int j = 0; j < 16; j++)
            attn_out[orow + j] = acc[j] * inv;
    }
}

// ---------------------------------------------------------------------------
// Launch
// ---------------------------------------------------------------------------
extern "C" void kernel_launch(void* const* d_in, const int* in_sizes, int n_in,
                              void* d_out, int out_size)
{
    const float* x     = (const float*)d_in[0];
    const float* Wqkv  = (const float*)d_in[1];
    const float* bqkv  = (const float*)d_in[2];
    const float* Wproj = (const float*)d_in[3];
    const float* bproj = (const float*)d_in[4];
    const int*   mapping = (const int*)d_in[5];
    float* out = (float*)d_out;

    float *qkv, *attn;
    __nv_bfloat16 *ahi, *alo, *wqh, *wql, *wph, *wpl;
    cudaGetSymbolAddress((void**)&qkv,  g_qkv);
    cudaGetSymbolAddress((void**)&attn, g_attn);
    cudaGetSymbolAddress((void**)&ahi,  g_ahi);
    cudaGetSymbolAddress((void**)&alo,  g_alo);
    cudaGetSymbolAddress((void**)&wqh,  g_wqT_hi);
    cudaGetSymbolAddress((void**)&wql,  g_wqT_lo);
    cudaGetSymbolAddress((void**)&wph,  g_wpT_hi);
    cudaGetSymbolAddress((void**)&wpl,  g_wpT_lo);

    cudaFuncSetAttribute(attn_kernel,
                         cudaFuncAttributeMaxDynamicSharedMemorySize, ATTN_SMEM_BYTES);
    cudaFuncSetAttribute(gemm_bf16x3,
                         cudaFuncAttributeMaxDynamicSharedMemorySize, GEMM_SMEM);

    const int n4 = MROWS * DIM / 4;

    // Prepasses
    split_bf16<<<(n4 + 255) / 256, 256>>>(x, ahi, alo, n4);
    transpose_split<<<dim3(QKV_N / 32, DIM / 32), dim3(32, 8)>>>(Wqkv, wqh, wql, DIM, QKV_N);
    transpose_split<<<dim3(DIM / 32, DIM / 32), dim3(32, 8)>>>(Wproj, wph, wpl, DIM, DIM);

    // 1) QKV projection (tensor cores, bf16x3)
    gemm_bf16x3<<<dim3(QKV_N / GBN, MROWS / GBM), 256, GEMM_SMEM>>>(
        ahi, alo, wqh, wql, bqkv, qkv, MROWS, QKV_N, DIM);

    // 2) Hilbert block attention (fp32)
    attn_kernel<<<dim3(NBLK, NHEAD, BATCH), 256, ATTN_SMEM_BYTES>>>(qkv, mapping, attn);

    // 3) Split attention output, then output projection (tensor cores)
    split_bf16<<<(n4 + 255) / 256, 256>>>(attn, ahi, alo, n4);
    gemm_bf16x3<<<dim3(DIM / GBN, MROWS / GBM), 256, GEMM_SMEM>>>(
        ahi, alo, wph, wpl, bproj, out, MROWS, DIM, DIM);
}

// round 7
// speedup vs baseline: 2.0939x; 1.1766x over previous
#include <cuda_runtime.h>
#include <cuda_bf16.h>
#include <cstdint>

// ---------------------------------------------------------------------------
// Problem constants
// ---------------------------------------------------------------------------
#define BATCH 2
#define SEQ   4096
#define DIM   1024
#define NHEAD 16
#define HDIM  64
#define NBLK  64
#define QKV_N 3072
#define MROWS (BATCH * SEQ)          // 8192

// ---------------------------------------------------------------------------
// Scratch (static device globals; no cudaMalloc allowed)
// ---------------------------------------------------------------------------
__device__ float g_qkv[(size_t)MROWS * QKV_N];
__device__ float g_attn[(size_t)MROWS * DIM];
__device__ __nv_bfloat16 g_ahi[(size_t)MROWS * DIM];
__device__ __nv_bfloat16 g_alo[(size_t)MROWS * DIM];
__device__ __nv_bfloat16 g_wqT_hi[(size_t)QKV_N * DIM];
__device__ __nv_bfloat16 g_wqT_lo[(size_t)QKV_N * DIM];
__device__ __nv_bfloat16 g_wpT_hi[(size_t)DIM * DIM];
__device__ __nv_bfloat16 g_wpT_lo[(size_t)DIM * DIM];

// ---------------------------------------------------------------------------
// Helpers (baseline compute_100-safe PTX)
// ---------------------------------------------------------------------------
__device__ __forceinline__ uint32_t smem_u32(const void* p) {
    uint32_t a;
    asm("{ .reg .u64 t; cvta.to.shared.u64 t, %1; cvt.u32.u64 %0, t; }"
        : "=r"(a) : "l"(p));
    return a;
}

#define LDSM_X4(r0, r1, r2, r3, addr)                                         \
    asm volatile("ldmatrix.sync.aligned.m8n8.x4.shared.b16 {%0,%1,%2,%3}, [%4];" \
                 : "=r"(r0), "=r"(r1), "=r"(r2), "=r"(r3) : "r"(addr))

#define MMA16816(c, a0, a1, a2, a3, b0, b1)                                   \
    asm volatile("mma.sync.aligned.m16n8k16.row.col.f32.bf16.bf16.f32 "       \
                 "{%0,%1,%2,%3}, {%4,%5,%6,%7}, {%8,%9}, {%0,%1,%2,%3};"      \
                 : "+f"((c)[0]), "+f"((c)[1]), "+f"((c)[2]), "+f"((c)[3])     \
                 : "r"(a0), "r"(a1), "r"(a2), "r"(a3), "r"(b0), "r"(b1))

#define CP_ASYNC16(sm, gm)                                                    \
    asm volatile("cp.async.cg.shared.global [%0], [%1], 16;"                  \
                 :: "r"(sm), "l"(gm))
#define CP_COMMIT()  asm volatile("cp.async.commit_group;" ::: "memory")
#define CP_WAIT0()   asm volatile("cp.async.wait_group 0;" ::: "memory")

// ---------------------------------------------------------------------------
// bf16x3 tensor-core GEMM:
//   C[M,N] = (Ahi+Alo)[M,K] * (BThi+BTlo)[N,K]^T + bias[N]
// Block 128x128, 128 threads (4 warps, 2x2), warp tile 64x64, BK=32.
// cp.async double-buffered smem; 3 MMA passes (Ah*Bh + Ah*Bl + Al*Bh).
// Padded 40-bf16 row stride => conflict-free ldmatrix.
// ---------------------------------------------------------------------------
#define GBM 128
#define GBN 128
#define GBK 32
#define SP 40
#define TILE_B (128 * SP * 2)       // 10240 B per tile
#define BUF_B  (4 * TILE_B)         // Ah, Al, Bh, Bl
#define GEMM_SMEM (2 * BUF_B)       // 81920 B

__global__ __launch_bounds__(128, 2) void gemm_bf16x3(
    const __nv_bfloat16* __restrict__ Ahi, const __nv_bfloat16* __restrict__ Alo,
    const __nv_bfloat16* __restrict__ BThi, const __nv_bfloat16* __restrict__ BTlo,
    const float* __restrict__ bias, float* __restrict__ C,
    int M, int N, int K)
{
    extern __shared__ char smem[];
    const uint32_t sb = smem_u32(smem);

    const int tid  = threadIdx.x;
    const int wid  = tid >> 5;
    const int lane = tid & 31;
    const int warp_m = wid & 1;          // 2 tiles of 64 rows
    const int warp_n = wid >> 1;         // 2 tiles of 64 cols
    const int m0 = blockIdx.y * GBM;
    const int n0 = blockIdx.x * GBN;

    const __nv_bfloat16* bases[4] = { Ahi, Alo, BThi, BTlo };

    float acc[4][8][4];
    #pragma unroll
    for (int i = 0; i < 4; i++)
        #pragma unroll
        for (int j = 0; j < 8; j++)
            #pragma unroll
            for (int q = 0; q < 4; q++)
                acc[i][j][q] = 0.0f;

    // cp.async map: per tile 512 16B-chunks; 128 threads x 4 passes
#define CPA_TILES(buf, k0) do {                                               \
    _Pragma("unroll")                                                         \
    for (int arr = 0; arr < 4; arr++) {                                       \
        int row0 = (arr < 2) ? m0 : n0;                                       \
        _Pragma("unroll")                                                     \
        for (int p = 0; p < 4; p++) {                                         \
            int idx = tid + 128 * p;                                          \
            int r = idx >> 2, c4 = idx & 3;                                   \
            uint32_t sa = sb + (buf) * BUF_B + arr * TILE_B +                 \
                          r * (SP * 2) + c4 * 16;                             \
            const __nv_bfloat16* ga = bases[arr] +                            \
                (size_t)(row0 + r) * K + (k0) + c4 * 8;                       \
            CP_ASYNC16(sa, ga);                                               \
        }                                                                     \
    } } while (0)

    const int a_lrow = (lane & 7) + ((lane >> 3) & 1) * 8;
    const int a_lcol = ((lane >> 4) & 1) * 8;
    const int b_lrow = (lane & 7) + ((lane >> 4) & 1) * 8;
    const int b_lcol = ((lane >> 3) & 1) * 8;

    const int niter = K / GBK;

    CPA_TILES(0, 0);
    CP_COMMIT();
    CP_WAIT0();
    __syncthreads();

    for (int it = 0; it < niter; it++) {
        const uint32_t bufb = sb + (it & 1) * BUF_B;

        if (it + 1 < niter) {
            CPA_TILES((it + 1) & 1, (it + 1) * GBK);
            CP_COMMIT();
        }

        #pragma unroll
        for (int ks = 0; ks < 2; ks++) {
            uint32_t ah[4][4], al[4][4], bh[8][2], bl[8][2];

            #pragma unroll
            for (int i = 0; i < 4; i++) {
                int arow = warp_m * 64 + i * 16 + a_lrow;
                uint32_t ad = bufb + 0 * TILE_B +
                              arow * (SP * 2) + (ks * 16 + a_lcol) * 2;
                LDSM_X4(ah[i][0], ah[i][1], ah[i][2], ah[i][3], ad);
            }
            #pragma unroll
            for (int jp = 0; jp < 4; jp++) {
                int nrow = warp_n * 64 + jp * 16 + b_lrow;
                uint32_t bd = bufb + 2 * TILE_B +
                              nrow * (SP * 2) + (ks * 16 + b_lcol) * 2;
                LDSM_X4(bh[jp * 2][0], bh[jp * 2][1],
                        bh[jp * 2 + 1][0], bh[jp * 2 + 1][1], bd);
            }
            // pass 1: Ah * Bh
            #pragma unroll
            for (int i = 0; i < 4; i++)
                #pragma unroll
                for (int j = 0; j < 8; j++)
                    MMA16816(acc[i][j], ah[i][0], ah[i][1], ah[i][2], ah[i][3],
                             bh[j][0], bh[j][1]);

            #pragma unroll
            for (int jp = 0; jp < 4; jp++) {
                int nrow = warp_n * 64 + jp * 16 + b_lrow;
                uint32_t bd = bufb + 3 * TILE_B +
                              nrow * (SP * 2) + (ks * 16 + b_lcol) * 2;
                LDSM_X4(bl[jp * 2][0], bl[jp * 2][1],
                        bl[jp * 2 + 1][0], bl[jp * 2 + 1][1], bd);
            }
            // pass 2: Ah * Bl
            #pragma unroll
            for (int i = 0; i < 4; i++)
                #pragma unroll
                for (int j = 0; j < 8; j++)
                    MMA16816(acc[i][j], ah[i][0], ah[i][1], ah[i][2], ah[i][3],
                             bl[j][0], bl[j][1]);

            #pragma unroll
            for (int i = 0; i < 4; i++) {
                int arow = warp_m * 64 + i * 16 + a_lrow;
                uint32_t ad = bufb + 1 * TILE_B +
                              arow * (SP * 2) + (ks * 16 + a_lcol) * 2;
                LDSM_X4(al[i][0], al[i][1], al[i][2], al[i][3], ad);
            }
            // pass 3: Al * Bh
            #pragma unroll
            for (int i = 0; i < 4; i++)
                #pragma unroll
                for (int j = 0; j < 8; j++)
                    MMA16816(acc[i][j], al[i][0], al[i][1], al[i][2], al[i][3],
                             bh[j][0], bh[j][1]);
        }

        if (it + 1 < niter) {
            CP_WAIT0();
            __syncthreads();
        }
    }

    // Epilogue: bias + store
    const int g  = lane >> 2;
    const int tq = lane & 3;
    #pragma unroll
    for (int i = 0; i < 4; i++) {
        #pragma unroll
        for (int j = 0; j < 8; j++) {
            int col = n0 + warp_n * 64 + j * 8 + tq * 2;
            float2 bz = *(const float2*)(bias + col);
            int row_a = m0 + warp_m * 64 + i * 16 + g;
            float2 o0 = { acc[i][j][0] + bz.x, acc[i][j][1] + bz.y };
            float2 o1 = { acc[i][j][2] + bz.x, acc[i][j][3] + bz.y };
            *(float2*)(C + (size_t)row_a * N + col) = o0;
            *(float2*)(C + (size_t)(row_a + 8) * N + col) = o1;
        }
    }
#undef CPA_TILES
}

// ---------------------------------------------------------------------------
// Prepass: elementwise fp32 -> (hi, lo) bf16 split
// ---------------------------------------------------------------------------
__global__ __launch_bounds__(256) void split_bf16(
    const float* __restrict__ in, __nv_bfloat16* __restrict__ hi,
    __nv_bfloat16* __restrict__ lo, int n4)
{
    int i = blockIdx.x * 256 + threadIdx.x;
    if (i >= n4) return;
    float4 x = ((const float4*)in)[i];
    __nv_bfloat16 hx = __float2bfloat16(x.x), hy = __float2bfloat16(x.y);
    __nv_bfloat16 hz = __float2bfloat16(x.z), hw = __float2bfloat16(x.w);
    __nv_bfloat16 lx = __float2bfloat16(x.x - __bfloat162float(hx));
    __nv_bfloat16 ly = __float2bfloat16(x.y - __bfloat162float(hy));
    __nv_bfloat16 lz = __float2bfloat16(x.z - __bfloat162float(hz));
    __nv_bfloat16 lw = __float2bfloat16(x.w - __bfloat162float(hw));
    ((__nv_bfloat162*)hi)[i * 2]     = __nv_bfloat162(hx, hy);
    ((__nv_bfloat162*)hi)[i * 2 + 1] = __nv_bfloat162(hz, hw);
    ((__nv_bfloat162*)lo)[i * 2]     = __nv_bfloat162(lx, ly);
    ((__nv_bfloat162*)lo)[i * 2 + 1] = __nv_bfloat162(lz, lw);
}

// ---------------------------------------------------------------------------
// Prepass: W[K][N] fp32 -> W^T hi/lo [N][K] bf16 (32x32 smem transpose)
// ---------------------------------------------------------------------------
__global__ __launch_bounds__(256) void transpose_split(
    const float* __restrict__ W, __nv_bfloat16* __restrict__ hiT,
    __nv_bfloat16* __restrict__ loT, int K, int N)
{
    __shared__ float t[32][33];
    const int kb = blockIdx.y * 32, nb = blockIdx.x * 32;
    const int tx = threadIdx.x, ty = threadIdx.y;
    #pragma unroll
    for (int s = 0; s < 32; s += 8)
        t[ty + s][tx] = W[(size_t)(kb + ty + s) * N + nb + tx];
    __syncthreads();
    #pragma unroll
    for (int s = 0; s < 32; s += 8) {
        int nn = nb + ty + s, kk = kb + tx;
        float vv = t[tx][ty + s];
        __nv_bfloat16 h = __float2bfloat16(vv);
        hiT[(size_t)nn * K + kk] = h;
        loT[(size_t)nn * K + kk] = __float2bfloat16(vv - __bfloat162float(h));
    }
}

// ---------------------------------------------------------------------------
// Attention kernel (column-max softmax; float4 gathers, full-width phases)
// ---------------------------------------------------------------------------
#define TILE_STRIDE 65
#define TILE_FLOATS (64 * TILE_STRIDE)
#define ATTN_SMEM_BYTES ((4 * TILE_FLOATS + 128) * 4)

__global__ __launch_bounds__(256) void attn_kernel(
    const float* __restrict__ qkv, const int* __restrict__ mapping,
    float* __restrict__ attn_out)
{
    extern __shared__ float sm[];
    float* Qs   = sm;
    float* Ks   = sm + TILE_FLOATS;
    float* Vs   = sm + 2 * TILE_FLOATS;
    float* Ss   = sm + 3 * TILE_FLOATS;
    float* cmax = sm + 4 * TILE_FLOATS;
    float* lsum = sm + 4 * TILE_FLOATS + 64;

    __shared__ int qrow[64];
    __shared__ int krow[64];

    const int t = threadIdx.x;
    const int n = blockIdx.x;
    const int h = blockIdx.y;
    const int b = blockIdx.z;

    if (t < 64) qrow[t] = mapping[n * 64 + t];
    __syncthreads();
    if (t < 64) {
        int seg = qrow[0] >> 8;
        krow[t] = mapping[seg * 256 + t * 4];
    }
    __syncthreads();

    const float scale = 0.125f;
    const size_t base_b = (size_t)b * SEQ * QKV_N;
    const int hoff = h * HDIM;

    // float4 gathers: 64x64 tile = 1024 float4 per array; 256 thr x 4 iters
    #pragma unroll
    for (int p = 0; p < 4; p++) {
        int idx = t + 256 * p;
        int m = idx >> 4, d = (idx & 15) * 4;
        float4 qv = *(const float4*)(qkv + base_b + (size_t)qrow[m] * QKV_N + hoff + d);
        float4 kv = *(const float4*)(qkv + base_b + (size_t)krow[m] * QKV_N + 1024 + hoff + d);
        float4 vv = *(const float4*)(qkv + base_b + (size_t)krow[m] * QKV_N + 2048 + hoff + d);
        float* qp = Qs + m * TILE_STRIDE + d;
        qp[0] = qv.x * scale; qp[1] = qv.y * scale;
        qp[2] = qv.z * scale; qp[3] = qv.w * scale;
        float* kp = Ks + m * TILE_STRIDE + d;
        kp[0] = kv.x; kp[1] = kv.y; kp[2] = kv.z; kp[3] = kv.w;
        float* vp = Vs + m * TILE_STRIDE + d;
        vp[0] = vv.x; vp[1] = vv.y; vp[2] = vv.z; vp[3] = vv.w;
    }
    __syncthreads();

    // Scores: thread t -> row m = t/4, 16 keys at (t%4)*16
    {
        int m = t >> 2, s0 = (t & 3) * 16;
        float sc[16];
        #pragma unroll
        for (int s = 0; s < 16; s++) {
            float a = 0.0f;
            #pragma unroll
            for (int d = 0; d < 64; d++)
                a += Qs[m * TILE_STRIDE + d] * Ks[(s0 + s) * TILE_STRIDE + d];
            sc[s] = a;
        }
        #pragma unroll
        for (int s = 0; s < 16; s++)
            Ss[m * TILE_STRIDE + s0 + s] = sc[s];
    }
    __syncthreads();

    // Column max over queries (full width): thread t -> col s = t/4, 16 rows
    {
        int s = t >> 2, mq0 = (t & 3) * 16;
        float mx = -1e30f;
        #pragma unroll
        for (int m = 0; m < 16; m++)
            mx = fmaxf(mx, Ss[(mq0 + m) * TILE_STRIDE + s]);
        mx = fmaxf(mx, __shfl_xor_sync(0xFFFFFFFF, mx, 1));
        mx = fmaxf(mx, __shfl_xor_sync(0xFFFFFFFF, mx, 2));
        if ((t & 3) == 0) cmax[s] = mx;
    }
    __syncthreads();

    // exp against COLUMN max + row sums (full width): thread t -> row m=t/4
    {
        int m = t >> 2, s0 = (t & 3) * 16;
        float sum = 0.0f;
        #pragma unroll
        for (int s = 0; s < 16; s++) {
            float e = __expf(Ss[m * TILE_STRIDE + s0 + s] - cmax[s0 + s]);
            Ss[m * TILE_STRIDE + s0 + s] = e;
            sum += e;
        }
        sum += __shfl_xor_sync(0xFFFFFFFF, sum, 1);
        sum += __shfl_xor_sync(0xFFFFFFFF, sum, 2);
        if ((t & 3) == 0) lsum[m] = 1e-6f + sum;
    }
    __syncthreads();

    // Output: thread t -> row m = t/4, 16 dims at (t%4)*16
    {
        int m = t >> 2, d0 = (t & 3) * 16;
        float acc[16];
        #pragma unroll
        for (int j = 0; j < 16; j++) acc[j] = 0.0f;
        #pragma unroll
        for (int s = 0; s < 64; s++) {
            float p = Ss[m * TILE_STRIDE + s];
            #pragma unroll
            for (int j = 0; j < 16; j++)
                acc[j] += p * Vs[s * TILE_STRIDE + d0 + j];
        }
        float inv = 1.0f / lsum[m];
        size_t orow = ((size_t)b * SEQ + n * 64 + m) * DIM + hoff + d0;
        #pragma unroll
        for (int j = 0; j < 16; j++)
            attn_out[orow + j] = acc[j] * inv;
    }
}

// ---------------------------------------------------------------------------
// Launch
// ---------------------------------------------------------------------------
extern "C" void kernel_launch(void* const* d_in, const int* in_sizes, int n_in,
                              void* d_out, int out_size)
{
    const float* x     = (const float*)d_in[0];
    const float* Wqkv  = (const float*)d_in[1];
    const float* bqkv  = (const float*)d_in[2];
    const float* Wproj = (const float*)d_in[3];
    const float* bproj = (const float*)d_in[4];
    const int*   mapping = (const int*)d_in[5];
    float* out = (float*)d_out;

    float *qkv, *attn;
    __nv_bfloat16 *ahi, *alo, *wqh, *wql, *wph, *wpl;
    cudaGetSymbolAddress((void**)&qkv,  g_qkv);
    cudaGetSymbolAddress((void**)&attn, g_attn);
    cudaGetSymbolAddress((void**)&ahi,  g_ahi);
    cudaGetSymbolAddress((void**)&alo,  g_alo);
    cudaGetSymbolAddress((void**)&wqh,  g_wqT_hi);
    cudaGetSymbolAddress((void**)&wql,  g_wqT_lo);
    cudaGetSymbolAddress((void**)&wph,  g_wpT_hi);
    cudaGetSymbolAddress((void**)&wpl,  g_wpT_lo);

    cudaFuncSetAttribute(attn_kernel,
                         cudaFuncAttributeMaxDynamicSharedMemorySize, ATTN_SMEM_BYTES);
    cudaFuncSetAttribute(gemm_bf16x3,
                         cudaFuncAttributeMaxDynamicSharedMemorySize, GEMM_SMEM);

    const int n4 = MROWS * DIM / 4;

    // Prepasses
    split_bf16<<<(n4 + 255) / 256, 256>>>(x, ahi, alo, n4);
    transpose_split<<<dim3(QKV_N / 32, DIM / 32), dim3(32, 8)>>>(Wqkv, wqh, wql, DIM, QKV_N);
    transpose_split<<<dim3(DIM / 32, DIM / 32), dim3(32, 8)>>>(Wproj, wph, wpl, DIM, DIM);

    // 1) QKV projection (tensor cores, bf16x3)
    gemm_bf16x3<<<dim3(QKV_N / GBN, MROWS / GBM), 128, GEMM_SMEM>>>(
        ahi, alo, wqh, wql, bqkv, qkv, MROWS, QKV_N, DIM);

    // 2) Hilbert block attention (fp32)
    attn_kernel<<<dim3(NBLK, NHEAD, BATCH), 256, ATTN_SMEM_BYTES>>>(qkv, mapping, attn);

    // 3) Split attention output, then output projection (tensor cores)
    split_bf16<<<(n4 + 255) / 256, 256>>>(attn, ahi, alo, n4);
    gemm_bf16x3<<<dim3(DIM / GBN, MROWS / GBM), 128, GEMM_SMEM>>>(
        ahi, alo, wph, wpl, bproj, out, MROWS, DIM, DIM);
}

// round 9
// speedup vs baseline: 2.8052x; 1.3397x over previous
#include <cuda_runtime.h>
#include <cuda_bf16.h>
#include <cstdint>

// ---------------------------------------------------------------------------
// Problem constants
// ---------------------------------------------------------------------------
#define BATCH 2
#define SEQ   4096
#define DIM   1024
#define NHEAD 16
#define HDIM  64
#define NBLK  64
#define QKV_N 3072
#define MROWS (BATCH * SEQ)          // 8192

// ---------------------------------------------------------------------------
// Scratch (static device globals; no cudaMalloc allowed)
// ---------------------------------------------------------------------------
__device__ float g_qkv[(size_t)MROWS * QKV_N];
__device__ __nv_bfloat16 g_ahi[(size_t)MROWS * DIM];
__device__ __nv_bfloat16 g_alo[(size_t)MROWS * DIM];
__device__ __nv_bfloat16 g_wqT_hi[(size_t)QKV_N * DIM];
__device__ __nv_bfloat16 g_wqT_lo[(size_t)QKV_N * DIM];
__device__ __nv_bfloat16 g_wpT_hi[(size_t)DIM * DIM];
__device__ __nv_bfloat16 g_wpT_lo[(size_t)DIM * DIM];

// ---------------------------------------------------------------------------
// Helpers (baseline compute_100-safe PTX)
// ---------------------------------------------------------------------------
__device__ __forceinline__ uint32_t smem_u32(const void* p) {
    uint32_t a;
    asm("{ .reg .u64 t; cvta.to.shared.u64 t, %1; cvt.u32.u64 %0, t; }"
        : "=r"(a) : "l"(p));
    return a;
}

#define LDSM_X4(r0, r1, r2, r3, addr)                                         \
    asm volatile("ldmatrix.sync.aligned.m8n8.x4.shared.b16 {%0,%1,%2,%3}, [%4];" \
                 : "=r"(r0), "=r"(r1), "=r"(r2), "=r"(r3) : "r"(addr))

#define MMA16816(c, a0, a1, a2, a3, b0, b1)                                   \
    asm volatile("mma.sync.aligned.m16n8k16.row.col.f32.bf16.bf16.f32 "       \
                 "{%0,%1,%2,%3}, {%4,%5,%6,%7}, {%8,%9}, {%0,%1,%2,%3};"      \
                 : "+f"((c)[0]), "+f"((c)[1]), "+f"((c)[2]), "+f"((c)[3])     \
                 : "r"(a0), "r"(a1), "r"(a2), "r"(a3), "r"(b0), "r"(b1))

#define CP_ASYNC16(sm, gm)                                                    \
    asm volatile("cp.async.cg.shared.global [%0], [%1], 16;"                  \
                 :: "r"(sm), "l"(gm))
#define CP_COMMIT()  asm volatile("cp.async.commit_group;" ::: "memory")
#define CP_WAIT0()   asm volatile("cp.async.wait_group 0;" ::: "memory")

// ---------------------------------------------------------------------------
// bf16x3 tensor-core GEMM (validated Round 7; unchanged)
//   C[M,N] = (Ahi+Alo)[M,K] * (BThi+BTlo)[N,K]^T + bias[N]
// ---------------------------------------------------------------------------
#define GBM 128
#define GBN 128
#define GBK 32
#define SP 40
#define TILE_B (128 * SP * 2)
#define BUF_B  (4 * TILE_B)
#define GEMM_SMEM (2 * BUF_B)       // 81920 B

__global__ __launch_bounds__(128, 2) void gemm_bf16x3(
    const __nv_bfloat16* __restrict__ Ahi, const __nv_bfloat16* __restrict__ Alo,
    const __nv_bfloat16* __restrict__ BThi, const __nv_bfloat16* __restrict__ BTlo,
    const float* __restrict__ bias, float* __restrict__ C,
    int M, int N, int K)
{
    extern __shared__ char smem[];
    const uint32_t sb = smem_u32(smem);

    const int tid  = threadIdx.x;
    const int wid  = tid >> 5;
    const int lane = tid & 31;
    const int warp_m = wid & 1;
    const int warp_n = wid >> 1;
    const int m0 = blockIdx.y * GBM;
    const int n0 = blockIdx.x * GBN;

    const __nv_bfloat16* bases[4] = { Ahi, Alo, BThi, BTlo };

    float acc[4][8][4];
    #pragma unroll
    for (int i = 0; i < 4; i++)
        #pragma unroll
        for (int j = 0; j < 8; j++)
            #pragma unroll
            for (int q = 0; q < 4; q++)
                acc[i][j][q] = 0.0f;

#define CPA_TILES(buf, k0) do {                                               \
    _Pragma("unroll")                                                         \
    for (int arr = 0; arr < 4; arr++) {                                       \
        int row0 = (arr < 2) ? m0 : n0;                                       \
        _Pragma("unroll")                                                     \
        for (int p = 0; p < 4; p++) {                                         \
            int idx = tid + 128 * p;                                          \
            int r = idx >> 2, c4 = idx & 3;                                   \
            uint32_t sa = sb + (buf) * BUF_B + arr * TILE_B +                 \
                          r * (SP * 2) + c4 * 16;                             \
            const __nv_bfloat16* ga = bases[arr] +                            \
                (size_t)(row0 + r) * K + (k0) + c4 * 8;                       \
            CP_ASYNC16(sa, ga);                                               \
        }                                                                     \
    } } while (0)

    const int a_lrow = (lane & 7) + ((lane >> 3) & 1) * 8;
    const int a_lcol = ((lane >> 4) & 1) * 8;
    const int b_lrow = (lane & 7) + ((lane >> 4) & 1) * 8;
    const int b_lcol = ((lane >> 3) & 1) * 8;

    const int niter = K / GBK;

    CPA_TILES(0, 0);
    CP_COMMIT();
    CP_WAIT0();
    __syncthreads();

    for (int it = 0; it < niter; it++) {
        const uint32_t bufb = sb + (it & 1) * BUF_B;

        if (it + 1 < niter) {
            CPA_TILES((it + 1) & 1, (it + 1) * GBK);
            CP_COMMIT();
        }

        #pragma unroll
        for (int ks = 0; ks < 2; ks++) {
            uint32_t ah[4][4], al[4][4], bh[8][2], bl[8][2];

            #pragma unroll
            for (int i = 0; i < 4; i++) {
                int arow = warp_m * 64 + i * 16 + a_lrow;
                uint32_t ad = bufb + 0 * TILE_B +
                              arow * (SP * 2) + (ks * 16 + a_lcol) * 2;
                LDSM_X4(ah[i][0], ah[i][1], ah[i][2], ah[i][3], ad);
            }
            #pragma unroll
            for (int jp = 0; jp < 4; jp++) {
                int nrow = warp_n * 64 + jp * 16 + b_lrow;
                uint32_t bd = bufb + 2 * TILE_B +
                              nrow * (SP * 2) + (ks * 16 + b_lcol) * 2;
                LDSM_X4(bh[jp * 2][0], bh[jp * 2][1],
                        bh[jp * 2 + 1][0], bh[jp * 2 + 1][1], bd);
            }
            #pragma unroll
            for (int i = 0; i < 4; i++)
                #pragma unroll
                for (int j = 0; j < 8; j++)
                    MMA16816(acc[i][j], ah[i][0], ah[i][1], ah[i][2], ah[i][3],
                             bh[j][0], bh[j][1]);

            #pragma unroll
            for (int jp = 0; jp < 4; jp++) {
                int nrow = warp_n * 64 + jp * 16 + b_lrow;
                uint32_t bd = bufb + 3 * TILE_B +
                              nrow * (SP * 2) + (ks * 16 + b_lcol) * 2;
                LDSM_X4(bl[jp * 2][0], bl[jp * 2][1],
                        bl[jp * 2 + 1][0], bl[jp * 2 + 1][1], bd);
            }
            #pragma unroll
            for (int i = 0; i < 4; i++)
                #pragma unroll
                for (int j = 0; j < 8; j++)
                    MMA16816(acc[i][j], ah[i][0], ah[i][1], ah[i][2], ah[i][3],
                             bl[j][0], bl[j][1]);

            #pragma unroll
            for (int i = 0; i < 4; i++) {
                int arow = warp_m * 64 + i * 16 + a_lrow;
                uint32_t ad = bufb + 1 * TILE_B +
                              arow * (SP * 2) + (ks * 16 + a_lcol) * 2;
                LDSM_X4(al[i][0], al[i][1], al[i][2], al[i][3], ad);
            }
            #pragma unroll
            for (int i = 0; i < 4; i++)
                #pragma unroll
                for (int j = 0; j < 8; j++)
                    MMA16816(acc[i][j], al[i][0], al[i][1], al[i][2], al[i][3],
                             bh[j][0], bh[j][1]);
        }

        if (it + 1 < niter) {
            CP_WAIT0();
            __syncthreads();
        }
    }

    const int g  = lane >> 2;
    const int tq = lane & 3;
    #pragma unroll
    for (int i = 0; i < 4; i++) {
        #pragma unroll
        for (int j = 0; j < 8; j++) {
            int col = n0 + warp_n * 64 + j * 8 + tq * 2;
            float2 bz = *(const float2*)(bias + col);
            int row_a = m0 + warp_m * 64 + i * 16 + g;
            float2 o0 = { acc[i][j][0] + bz.x, acc[i][j][1] + bz.y };
            float2 o1 = { acc[i][j][2] + bz.x, acc[i][j][3] + bz.y };
            *(float2*)(C + (size_t)row_a * N + col) = o0;
            *(float2*)(C + (size_t)(row_a + 8) * N + col) = o1;
        }
    }
#undef CPA_TILES
}

// ---------------------------------------------------------------------------
// Prepass: elementwise fp32 -> (hi, lo) bf16 split (x only)
// ---------------------------------------------------------------------------
__global__ __launch_bounds__(256) void split_bf16(
    const float* __restrict__ in, __nv_bfloat16* __restrict__ hi,
    __nv_bfloat16* __restrict__ lo, int n4)
{
    int i = blockIdx.x * 256 + threadIdx.x;
    if (i >= n4) return;
    float4 x = ((const float4*)in)[i];
    __nv_bfloat16 hx = __float2bfloat16(x.x), hy = __float2bfloat16(x.y);
    __nv_bfloat16 hz = __float2bfloat16(x.z), hw = __float2bfloat16(x.w);
    __nv_bfloat16 lx = __float2bfloat16(x.x - __bfloat162float(hx));
    __nv_bfloat16 ly = __float2bfloat16(x.y - __bfloat162float(hy));
    __nv_bfloat16 lz = __float2bfloat16(x.z - __bfloat162float(hz));
    __nv_bfloat16 lw = __float2bfloat16(x.w - __bfloat162float(hw));
    ((__nv_bfloat162*)hi)[i * 2]     = __nv_bfloat162(hx, hy);
    ((__nv_bfloat162*)hi)[i * 2 + 1] = __nv_bfloat162(hz, hw);
    ((__nv_bfloat162*)lo)[i * 2]     = __nv_bfloat162(lx, ly);
    ((__nv_bfloat162*)lo)[i * 2 + 1] = __nv_bfloat162(lz, lw);
}

// ---------------------------------------------------------------------------
// Prepass: W[K][N] fp32 -> W^T hi/lo [N][K] bf16 (32x32 smem transpose)
// ---------------------------------------------------------------------------
__global__ __launch_bounds__(256) void transpose_split(
    const float* __restrict__ W, __nv_bfloat16* __restrict__ hiT,
    __nv_bfloat16* __restrict__ loT, int K, int N)
{
    __shared__ float t[32][33];
    const int kb = blockIdx.y * 32, nb = blockIdx.x * 32;
    const int tx = threadIdx.x, ty = threadIdx.y;
    #pragma unroll
    for (int s = 0; s < 32; s += 8)
        t[ty + s][tx] = W[(size_t)(kb + ty + s) * N + nb + tx];
    __syncthreads();
    #pragma unroll
    for (int s = 0; s < 32; s += 8) {
        int nn = nb + ty + s, kk = kb + tx;
        float vv = t[tx][ty + s];
        __nv_bfloat16 h = __float2bfloat16(vv);
        hiT[(size_t)nn * K + kk] = h;
        loT[(size_t)nn * K + kk] = __float2bfloat16(vv - __bfloat162float(h));
    }
}

// ---------------------------------------------------------------------------
// Attention kernel: column-max softmax, 4x4 register micro-tiles (4x fewer
// LDS in score/output phases), direct bf16 hi/lo epilogue (feeds GEMM2).
// Conflict-free lane maps: K/V rows indexed ts+16k (stride 65 ≡ 1 mod 32).
// ---------------------------------------------------------------------------
#define TILE_STRIDE 65
#define TILE_FLOATS (64 * TILE_STRIDE)
#define ATTN_SMEM_BYTES ((4 * TILE_FLOATS + 128) * 4)

__global__ __launch_bounds__(256) void attn_kernel(
    const float* __restrict__ qkv, const int* __restrict__ mapping,
    __nv_bfloat16* __restrict__ out_hi, __nv_bfloat16* __restrict__ out_lo)
{
    extern __shared__ float sm[];
    float* Qs   = sm;
    float* Ks   = sm + TILE_FLOATS;
    float* Vs   = sm + 2 * TILE_FLOATS;
    float* Ss   = sm + 3 * TILE_FLOATS;
    float* cmax = sm + 4 * TILE_FLOATS;
    float* lsum = sm + 4 * TILE_FLOATS + 64;

    __shared__ int qrow[64];
    __shared__ int krow[64];

    const int t = threadIdx.x;
    const int n = blockIdx.x;
    const int h = blockIdx.y;
    const int b = blockIdx.z;

    if (t < 64) qrow[t] = mapping[n * 64 + t];
    __syncthreads();
    if (t < 64) {
        int seg = qrow[0] >> 8;
        krow[t] = mapping[seg * 256 + t * 4];
    }
    __syncthreads();

    const float scale = 0.125f;
    const size_t base_b = (size_t)b * SEQ * QKV_N;
    const int hoff = h * HDIM;

    // float4 gathers
    #pragma unroll
    for (int p = 0; p < 4; p++) {
        int idx = t + 256 * p;
        int m = idx >> 4, d = (idx & 15) * 4;
        float4 qv = *(const float4*)(qkv + base_b + (size_t)qrow[m] * QKV_N + hoff + d);
        float4 kv = *(const float4*)(qkv + base_b + (size_t)krow[m] * QKV_N + 1024 + hoff + d);
        float4 vv = *(const float4*)(qkv + base_b + (size_t)krow[m] * QKV_N + 2048 + hoff + d);
        float* qp = Qs + m * TILE_STRIDE + d;
        qp[0] = qv.x * scale; qp[1] = qv.y * scale;
        qp[2] = qv.z * scale; qp[3] = qv.w * scale;
        float* kp = Ks + m * TILE_STRIDE + d;
        kp[0] = kv.x; kp[1] = kv.y; kp[2] = kv.z; kp[3] = kv.w;
        float* vp = Vs + m * TILE_STRIDE + d;
        vp[0] = vv.x; vp[1] = vv.y; vp[2] = vv.z; vp[3] = vv.w;
    }
    __syncthreads();

    // Scores: thread t -> rows 4*tm..+3 (tm=t/16), key cols {ts+16k} (ts=t%16)
    {
        int tm = t >> 4, ts = t & 15;
        float sc[4][4];
        #pragma unroll
        for (int i = 0; i < 4; i++)
            #pragma unroll
            for (int j = 0; j < 4; j++)
                sc[i][j] = 0.0f;
        #pragma unroll
        for (int d = 0; d < 64; d++) {
            float qv[4], kv[4];
            #pragma unroll
            for (int i = 0; i < 4; i++)
                qv[i] = Qs[(tm * 4 + i) * TILE_STRIDE + d];
            #pragma unroll
            for (int j = 0; j < 4; j++)
                kv[j] = Ks[(ts + 16 * j) * TILE_STRIDE + d];
            #pragma unroll
            for (int i = 0; i < 4; i++)
                #pragma unroll
                for (int j = 0; j < 4; j++)
                    sc[i][j] += qv[i] * kv[j];
        }
        #pragma unroll
        for (int i = 0; i < 4; i++)
            #pragma unroll
            for (int j = 0; j < 4; j++)
                Ss[(tm * 4 + i) * TILE_STRIDE + ts + 16 * j] = sc[i][j];
    }
    __syncthreads();

    // Column max over queries: thread t -> col s = t/4, 16 rows
    {
        int s = t >> 2, mq0 = (t & 3) * 16;
        float mx = -1e30f;
        #pragma unroll
        for (int m = 0; m < 16; m++)
            mx = fmaxf(mx, Ss[(mq0 + m) * TILE_STRIDE + s]);
        mx = fmaxf(mx, __shfl_xor_sync(0xFFFFFFFF, mx, 1));
        mx = fmaxf(mx, __shfl_xor_sync(0xFFFFFFFF, mx, 2));
        if ((t & 3) == 0) cmax[s] = mx;
    }
    __syncthreads();

    // exp against COLUMN max + row sums: thread t -> row m = t/4
    {
        int m = t >> 2, s0 = (t & 3) * 16;
        float sum = 0.0f;
        #pragma unroll
        for (int s = 0; s < 16; s++) {
            float e = __expf(Ss[m * TILE_STRIDE + s0 + s] - cmax[s0 + s]);
            Ss[m * TILE_STRIDE + s0 + s] = e;
            sum += e;
        }
        sum += __shfl_xor_sync(0xFFFFFFFF, sum, 1);
        sum += __shfl_xor_sync(0xFFFFFFFF, sum, 2);
        if ((t & 3) == 0) lsum[m] = 1e-6f + sum;
    }
    __syncthreads();

    // Output: thread t -> rows 4*tm..+3, dim cols {td+16k}; bf16 hi/lo epilogue
    {
        int tm = t >> 4, td = t & 15;
        float acc[4][4];
        #pragma unroll
        for (int i = 0; i < 4; i++)
            #pragma unroll
            for (int j = 0; j < 4; j++)
                acc[i][j] = 0.0f;
        #pragma unroll
        for (int s = 0; s < 64; s++) {
            float pv[4], vv[4];
            #pragma unroll
            for (int i = 0; i < 4; i++)
                pv[i] = Ss[(tm * 4 + i) * TILE_STRIDE + s];
            #pragma unroll
            for (int j = 0; j < 4; j++)
                vv[j] = Vs[s * TILE_STRIDE + td + 16 * j];
            #pragma unroll
            for (int i = 0; i < 4; i++)
                #pragma unroll
                for (int j = 0; j < 4; j++)
                    acc[i][j] += pv[i] * vv[j];
        }
        #pragma unroll
        for (int i = 0; i < 4; i++) {
            float inv = 1.0f / lsum[tm * 4 + i];
            size_t orow = ((size_t)b * SEQ + n * 64 + tm * 4 + i) * DIM + hoff;
            #pragma unroll
            for (int j = 0; j < 4; j++) {
                float val = acc[i][j] * inv;
                __nv_bfloat16 hv = __float2bfloat16(val);
                out_hi[orow + td + 16 * j] = hv;
                out_lo[orow + td + 16 * j] =
                    __float2bfloat16(val - __bfloat162float(hv));
            }
        }
    }
}

// ---------------------------------------------------------------------------
// Launch
// ---------------------------------------------------------------------------
extern "C" void kernel_launch(void* const* d_in, const int* in_sizes, int n_in,
                              void* d_out, int out_size)
{
    const float* x     = (const float*)d_in[0];
    const float* Wqkv  = (const float*)d_in[1];
    const float* bqkv  = (const float*)d_in[2];
    const float* Wproj = (const float*)d_in[3];
    const float* bproj = (const float*)d_in[4];
    const int*   mapping = (const int*)d_in[5];
    float* out = (float*)d_out;

    float *qkv;
    __nv_bfloat16 *ahi, *alo, *wqh, *wql, *wph, *wpl;
    cudaGetSymbolAddress((void**)&qkv,  g_qkv);
    cudaGetSymbolAddress((void**)&ahi,  g_ahi);
    cudaGetSymbolAddress((void**)&alo,  g_alo);
    cudaGetSymbolAddress((void**)&wqh,  g_wqT_hi);
    cudaGetSymbolAddress((void**)&wql,  g_wqT_lo);
    cudaGetSymbolAddress((void**)&wph,  g_wpT_hi);
    cudaGetSymbolAddress((void**)&wpl,  g_wpT_lo);

    cudaFuncSetAttribute(attn_kernel,
                         cudaFuncAttributeMaxDynamicSharedMemorySize, ATTN_SMEM_BYTES);
    cudaFuncSetAttribute(gemm_bf16x3,
                         cudaFuncAttributeMaxDynamicSharedMemorySize, GEMM_SMEM);

    const int n4 = MROWS * DIM / 4;

    // Prepasses
    split_bf16<<<(n4 + 255) / 256, 256>>>(x, ahi, alo, n4);
    transpose_split<<<dim3(QKV_N / 32, DIM / 32), dim3(32, 8)>>>(Wqkv, wqh, wql, DIM, QKV_N);
    transpose_split<<<dim3(DIM / 32, DIM / 32), dim3(32, 8)>>>(Wproj, wph, wpl, DIM, DIM);

    // 1) QKV projection (tensor cores, bf16x3)
    gemm_bf16x3<<<dim3(QKV_N / GBN, MROWS / GBM), 128, GEMM_SMEM>>>(
        ahi, alo, wqh, wql, bqkv, qkv, MROWS, QKV_N, DIM);

    // 2) Hilbert block attention -> writes bf16 hi/lo directly (g_ahi/g_alo)
    attn_kernel<<<dim3(NBLK, NHEAD, BATCH), 256, ATTN_SMEM_BYTES>>>(
        qkv, mapping, ahi, alo);

    // 3) Output projection (tensor cores)
    gemm_bf16x3<<<dim3(DIM / GBN, MROWS / GBM), 128, GEMM_SMEM>>>(
        ahi, alo, wph, wpl, bproj, out, MROWS, DIM, DIM);
}

// round 10
// speedup vs baseline: 3.7233x; 1.3273x over previous
#include <cuda_runtime.h>
#include <cuda_bf16.h>
#include <cstdint>

// ---------------------------------------------------------------------------
// Problem constants
// ---------------------------------------------------------------------------
#define BATCH 2
#define SEQ   4096
#define DIM   1024
#define NHEAD 16
#define HDIM  64
#define NBLK  64
#define QKV_N 3072
#define MROWS (BATCH * SEQ)          // 8192
#define KVROWS 2048                  // 2 batches * 16 segs * 64 keys

// ---------------------------------------------------------------------------
// Scratch (static device globals; no cudaMalloc allowed)
// ---------------------------------------------------------------------------
__device__ float g_q[(size_t)MROWS * DIM];                // 32 MB (Q)
__device__ float g_kv[(size_t)KVROWS * 2 * DIM];          // 16 MB (K|V compact)
__device__ __nv_bfloat16 g_ahi[(size_t)MROWS * DIM];
__device__ __nv_bfloat16 g_alo[(size_t)MROWS * DIM];
__device__ __nv_bfloat16 g_wqT_hi[(size_t)QKV_N * DIM];
__device__ __nv_bfloat16 g_wqT_lo[(size_t)QKV_N * DIM];
__device__ __nv_bfloat16 g_wpT_hi[(size_t)DIM * DIM];
__device__ __nv_bfloat16 g_wpT_lo[(size_t)DIM * DIM];
__device__ int g_rowlist[KVROWS];

// ---------------------------------------------------------------------------
// Helpers (baseline compute_100-safe PTX)
// ---------------------------------------------------------------------------
__device__ __forceinline__ uint32_t smem_u32(const void* p) {
    uint32_t a;
    asm("{ .reg .u64 t; cvta.to.shared.u64 t, %1; cvt.u32.u64 %0, t; }"
        : "=r"(a) : "l"(p));
    return a;
}

#define LDSM_X4(r0, r1, r2, r3, addr)                                         \
    asm volatile("ldmatrix.sync.aligned.m8n8.x4.shared.b16 {%0,%1,%2,%3}, [%4];" \
                 : "=r"(r0), "=r"(r1), "=r"(r2), "=r"(r3) : "r"(addr))

#define MMA16816(c, a0, a1, a2, a3, b0, b1)                                   \
    asm volatile("mma.sync.aligned.m16n8k16.row.col.f32.bf16.bf16.f32 "       \
                 "{%0,%1,%2,%3}, {%4,%5,%6,%7}, {%8,%9}, {%0,%1,%2,%3};"      \
                 : "+f"((c)[0]), "+f"((c)[1]), "+f"((c)[2]), "+f"((c)[3])     \
                 : "r"(a0), "r"(a1), "r"(a2), "r"(a3), "r"(b0), "r"(b1))

#define CP_ASYNC16(sm, gm)                                                    \
    asm volatile("cp.async.cg.shared.global [%0], [%1], 16;"                  \
                 :: "r"(sm), "l"(gm))
#define CP_COMMIT()  asm volatile("cp.async.commit_group;" ::: "memory")
#define CP_WAIT0()   asm volatile("cp.async.wait_group 0;" ::: "memory")

// ---------------------------------------------------------------------------
// bf16x3 tensor-core GEMM with optional A-row indirection:
//   C[M,N] = (Ahi+Alo)[rows][K] * (BThi+BTlo)[N,K]^T + bias[N]
//   Arows == nullptr -> identity row map.
// Block 128x128, 128 threads (2x2 warps), BK=32, cp.async double buffer.
// ---------------------------------------------------------------------------
#define GBM 128
#define GBN 128
#define GBK 32
#define SP 40
#define TILE_B (128 * SP * 2)
#define BUF_B  (4 * TILE_B)
#define GEMM_SMEM (2 * BUF_B)       // 81920 B

__global__ __launch_bounds__(128, 2) void gemm_bf16x3(
    const __nv_bfloat16* __restrict__ Ahi, const __nv_bfloat16* __restrict__ Alo,
    const __nv_bfloat16* __restrict__ BThi, const __nv_bfloat16* __restrict__ BTlo,
    const float* __restrict__ bias, float* __restrict__ C,
    const int* __restrict__ Arows,
    int M, int N, int K)
{
    extern __shared__ char smem[];
    const uint32_t sb = smem_u32(smem);

    const int tid  = threadIdx.x;
    const int wid  = tid >> 5;
    const int lane = tid & 31;
    const int warp_m = wid & 1;
    const int warp_n = wid >> 1;
    const int m0 = blockIdx.y * GBM;
    const int n0 = blockIdx.x * GBN;

    float acc[4][8][4];
    #pragma unroll
    for (int i = 0; i < 4; i++)
        #pragma unroll
        for (int j = 0; j < 8; j++)
            #pragma unroll
            for (int q = 0; q < 4; q++)
                acc[i][j][q] = 0.0f;

    // Hoisted per-thread load pointers (row/col fixed; only k0 varies)
    const int rbase = tid >> 2;
    const int c4    = tid & 3;
    const __nv_bfloat16* gp[4][4];   // [arr][p]
    uint32_t sa_off[4][4];
    #pragma unroll
    for (int p = 0; p < 4; p++) {
        int r = rbase + 32 * p;
        int arow = m0 + r;
        if (Arows) arow = Arows[m0 + r];
        gp[0][p] = Ahi  + (size_t)arow * K + c4 * 8;
        gp[1][p] = Alo  + (size_t)arow * K + c4 * 8;
        gp[2][p] = BThi + (size_t)(n0 + r) * K + c4 * 8;
        gp[3][p] = BTlo + (size_t)(n0 + r) * K + c4 * 8;
        uint32_t so = r * (SP * 2) + c4 * 16;
        sa_off[0][p] = 0 * TILE_B + so;
        sa_off[1][p] = 1 * TILE_B + so;
        sa_off[2][p] = 2 * TILE_B + so;
        sa_off[3][p] = 3 * TILE_B + so;
    }

#define CPA_TILES(buf, k0) do {                                               \
    uint32_t _b = sb + (buf) * BUF_B;                                         \
    _Pragma("unroll")                                                         \
    for (int arr = 0; arr < 4; arr++)                                         \
        _Pragma("unroll")                                                     \
        for (int p = 0; p < 4; p++)                                           \
            CP_ASYNC16(_b + sa_off[arr][p], gp[arr][p] + (k0));               \
    } while (0)

    const int a_lrow = (lane & 7) + ((lane >> 3) & 1) * 8;
    const int a_lcol = ((lane >> 4) & 1) * 8;
    const int b_lrow = (lane & 7) + ((lane >> 4) & 1) * 8;
    const int b_lcol = ((lane >> 3) & 1) * 8;

    const int niter = K / GBK;

    CPA_TILES(0, 0);
    CP_COMMIT();
    CP_WAIT0();
    __syncthreads();

    for (int it = 0; it < niter; it++) {
        const uint32_t bufb = sb + (it & 1) * BUF_B;

        if (it + 1 < niter) {
            CPA_TILES((it + 1) & 1, (it + 1) * GBK);
            CP_COMMIT();
        }

        #pragma unroll
        for (int ks = 0; ks < 2; ks++) {
            uint32_t ah[4][4], al[4][4], bh[8][2], bl[8][2];

            #pragma unroll
            for (int i = 0; i < 4; i++) {
                int arow = warp_m * 64 + i * 16 + a_lrow;
                uint32_t ad = bufb + 0 * TILE_B +
                              arow * (SP * 2) + (ks * 16 + a_lcol) * 2;
                LDSM_X4(ah[i][0], ah[i][1], ah[i][2], ah[i][3], ad);
            }
            #pragma unroll
            for (int jp = 0; jp < 4; jp++) {
                int nrow = warp_n * 64 + jp * 16 + b_lrow;
                uint32_t bd = bufb + 2 * TILE_B +
                              nrow * (SP * 2) + (ks * 16 + b_lcol) * 2;
                LDSM_X4(bh[jp * 2][0], bh[jp * 2][1],
                        bh[jp * 2 + 1][0], bh[jp * 2 + 1][1], bd);
            }
            #pragma unroll
            for (int i = 0; i < 4; i++)
                #pragma unroll
                for (int j = 0; j < 8; j++)
                    MMA16816(acc[i][j], ah[i][0], ah[i][1], ah[i][2], ah[i][3],
                             bh[j][0], bh[j][1]);

            #pragma unroll
            for (int jp = 0; jp < 4; jp++) {
                int nrow = warp_n * 64 + jp * 16 + b_lrow;
                uint32_t bd = bufb + 3 * TILE_B +
                              nrow * (SP * 2) + (ks * 16 + b_lcol) * 2;
                LDSM_X4(bl[jp * 2][0], bl[jp * 2][1],
                        bl[jp * 2 + 1][0], bl[jp * 2 + 1][1], bd);
            }
            #pragma unroll
            for (int i = 0; i < 4; i++)
                #pragma unroll
                for (int j = 0; j < 8; j++)
                    MMA16816(acc[i][j], ah[i][0], ah[i][1], ah[i][2], ah[i][3],
                             bl[j][0], bl[j][1]);

            #pragma unroll
            for (int i = 0; i < 4; i++) {
                int arow = warp_m * 64 + i * 16 + a_lrow;
                uint32_t ad = bufb + 1 * TILE_B +
                              arow * (SP * 2) + (ks * 16 + a_lcol) * 2;
                LDSM_X4(al[i][0], al[i][1], al[i][2], al[i][3], ad);
            }
            #pragma unroll
            for (int i = 0; i < 4; i++)
                #pragma unroll
                for (int j = 0; j < 8; j++)
                    MMA16816(acc[i][j], al[i][0], al[i][1], al[i][2], al[i][3],
                             bh[j][0], bh[j][1]);
        }

        if (it + 1 < niter) {
            CP_WAIT0();
            __syncthreads();
        }
    }

    const int g  = lane >> 2;
    const int tq = lane & 3;
    #pragma unroll
    for (int i = 0; i < 4; i++) {
        #pragma unroll
        for (int j = 0; j < 8; j++) {
            int col = n0 + warp_n * 64 + j * 8 + tq * 2;
            float2 bz = *(const float2*)(bias + col);
            int row_a = m0 + warp_m * 64 + i * 16 + g;
            float2 o0 = { acc[i][j][0] + bz.x, acc[i][j][1] + bz.y };
            float2 o1 = { acc[i][j][2] + bz.x, acc[i][j][3] + bz.y };
            *(float2*)(C + (size_t)row_a * N + col) = o0;
            *(float2*)(C + (size_t)(row_a + 8) * N + col) = o1;
        }
    }
#undef CPA_TILES
}

// ---------------------------------------------------------------------------
// Prepass: elementwise fp32 -> (hi, lo) bf16 split (x only)
// ---------------------------------------------------------------------------
__global__ __launch_bounds__(256) void split_bf16(
    const float* __restrict__ in, __nv_bfloat16* __restrict__ hi,
    __nv_bfloat16* __restrict__ lo, int n4)
{
    int i = blockIdx.x * 256 + threadIdx.x;
    if (i >= n4) return;
    float4 x = ((const float4*)in)[i];
    __nv_bfloat16 hx = __float2bfloat16(x.x), hy = __float2bfloat16(x.y);
    __nv_bfloat16 hz = __float2bfloat16(x.z), hw = __float2bfloat16(x.w);
    __nv_bfloat16 lx = __float2bfloat16(x.x - __bfloat162float(hx));
    __nv_bfloat16 ly = __float2bfloat16(x.y - __bfloat162float(hy));
    __nv_bfloat16 lz = __float2bfloat16(x.z - __bfloat162float(hz));
    __nv_bfloat16 lw = __float2bfloat16(x.w - __bfloat162float(hw));
    ((__nv_bfloat162*)hi)[i * 2]     = __nv_bfloat162(hx, hy);
    ((__nv_bfloat162*)hi)[i * 2 + 1] = __nv_bfloat162(hz, hw);
    ((__nv_bfloat162*)lo)[i * 2]     = __nv_bfloat162(lx, ly);
    ((__nv_bfloat162*)lo)[i * 2 + 1] = __nv_bfloat162(lz, lw);
}

// ---------------------------------------------------------------------------
// Prepass: W[K][N] fp32 -> W^T hi/lo [N][K] bf16
// ---------------------------------------------------------------------------
__global__ __launch_bounds__(256) void transpose_split(
    const float* __restrict__ W, __nv_bfloat16* __restrict__ hiT,
    __nv_bfloat16* __restrict__ loT, int K, int N)
{
    __shared__ float t[32][33];
    const int kb = blockIdx.y * 32, nb = blockIdx.x * 32;
    const int tx = threadIdx.x, ty = threadIdx.y;
    #pragma unroll
    for (int s = 0; s < 32; s += 8)
        t[ty + s][tx] = W[(size_t)(kb + ty + s) * N + nb + tx];
    __syncthreads();
    #pragma unroll
    for (int s = 0; s < 32; s += 8) {
        int nn = nb + ty + s, kk = kb + tx;
        float vv = t[tx][ty + s];
        __nv_bfloat16 h = __float2bfloat16(vv);
        hiT[(size_t)nn * K + kk] = h;
        loT[(size_t)nn * K + kk] = __float2bfloat16(vv - __bfloat162float(h));
    }
}

// ---------------------------------------------------------------------------
// Prepass: compact KV row list
//   rowlist[b*1024 + seg*64 + j] = b*4096 + mapping[seg*256 + 4*j]
// ---------------------------------------------------------------------------
__global__ void build_rowlist(const int* __restrict__ mapping,
                              int* __restrict__ rowlist)
{
    int i = blockIdx.x * 256 + threadIdx.x;
    if (i >= KVROWS) return;
    int b = i >> 10, r = i & 1023, seg = r >> 6, j = r & 63;
    rowlist[i] = b * SEQ + mapping[seg * 256 + 4 * j];
}

// ---------------------------------------------------------------------------
// Attention kernel: Q from g_q (gathered rows), K/V from compact g_kv
// (dense rows b*1024+seg*64+s). Column-max softmax, 4x4 micro-tiles,
// direct bf16 hi/lo epilogue.
// ---------------------------------------------------------------------------
#define TILE_STRIDE 65
#define TILE_FLOATS (64 * TILE_STRIDE)
#define ATTN_SMEM_BYTES ((4 * TILE_FLOATS + 128) * 4)

__global__ __launch_bounds__(256) void attn_kernel(
    const float* __restrict__ q, const float* __restrict__ kv,
    const int* __restrict__ mapping,
    __nv_bfloat16* __restrict__ out_hi, __nv_bfloat16* __restrict__ out_lo)
{
    extern __shared__ float sm[];
    float* Qs   = sm;
    float* Ks   = sm + TILE_FLOATS;
    float* Vs   = sm + 2 * TILE_FLOATS;
    float* Ss   = sm + 3 * TILE_FLOATS;
    float* cmax = sm + 4 * TILE_FLOATS;
    float* lsum = sm + 4 * TILE_FLOATS + 64;

    __shared__ int qrow[64];
    __shared__ int seg_s;

    const int t = threadIdx.x;
    const int n = blockIdx.x;
    const int h = blockIdx.y;
    const int b = blockIdx.z;

    if (t < 64) {
        int qr = mapping[n * 64 + t];
        qrow[t] = qr;
        if (t == 0) seg_s = qr >> 8;
    }
    __syncthreads();

    const float scale = 0.125f;
    const int hoff = h * HDIM;
    const size_t kvrow0 = ((size_t)b * 1024 + seg_s * 64) * (2 * DIM);

    // float4 gathers (Q gathered; K/V dense compact rows)
    #pragma unroll
    for (int p = 0; p < 4; p++) {
        int idx = t + 256 * p;
        int m = idx >> 4, d = (idx & 15) * 4;
        float4 qv = *(const float4*)(q + ((size_t)b * SEQ + qrow[m]) * DIM + hoff + d);
        float4 kvv = *(const float4*)(kv + kvrow0 + (size_t)m * 2 * DIM + hoff + d);
        float4 vv  = *(const float4*)(kv + kvrow0 + (size_t)m * 2 * DIM + DIM + hoff + d);
        float* qp = Qs + m * TILE_STRIDE + d;
        qp[0] = qv.x * scale; qp[1] = qv.y * scale;
        qp[2] = qv.z * scale; qp[3] = qv.w * scale;
        float* kp = Ks + m * TILE_STRIDE + d;
        kp[0] = kvv.x; kp[1] = kvv.y; kp[2] = kvv.z; kp[3] = kvv.w;
        float* vp = Vs + m * TILE_STRIDE + d;
        vp[0] = vv.x; vp[1] = vv.y; vp[2] = vv.z; vp[3] = vv.w;
    }
    __syncthreads();

    // Scores: thread t -> rows 4*tm..+3, key cols {ts+16k}
    {
        int tm = t >> 4, ts = t & 15;
        float sc[4][4];
        #pragma unroll
        for (int i = 0; i < 4; i++)
            #pragma unroll
            for (int j = 0; j < 4; j++)
                sc[i][j] = 0.0f;
        #pragma unroll
        for (int d = 0; d < 64; d++) {
            float qv[4], kvr[4];
            #pragma unroll
            for (int i = 0; i < 4; i++)
                qv[i] = Qs[(tm * 4 + i) * TILE_STRIDE + d];
            #pragma unroll
            for (int j = 0; j < 4; j++)
                kvr[j] = Ks[(ts + 16 * j) * TILE_STRIDE + d];
            #pragma unroll
            for (int i = 0; i < 4; i++)
                #pragma unroll
                for (int j = 0; j < 4; j++)
                    sc[i][j] += qv[i] * kvr[j];
        }
        #pragma unroll
        for (int i = 0; i < 4; i++)
            #pragma unroll
            for (int j = 0; j < 4; j++)
                Ss[(tm * 4 + i) * TILE_STRIDE + ts + 16 * j] = sc[i][j];
    }
    __syncthreads();

    // Column max over queries
    {
        int s = t >> 2, mq0 = (t & 3) * 16;
        float mx = -1e30f;
        #pragma unroll
        for (int m = 0; m < 16; m++)
            mx = fmaxf(mx, Ss[(mq0 + m) * TILE_STRIDE + s]);
        mx = fmaxf(mx, __shfl_xor_sync(0xFFFFFFFF, mx, 1));
        mx = fmaxf(mx, __shfl_xor_sync(0xFFFFFFFF, mx, 2));
        if ((t & 3) == 0) cmax[s] = mx;
    }
    __syncthreads();

    // exp against COLUMN max + row sums
    {
        int m = t >> 2, s0 = (t & 3) * 16;
        float sum = 0.0f;
        #pragma unroll
        for (int s = 0; s < 16; s++) {
            float e = __expf(Ss[m * TILE_STRIDE + s0 + s] - cmax[s0 + s]);
            Ss[m * TILE_STRIDE + s0 + s] = e;
            sum += e;
        }
        sum += __shfl_xor_sync(0xFFFFFFFF, sum, 1);
        sum += __shfl_xor_sync(0xFFFFFFFF, sum, 2);
        if ((t & 3) == 0) lsum[m] = 1e-6f + sum;
    }
    __syncthreads();

    // Output with bf16 hi/lo epilogue
    {
        int tm = t >> 4, td = t & 15;
        float acc[4][4];
        #pragma unroll
        for (int i = 0; i < 4; i++)
            #pragma unroll
            for (int j = 0; j < 4; j++)
                acc[i][j] = 0.0f;
        #pragma unroll
        for (int s = 0; s < 64; s++) {
            float pv[4], vv[4];
            #pragma unroll
            for (int i = 0; i < 4; i++)
                pv[i] = Ss[(tm * 4 + i) * TILE_STRIDE + s];
            #pragma unroll
            for (int j = 0; j < 4; j++)
                vv[j] = Vs[s * TILE_STRIDE + td + 16 * j];
            #pragma unroll
            for (int i = 0; i < 4; i++)
                #pragma unroll
                for (int j = 0; j < 4; j++)
                    acc[i][j] += pv[i] * vv[j];
        }
        #pragma unroll
        for (int i = 0; i < 4; i++) {
            float inv = 1.0f / lsum[tm * 4 + i];
            size_t orow = ((size_t)b * SEQ + n * 64 + tm * 4 + i) * DIM + hoff;
            #pragma unroll
            for (int j = 0; j < 4; j++) {
                float val = acc[i][j] * inv;
                __nv_bfloat16 hv = __float2bfloat16(val);
                out_hi[orow + td + 16 * j] = hv;
                out_lo[orow + td + 16 * j] =
                    __float2bfloat16(val - __bfloat162float(hv));
            }
        }
    }
}

// ---------------------------------------------------------------------------
// Launch
// ---------------------------------------------------------------------------
extern "C" void kernel_launch(void* const* d_in, const int* in_sizes, int n_in,
                              void* d_out, int out_size)
{
    const float* x     = (const float*)d_in[0];
    const float* Wqkv  = (const float*)d_in[1];
    const float* bqkv  = (const float*)d_in[2];
    const float* Wproj = (const float*)d_in[3];
    const float* bproj = (const float*)d_in[4];
    const int*   mapping = (const int*)d_in[5];
    float* out = (float*)d_out;

    float *q, *kv;
    int* rowlist;
    __nv_bfloat16 *ahi, *alo, *wqh, *wql, *wph, *wpl;
    cudaGetSymbolAddress((void**)&q,   g_q);
    cudaGetSymbolAddress((void**)&kv,  g_kv);
    cudaGetSymbolAddress((void**)&rowlist, g_rowlist);
    cudaGetSymbolAddress((void**)&ahi, g_ahi);
    cudaGetSymbolAddress((void**)&alo, g_alo);
    cudaGetSymbolAddress((void**)&wqh, g_wqT_hi);
    cudaGetSymbolAddress((void**)&wql, g_wqT_lo);
    cudaGetSymbolAddress((void**)&wph, g_wpT_hi);
    cudaGetSymbolAddress((void**)&wpl, g_wpT_lo);

    cudaFuncSetAttribute(attn_kernel,
                         cudaFuncAttributeMaxDynamicSharedMemorySize, ATTN_SMEM_BYTES);
    cudaFuncSetAttribute(gemm_bf16x3,
                         cudaFuncAttributeMaxDynamicSharedMemorySize, GEMM_SMEM);

    const int n4 = MROWS * DIM / 4;

    // Prepasses
    split_bf16<<<(n4 + 255) / 256, 256>>>(x, ahi, alo, n4);
    transpose_split<<<dim3(QKV_N / 32, DIM / 32), dim3(32, 8)>>>(Wqkv, wqh, wql, DIM, QKV_N);
    transpose_split<<<dim3(DIM / 32, DIM / 32), dim3(32, 8)>>>(Wproj, wph, wpl, DIM, DIM);
    build_rowlist<<<KVROWS / 256, 256>>>(mapping, rowlist);

    // 1a) Q projection: all 8192 rows x 1024 cols
    gemm_bf16x3<<<dim3(DIM / GBN, MROWS / GBM), 128, GEMM_SMEM>>>(
        ahi, alo, wqh, wql, bqkv, q, nullptr, MROWS, DIM, DIM);

    // 1b) KV projection: compact 2048 gathered rows x 2048 cols (K|V)
    gemm_bf16x3<<<dim3(2 * DIM / GBN, KVROWS / GBM), 128, GEMM_SMEM>>>(
        ahi, alo, wqh + (size_t)DIM * DIM, wql + (size_t)DIM * DIM,
        bqkv + DIM, kv, rowlist, KVROWS, 2 * DIM, DIM);

    // 2) Hilbert block attention -> bf16 hi/lo (overwrites g_ahi/g_alo)
    attn_kernel<<<dim3(NBLK, NHEAD, BATCH), 256, ATTN_SMEM_BYTES>>>(
        q, kv, mapping, ahi, alo);

    // 3) Output projection
    gemm_bf16x3<<<dim3(DIM / GBN, MROWS / GBM), 128, GEMM_SMEM>>>(
        ahi, alo, wph, wpl, bproj, out, nullptr, MROWS, DIM, DIM);
}

// round 11
// speedup vs baseline: 3.8403x; 1.0314x over previous
#include <cuda_runtime.h>
#include <cuda_bf16.h>
#include <cstdint>

// ---------------------------------------------------------------------------
// Problem constants
// ---------------------------------------------------------------------------
#define BATCH 2
#define SEQ   4096
#define DIM   1024
#define NHEAD 16
#define HDIM  64
#define NBLK  64
#define QKV_N 3072
#define MROWS (BATCH * SEQ)          // 8192
#define KVROWS 2048                  // 2 batches * 16 segs * 64 keys

// ---------------------------------------------------------------------------
// Scratch (static device globals; no cudaMalloc allowed)
// ---------------------------------------------------------------------------
__device__ float g_q[(size_t)MROWS * DIM];                // 32 MB
__device__ float g_kv[(size_t)KVROWS * 2 * DIM];          // 16 MB (K|V compact)
__device__ __nv_bfloat16 g_ahi[(size_t)MROWS * DIM];
__device__ __nv_bfloat16 g_alo[(size_t)MROWS * DIM];
__device__ __nv_bfloat16 g_wqT_hi[(size_t)QKV_N * DIM];
__device__ __nv_bfloat16 g_wqT_lo[(size_t)QKV_N * DIM];
__device__ __nv_bfloat16 g_wpT_hi[(size_t)DIM * DIM];
__device__ __nv_bfloat16 g_wpT_lo[(size_t)DIM * DIM];
__device__ int g_rowlist[KVROWS];

// ---------------------------------------------------------------------------
// Helpers (baseline compute_100-safe PTX)
// ---------------------------------------------------------------------------
__device__ __forceinline__ uint32_t smem_u32(const void* p) {
    uint32_t a;
    asm("{ .reg .u64 t; cvta.to.shared.u64 t, %1; cvt.u32.u64 %0, t; }"
        : "=r"(a) : "l"(p));
    return a;
}

#define LDSM_X4(r0, r1, r2, r3, addr)                                         \
    asm volatile("ldmatrix.sync.aligned.m8n8.x4.shared.b16 {%0,%1,%2,%3}, [%4];" \
                 : "=r"(r0), "=r"(r1), "=r"(r2), "=r"(r3) : "r"(addr))

#define MMA16816(c, a0, a1, a2, a3, b0, b1)                                   \
    asm volatile("mma.sync.aligned.m16n8k16.row.col.f32.bf16.bf16.f32 "       \
                 "{%0,%1,%2,%3}, {%4,%5,%6,%7}, {%8,%9}, {%0,%1,%2,%3};"      \
                 : "+f"((c)[0]), "+f"((c)[1]), "+f"((c)[2]), "+f"((c)[3])     \
                 : "r"(a0), "r"(a1), "r"(a2), "r"(a3), "r"(b0), "r"(b1))

#define CP_ASYNC16(sm, gm)                                                    \
    asm volatile("cp.async.cg.shared.global [%0], [%1], 16;"                  \
                 :: "r"(sm), "l"(gm))
#define CP_COMMIT()  asm volatile("cp.async.commit_group;" ::: "memory")
#define CP_WAIT0()   asm volatile("cp.async.wait_group 0;" ::: "memory")

// ---------------------------------------------------------------------------
// Shared GEMM tile geometry
// ---------------------------------------------------------------------------
#define GBM 128
#define GBN 128
#define GBK 32
#define SP 40
#define TILE_B (128 * SP * 2)
#define BUF_B  (4 * TILE_B)
#define GEMM_SMEM (2 * BUF_B)       // 81920 B
#define KDIM 1024                   // K is always 1024 in this problem

// The GEMM core, parameterized by runtime config. Register-lean loader:
// 4 A row indices + base pointers; addresses computed at cp.async issue.
__device__ __forceinline__ void gemm_core(
    const __nv_bfloat16* __restrict__ Ahi, const __nv_bfloat16* __restrict__ Alo,
    const __nv_bfloat16* __restrict__ BThi, const __nv_bfloat16* __restrict__ BTlo,
    const float* __restrict__ bias, float* __restrict__ C,
    const int* __restrict__ Arows,
    int m0, int n0, int N, char* smem)
{
    const uint32_t sb = smem_u32(smem);
    const int tid  = threadIdx.x;
    const int wid  = tid >> 5;
    const int lane = tid & 31;
    const int warp_m = wid & 1;
    const int warp_n = wid >> 1;

    float acc[4][8][4];
    #pragma unroll
    for (int i = 0; i < 4; i++)
        #pragma unroll
        for (int j = 0; j < 8; j++)
            #pragma unroll
            for (int q = 0; q < 4; q++)
                acc[i][j][q] = 0.0f;

    const int rbase = tid >> 2;
    const int c4    = tid & 3;
    int arow4[4];
    #pragma unroll
    for (int p = 0; p < 4; p++) {
        int r = m0 + rbase + 32 * p;
        arow4[p] = Arows ? Arows[r] : r;
    }
    const __nv_bfloat16* bhp = BThi + (size_t)(n0 + rbase) * KDIM + c4 * 8;
    const __nv_bfloat16* blp = BTlo + (size_t)(n0 + rbase) * KDIM + c4 * 8;
    const uint32_t so0 = rbase * (SP * 2) + c4 * 16;

#define CPA_TILES(buf, k0) do {                                               \
    uint32_t _b = sb + (buf) * BUF_B;                                         \
    _Pragma("unroll")                                                         \
    for (int p = 0; p < 4; p++) {                                             \
        uint32_t _so = so0 + p * (32 * SP * 2);                               \
        size_t _ao = (size_t)arow4[p] * KDIM + c4 * 8 + (k0);                 \
        CP_ASYNC16(_b + 0 * TILE_B + _so, Ahi + _ao);                         \
        CP_ASYNC16(_b + 1 * TILE_B + _so, Alo + _ao);                         \
        size_t _bo = (size_t)p * 32 * KDIM + (k0);                            \
        CP_ASYNC16(_b + 2 * TILE_B + _so, bhp + _bo);                         \
        CP_ASYNC16(_b + 3 * TILE_B + _so, blp + _bo);                         \
    } } while (0)

    const int a_lrow = (lane & 7) + ((lane >> 3) & 1) * 8;
    const int a_lcol = ((lane >> 4) & 1) * 8;
    const int b_lrow = (lane & 7) + ((lane >> 4) & 1) * 8;
    const int b_lcol = ((lane >> 3) & 1) * 8;

    const int niter = KDIM / GBK;

    CPA_TILES(0, 0);
    CP_COMMIT();
    CP_WAIT0();
    __syncthreads();

    for (int it = 0; it < niter; it++) {
        const uint32_t bufb = sb + (it & 1) * BUF_B;

        if (it + 1 < niter) {
            CPA_TILES((it + 1) & 1, (it + 1) * GBK);
            CP_COMMIT();
        }

        #pragma unroll
        for (int ks = 0; ks < 2; ks++) {
            uint32_t ah[4][4], al[4][4], bh[8][2], bl[8][2];

            #pragma unroll
            for (int i = 0; i < 4; i++) {
                int arow = warp_m * 64 + i * 16 + a_lrow;
                uint32_t ad = bufb + 0 * TILE_B +
                              arow * (SP * 2) + (ks * 16 + a_lcol) * 2;
                LDSM_X4(ah[i][0], ah[i][1], ah[i][2], ah[i][3], ad);
            }
            #pragma unroll
            for (int jp = 0; jp < 4; jp++) {
                int nrow = warp_n * 64 + jp * 16 + b_lrow;
                uint32_t bd = bufb + 2 * TILE_B +
                              nrow * (SP * 2) + (ks * 16 + b_lcol) * 2;
                LDSM_X4(bh[jp * 2][0], bh[jp * 2][1],
                        bh[jp * 2 + 1][0], bh[jp * 2 + 1][1], bd);
            }
            #pragma unroll
            for (int i = 0; i < 4; i++)
                #pragma unroll
                for (int j = 0; j < 8; j++)
                    MMA16816(acc[i][j], ah[i][0], ah[i][1], ah[i][2], ah[i][3],
                             bh[j][0], bh[j][1]);

            #pragma unroll
            for (int jp = 0; jp < 4; jp++) {
                int nrow = warp_n * 64 + jp * 16 + b_lrow;
                uint32_t bd = bufb + 3 * TILE_B +
                              nrow * (SP * 2) + (ks * 16 + b_lcol) * 2;
                LDSM_X4(bl[jp * 2][0], bl[jp * 2][1],
                        bl[jp * 2 + 1][0], bl[jp * 2 + 1][1], bd);
            }
            #pragma unroll
            for (int i = 0; i < 4; i++)
                #pragma unroll
                for (int j = 0; j < 8; j++)
                    MMA16816(acc[i][j], ah[i][0], ah[i][1], ah[i][2], ah[i][3],
                             bl[j][0], bl[j][1]);

            #pragma unroll
            for (int i = 0; i < 4; i++) {
                int arow = warp_m * 64 + i * 16 + a_lrow;
                uint32_t ad = bufb + 1 * TILE_B +
                              arow * (SP * 2) + (ks * 16 + a_lcol) * 2;
                LDSM_X4(al[i][0], al[i][1], al[i][2], al[i][3], ad);
            }
            #pragma unroll
            for (int i = 0; i < 4; i++)
                #pragma unroll
                for (int j = 0; j < 8; j++)
                    MMA16816(acc[i][j], al[i][0], al[i][1], al[i][2], al[i][3],
                             bh[j][0], bh[j][1]);
        }

        if (it + 1 < niter) {
            CP_WAIT0();
            __syncthreads();
        }
    }

    const int g  = lane >> 2;
    const int tq = lane & 3;
    #pragma unroll
    for (int i = 0; i < 4; i++) {
        #pragma unroll
        for (int j = 0; j < 8; j++) {
            int col = n0 + warp_n * 64 + j * 8 + tq * 2;
            float2 bz = *(const float2*)(bias + col);
            int row_a = m0 + warp_m * 64 + i * 16 + g;
            float2 o0 = { acc[i][j][0] + bz.x, acc[i][j][1] + bz.y };
            float2 o1 = { acc[i][j][2] + bz.x, acc[i][j][3] + bz.y };
            *(float2*)(C + (size_t)row_a * N + col) = o0;
            *(float2*)(C + (size_t)(row_a + 8) * N + col) = o1;
        }
    }
#undef CPA_TILES
}

// ---------------------------------------------------------------------------
// Fused Q + KV projection: one launch, 768 blocks.
//   blocks [0, 512):  Q   = x @ WqkvT[0:1024]   (8192 x 1024)
//   blocks [512,768): KV  = gather(x) @ WqkvT[1024:3072] (2048 x 2048)
// ---------------------------------------------------------------------------
__global__ __launch_bounds__(128, 2) void gemm_qkv_fused(
    const __nv_bfloat16* __restrict__ Ahi, const __nv_bfloat16* __restrict__ Alo,
    const __nv_bfloat16* __restrict__ WqTh, const __nv_bfloat16* __restrict__ WqTl,
    const float* __restrict__ bqkv, float* __restrict__ q,
    float* __restrict__ kvo, const int* __restrict__ rowlist)
{
    extern __shared__ char smem[];
    int bx = blockIdx.x;
    if (bx < 512) {
        // Q: 64 m-blocks x 8 n-blocks
        int m0 = (bx >> 3) * GBM, n0 = (bx & 7) * GBN;
        gemm_core(Ahi, Alo, WqTh, WqTl, bqkv, q, nullptr, m0, n0, DIM, smem);
    } else {
        bx -= 512;
        // KV: 16 m-blocks x 16 n-blocks
        int m0 = (bx >> 4) * GBM, n0 = (bx & 15) * GBN;
        gemm_core(Ahi, Alo,
                  WqTh + (size_t)DIM * KDIM, WqTl + (size_t)DIM * KDIM,
                  bqkv + DIM, kvo, rowlist, m0, n0, 2 * DIM, smem);
    }
}

// ---------------------------------------------------------------------------
// Output projection GEMM (identity rows)
// ---------------------------------------------------------------------------
__global__ __launch_bounds__(128, 2) void gemm_proj(
    const __nv_bfloat16* __restrict__ Ahi, const __nv_bfloat16* __restrict__ Alo,
    const __nv_bfloat16* __restrict__ BThi, const __nv_bfloat16* __restrict__ BTlo,
    const float* __restrict__ bias, float* __restrict__ C)
{
    extern __shared__ char smem[];
    int m0 = blockIdx.y * GBM, n0 = blockIdx.x * GBN;
    gemm_core(Ahi, Alo, BThi, BTlo, bias, C, nullptr, m0, n0, DIM, smem);
}

// ---------------------------------------------------------------------------
// Prepass: elementwise fp32 -> (hi, lo) bf16 split (x only)
// ---------------------------------------------------------------------------
__global__ __launch_bounds__(256) void split_bf16(
    const float* __restrict__ in, __nv_bfloat16* __restrict__ hi,
    __nv_bfloat16* __restrict__ lo, int n4)
{
    int i = blockIdx.x * 256 + threadIdx.x;
    if (i >= n4) return;
    float4 x = ((const float4*)in)[i];
    __nv_bfloat16 hx = __float2bfloat16(x.x), hy = __float2bfloat16(x.y);
    __nv_bfloat16 hz = __float2bfloat16(x.z), hw = __float2bfloat16(x.w);
    __nv_bfloat16 lx = __float2bfloat16(x.x - __bfloat162float(hx));
    __nv_bfloat16 ly = __float2bfloat16(x.y - __bfloat162float(hy));
    __nv_bfloat16 lz = __float2bfloat16(x.z - __bfloat162float(hz));
    __nv_bfloat16 lw = __float2bfloat16(x.w - __bfloat162float(hw));
    ((__nv_bfloat162*)hi)[i * 2]     = __nv_bfloat162(hx, hy);
    ((__nv_bfloat162*)hi)[i * 2 + 1] = __nv_bfloat162(hz, hw);
    ((__nv_bfloat162*)lo)[i * 2]     = __nv_bfloat162(lx, ly);
    ((__nv_bfloat162*)lo)[i * 2 + 1] = __nv_bfloat162(lz, lw);
}

// ---------------------------------------------------------------------------
// Prepass: W[K][N] fp32 -> W^T hi/lo [N][K] bf16
// ---------------------------------------------------------------------------
__global__ __launch_bounds__(256) void transpose_split(
    const float* __restrict__ W, __nv_bfloat16* __restrict__ hiT,
    __nv_bfloat16* __restrict__ loT, int K, int N)
{
    __shared__ float t[32][33];
    const int kb = blockIdx.y * 32, nb = blockIdx.x * 32;
    const int tx = threadIdx.x, ty = threadIdx.y;
    #pragma unroll
    for (int s = 0; s < 32; s += 8)
        t[ty + s][tx] = W[(size_t)(kb + ty + s) * N + nb + tx];
    __syncthreads();
    #pragma unroll
    for (int s = 0; s < 32; s += 8) {
        int nn = nb + ty + s, kk = kb + tx;
        float vv = t[tx][ty + s];
        __nv_bfloat16 h = __float2bfloat16(vv);
        hiT[(size_t)nn * K + kk] = h;
        loT[(size_t)nn * K + kk] = __float2bfloat16(vv - __bfloat162float(h));
    }
}

// ---------------------------------------------------------------------------
// Prepass: compact KV row list
// ---------------------------------------------------------------------------
__global__ void build_rowlist(const int* __restrict__ mapping,
                              int* __restrict__ rowlist)
{
    int i = blockIdx.x * 256 + threadIdx.x;
    if (i >= KVROWS) return;
    int b = i >> 10, r = i & 1023, seg = r >> 6, j = r & 63;
    rowlist[i] = b * SEQ + mapping[seg * 256 + 4 * j];
}

// ---------------------------------------------------------------------------
// Attention kernel (validated Round 10; unchanged)
// ---------------------------------------------------------------------------
#define TILE_STRIDE 65
#define TILE_FLOATS (64 * TILE_STRIDE)
#define ATTN_SMEM_BYTES ((4 * TILE_FLOATS + 128) * 4)

__global__ __launch_bounds__(256) void attn_kernel(
    const float* __restrict__ q, const float* __restrict__ kv,
    const int* __restrict__ mapping,
    __nv_bfloat16* __restrict__ out_hi, __nv_bfloat16* __restrict__ out_lo)
{
    extern __shared__ float sm[];
    float* Qs   = sm;
    float* Ks   = sm + TILE_FLOATS;
    float* Vs   = sm + 2 * TILE_FLOATS;
    float* Ss   = sm + 3 * TILE_FLOATS;
    float* cmax = sm + 4 * TILE_FLOATS;
    float* lsum = sm + 4 * TILE_FLOATS + 64;

    __shared__ int qrow[64];
    __shared__ int seg_s;

    const int t = threadIdx.x;
    const int n = blockIdx.x;
    const int h = blockIdx.y;
    const int b = blockIdx.z;

    if (t < 64) {
        int qr = mapping[n * 64 + t];
        qrow[t] = qr;
        if (t == 0) seg_s = qr >> 8;
    }
    __syncthreads();

    const float scale = 0.125f;
    const int hoff = h * HDIM;
    const size_t kvrow0 = ((size_t)b * 1024 + seg_s * 64) * (2 * DIM);

    #pragma unroll
    for (int p = 0; p < 4; p++) {
        int idx = t + 256 * p;
        int m = idx >> 4, d = (idx & 15) * 4;
        float4 qv = *(const float4*)(q + ((size_t)b * SEQ + qrow[m]) * DIM + hoff + d);
        float4 kvv = *(const float4*)(kv + kvrow0 + (size_t)m * 2 * DIM + hoff + d);
        float4 vv  = *(const float4*)(kv + kvrow0 + (size_t)m * 2 * DIM + DIM + hoff + d);
        float* qp = Qs + m * TILE_STRIDE + d;
        qp[0] = qv.x * scale; qp[1] = qv.y * scale;
        qp[2] = qv.z * scale; qp[3] = qv.w * scale;
        float* kp = Ks + m * TILE_STRIDE + d;
        kp[0] = kvv.x; kp[1] = kvv.y; kp[2] = kvv.z; kp[3] = kvv.w;
        float* vp = Vs + m * TILE_STRIDE + d;
        vp[0] = vv.x; vp[1] = vv.y; vp[2] = vv.z; vp[3] = vv.w;
    }
    __syncthreads();

    {
        int tm = t >> 4, ts = t & 15;
        float sc[4][4];
        #pragma unroll
        for (int i = 0; i < 4; i++)
            #pragma unroll
            for (int j = 0; j < 4; j++)
                sc[i][j] = 0.0f;
        #pragma unroll
        for (int d = 0; d < 64; d++) {
            float qv[4], kvr[4];
            #pragma unroll
            for (int i = 0; i < 4; i++)
                qv[i] = Qs[(tm * 4 + i) * TILE_STRIDE + d];
            #pragma unroll
            for (int j = 0; j < 4; j++)
                kvr[j] = Ks[(ts + 16 * j) * TILE_STRIDE + d];
            #pragma unroll
            for (int i = 0; i < 4; i++)
                #pragma unroll
                for (int j = 0; j < 4; j++)
                    sc[i][j] += qv[i] * kvr[j];
        }
        #pragma unroll
        for (int i = 0; i < 4; i++)
            #pragma unroll
            for (int j = 0; j < 4; j++)
                Ss[(tm * 4 + i) * TILE_STRIDE + ts + 16 * j] = sc[i][j];
    }
    __syncthreads();

    {
        int s = t >> 2, mq0 = (t & 3) * 16;
        float mx = -1e30f;
        #pragma unroll
        for (int m = 0; m < 16; m++)
            mx = fmaxf(mx, Ss[(mq0 + m) * TILE_STRIDE + s]);
        mx = fmaxf(mx, __shfl_xor_sync(0xFFFFFFFF, mx, 1));
        mx = fmaxf(mx, __shfl_xor_sync(0xFFFFFFFF, mx, 2));
        if ((t & 3) == 0) cmax[s] = mx;
    }
    __syncthreads();

    {
        int m = t >> 2, s0 = (t & 3) * 16;
        float sum = 0.0f;
        #pragma unroll
        for (int s = 0; s < 16; s++) {
            float e = __expf(Ss[m * TILE_STRIDE + s0 + s] - cmax[s0 + s]);
            Ss[m * TILE_STRIDE + s0 + s] = e;
            sum += e;
        }
        sum += __shfl_xor_sync(0xFFFFFFFF, sum, 1);
        sum += __shfl_xor_sync(0xFFFFFFFF, sum, 2);
        if ((t & 3) == 0) lsum[m] = 1e-6f + sum;
    }
    __syncthreads();

    {
        int tm = t >> 4, td = t & 15;
        float acc[4][4];
        #pragma unroll
        for (int i = 0; i < 4; i++)
            #pragma unroll
            for (int j = 0; j < 4; j++)
                acc[i][j] = 0.0f;
        #pragma unroll
        for (int s = 0; s < 64; s++) {
            float pv[4], vv[4];
            #pragma unroll
            for (int i = 0; i < 4; i++)
                pv[i] = Ss[(tm * 4 + i) * TILE_STRIDE + s];
            #pragma unroll
            for (int j = 0; j < 4; j++)
                vv[j] = Vs[s * TILE_STRIDE + td + 16 * j];
            #pragma unroll
            for (int i = 0; i < 4; i++)
                #pragma unroll
                for (int j = 0; j < 4; j++)
                    acc[i][j] += pv[i] * vv[j];
        }
        #pragma unroll
        for (int i = 0; i < 4; i++) {
            float inv = 1.0f / lsum[tm * 4 + i];
            size_t orow = ((size_t)b * SEQ + n * 64 + tm * 4 + i) * DIM + hoff;
            #pragma unroll
            for (int j = 0; j < 4; j++) {
                float val = acc[i][j] * inv;
                __nv_bfloat16 hv = __float2bfloat16(val);
                out_hi[orow + td + 16 * j] = hv;
                out_lo[orow + td + 16 * j] =
                    __float2bfloat16(val - __bfloat162float(hv));
            }
        }
    }
}

// ---------------------------------------------------------------------------
// Launch
// ---------------------------------------------------------------------------
extern "C" void kernel_launch(void* const* d_in, const int* in_sizes, int n_in,
                              void* d_out, int out_size)
{
    const float* x     = (const float*)d_in[0];
    const float* Wqkv  = (const float*)d_in[1];
    const float* bqkv  = (const float*)d_in[2];
    const float* Wproj = (const float*)d_in[3];
    const float* bproj = (const float*)d_in[4];
    const int*   mapping = (const int*)d_in[5];
    float* out = (float*)d_out;

    float *q, *kv;
    int* rowlist;
    __nv_bfloat16 *ahi, *alo, *wqh, *wql, *wph, *wpl;
    cudaGetSymbolAddress((void**)&q,   g_q);
    cudaGetSymbolAddress((void**)&kv,  g_kv);
    cudaGetSymbolAddress((void**)&rowlist, g_rowlist);
    cudaGetSymbolAddress((void**)&ahi, g_ahi);
    cudaGetSymbolAddress((void**)&alo, g_alo);
    cudaGetSymbolAddress((void**)&wqh, g_wqT_hi);
    cudaGetSymbolAddress((void**)&wql, g_wqT_lo);
    cudaGetSymbolAddress((void**)&wph, g_wpT_hi);
    cudaGetSymbolAddress((void**)&wpl, g_wpT_lo);

    cudaFuncSetAttribute(attn_kernel,
                         cudaFuncAttributeMaxDynamicSharedMemorySize, ATTN_SMEM_BYTES);
    cudaFuncSetAttribute(gemm_qkv_fused,
                         cudaFuncAttributeMaxDynamicSharedMemorySize, GEMM_SMEM);
    cudaFuncSetAttribute(gemm_proj,
                         cudaFuncAttributeMaxDynamicSharedMemorySize, GEMM_SMEM);

    const int n4 = MROWS * DIM / 4;

    // Prepasses
    split_bf16<<<(n4 + 255) / 256, 256>>>(x, ahi, alo, n4);
    transpose_split<<<dim3(QKV_N / 32, DIM / 32), dim3(32, 8)>>>(Wqkv, wqh, wql, DIM, QKV_N);
    transpose_split<<<dim3(DIM / 32, DIM / 32), dim3(32, 8)>>>(Wproj, wph, wpl, DIM, DIM);
    build_rowlist<<<KVROWS / 256, 256>>>(mapping, rowlist);

    // 1) Fused Q + KV projection (768 blocks, one wave structure)
    gemm_qkv_fused<<<768, 128, GEMM_SMEM>>>(
        ahi, alo, wqh, wql, bqkv, q, kv, rowlist);

    // 2) Hilbert block attention -> bf16 hi/lo
    attn_kernel<<<dim3(NBLK, NHEAD, BATCH), 256, ATTN_SMEM_BYTES>>>(
        q, kv, mapping, ahi, alo);

    // 3) Output projection
    gemm_proj<<<dim3(DIM / GBN, MROWS / GBM), 128, GEMM_SMEM>>>(
        ahi, alo, wph, wpl, bproj, out);
}

// round 13
// speedup vs baseline: 4.9641x; 1.2926x over previous
#include <cuda_runtime.h>
#include <cuda_bf16.h>
#include <cuda_fp16.h>
#include <cstdint>

// ---------------------------------------------------------------------------
// Problem constants
// ---------------------------------------------------------------------------
#define BATCH 2
#define SEQ   4096
#define DIM   1024
#define NHEAD 16
#define HDIM  64
#define NBLK  64
#define QKV_N 3072
#define MROWS (BATCH * SEQ)          // 8192
#define KVROWS 2048                  // 2 batches * 16 segs * 64 keys

// ---------------------------------------------------------------------------
// Scratch (static device globals; no cudaMalloc allowed)
// ---------------------------------------------------------------------------
__device__ float g_q[(size_t)MROWS * DIM];                // 32 MB
__device__ float g_kv[(size_t)KVROWS * 2 * DIM];          // 16 MB (K|V compact)
__device__ __half g_ahi[(size_t)MROWS * DIM];             // activations hi
__device__ __half g_alo[(size_t)MROWS * DIM];             // activations lo
__device__ __half g_wqT[(size_t)QKV_N * DIM];             // Wqkv^T fp16
__device__ __half g_wpT[(size_t)DIM * DIM];               // Wproj^T fp16
__device__ int g_rowlist[KVROWS];

// ---------------------------------------------------------------------------
// Helpers (baseline compute_100-safe PTX)
// ---------------------------------------------------------------------------
__device__ __forceinline__ uint32_t smem_u32(const void* p) {
    uint32_t a;
    asm("{ .reg .u64 t; cvta.to.shared.u64 t, %1; cvt.u32.u64 %0, t; }"
        : "=r"(a) : "l"(p));
    return a;
}

#define LDSM_X4(r0, r1, r2, r3, addr)                                         \
    asm volatile("ldmatrix.sync.aligned.m8n8.x4.shared.b16 {%0,%1,%2,%3}, [%4];" \
                 : "=r"(r0), "=r"(r1), "=r"(r2), "=r"(r3) : "r"(addr))

#define MMA16816F(c, a0, a1, a2, a3, b0, b1)                                  \
    asm volatile("mma.sync.aligned.m16n8k16.row.col.f32.f16.f16.f32 "         \
                 "{%0,%1,%2,%3}, {%4,%5,%6,%7}, {%8,%9}, {%0,%1,%2,%3};"      \
                 : "+f"((c)[0]), "+f"((c)[1]), "+f"((c)[2]), "+f"((c)[3])     \
                 : "r"(a0), "r"(a1), "r"(a2), "r"(a3), "r"(b0), "r"(b1))

#define CP_ASYNC16(sm, gm)                                                    \
    asm volatile("cp.async.cg.shared.global [%0], [%1], 16;"                  \
                 :: "r"(sm), "l"(gm))
#define CP_COMMIT()  asm volatile("cp.async.commit_group;" ::: "memory")
#define CP_WAIT0()   asm volatile("cp.async.wait_group 0;" ::: "memory")

// ---------------------------------------------------------------------------
// Shared GEMM tile geometry: 3 tiles per buffer (Ah, Al, B)
// ---------------------------------------------------------------------------
#define GBM 128
#define GBN 128
#define GBK 32
#define SP 40
#define TILE_B (128 * SP * 2)        // 10240 B per tile
#define BUF_B  (3 * TILE_B)          // Ah, Al, B
#define GEMM_SMEM (2 * BUF_B)        // 61440 B
#define KDIM 1024

// fp16 2-pass GEMM core: C = (Ah + Al)[rows][K] * B[N,K]^T + bias
// Error source: B's fp16 rounding only (~1.4e-4 RMS relative).
__device__ __forceinline__ void gemm_core(
    const __half* __restrict__ Ahi, const __half* __restrict__ Alo,
    const __half* __restrict__ BT,
    const float* __restrict__ bias, float* __restrict__ C,
    const int* __restrict__ Arows,
    int m0, int n0, int N, char* smem)
{
    const uint32_t sb = smem_u32(smem);
    const int tid  = threadIdx.x;
    const int wid  = tid >> 5;
    const int lane = tid & 31;
    const int warp_m = wid & 1;
    const int warp_n = wid >> 1;

    float acc[4][8][4];
    #pragma unroll
    for (int i = 0; i < 4; i++)
        #pragma unroll
        for (int j = 0; j < 8; j++)
            #pragma unroll
            for (int q = 0; q < 4; q++)
                acc[i][j][q] = 0.0f;

    const int rbase = tid >> 2;
    const int c4    = tid & 3;
    int arow4[4];
    #pragma unroll
    for (int p = 0; p < 4; p++) {
        int r = m0 + rbase + 32 * p;
        arow4[p] = Arows ? Arows[r] : r;
    }
    const __half* bp = BT + (size_t)(n0 + rbase) * KDIM + c4 * 8;
    const uint32_t so0 = rbase * (SP * 2) + c4 * 16;

#define CPA_TILES(buf, k0) do {                                               \
    uint32_t _b = sb + (buf) * BUF_B;                                         \
    _Pragma("unroll")                                                         \
    for (int p = 0; p < 4; p++) {                                             \
        uint32_t _so = so0 + p * (32 * SP * 2);                               \
        size_t _ao = (size_t)arow4[p] * KDIM + c4 * 8 + (k0);                 \
        CP_ASYNC16(_b + 0 * TILE_B + _so, Ahi + _ao);                         \
        CP_ASYNC16(_b + 1 * TILE_B + _so, Alo + _ao);                         \
        CP_ASYNC16(_b + 2 * TILE_B + _so, bp + (size_t)p * 32 * KDIM + (k0)); \
    } } while (0)

    const int a_lrow = (lane & 7) + ((lane >> 3) & 1) * 8;
    const int a_lcol = ((lane >> 4) & 1) * 8;
    const int b_lrow = (lane & 7) + ((lane >> 4) & 1) * 8;
    const int b_lcol = ((lane >> 3) & 1) * 8;

    const int niter = KDIM / GBK;

    CPA_TILES(0, 0);
    CP_COMMIT();
    CP_WAIT0();
    __syncthreads();

    for (int it = 0; it < niter; it++) {
        const uint32_t bufb = sb + (it & 1) * BUF_B;

        if (it + 1 < niter) {
            CPA_TILES((it + 1) & 1, (it + 1) * GBK);
            CP_COMMIT();
        }

        #pragma unroll
        for (int ks = 0; ks < 2; ks++) {
            uint32_t ah[4][4], al[4][4], bb[8][2];

            #pragma unroll
            for (int i = 0; i < 4; i++) {
                int arow = warp_m * 64 + i * 16 + a_lrow;
                uint32_t ad = bufb + 0 * TILE_B +
                              arow * (SP * 2) + (ks * 16 + a_lcol) * 2;
                LDSM_X4(ah[i][0], ah[i][1], ah[i][2], ah[i][3], ad);
            }
            #pragma unroll
            for (int jp = 0; jp < 4; jp++) {
                int nrow = warp_n * 64 + jp * 16 + b_lrow;
                uint32_t bd = bufb + 2 * TILE_B +
                              nrow * (SP * 2) + (ks * 16 + b_lcol) * 2;
                LDSM_X4(bb[jp * 2][0], bb[jp * 2][1],
                        bb[jp * 2 + 1][0], bb[jp * 2 + 1][1], bd);
            }
            // pass 1: Ah * B
            #pragma unroll
            for (int i = 0; i < 4; i++)
                #pragma unroll
                for (int j = 0; j < 8; j++)
                    MMA16816F(acc[i][j], ah[i][0], ah[i][1], ah[i][2], ah[i][3],
                              bb[j][0], bb[j][1]);

            #pragma unroll
            for (int i = 0; i < 4; i++) {
                int arow = warp_m * 64 + i * 16 + a_lrow;
                uint32_t ad = bufb + 1 * TILE_B +
                              arow * (SP * 2) + (ks * 16 + a_lcol) * 2;
                LDSM_X4(al[i][0], al[i][1], al[i][2], al[i][3], ad);
            }
            // pass 2: Al * B
            #pragma unroll
            for (int i = 0; i < 4; i++)
                #pragma unroll
                for (int j = 0; j < 8; j++)
                    MMA16816F(acc[i][j], al[i][0], al[i][1], al[i][2], al[i][3],
                              bb[j][0], bb[j][1]);
        }

        if (it + 1 < niter) {
            CP_WAIT0();
            __syncthreads();
        }
    }

    const int g  = lane >> 2;
    const int tq = lane & 3;
    #pragma unroll
    for (int i = 0; i < 4; i++) {
        #pragma unroll
        for (int j = 0; j < 8; j++) {
            int col = n0 + warp_n * 64 + j * 8 + tq * 2;
            float2 bz = *(const float2*)(bias + col);
            int row_a = m0 + warp_m * 64 + i * 16 + g;
            float2 o0 = { acc[i][j][0] + bz.x, acc[i][j][1] + bz.y };
            float2 o1 = { acc[i][j][2] + bz.x, acc[i][j][3] + bz.y };
            *(float2*)(C + (size_t)row_a * N + col) = o0;
            *(float2*)(C + (size_t)(row_a + 8) * N + col) = o1;
        }
    }
#undef CPA_TILES
}

// ---------------------------------------------------------------------------
// Fused Q + KV projection (768 blocks)
// ---------------------------------------------------------------------------
__global__ __launch_bounds__(128, 2) void gemm_qkv_fused(
    const __half* __restrict__ Ahi, const __half* __restrict__ Alo,
    const __half* __restrict__ WqT,
    const float* __restrict__ bqkv, float* __restrict__ q,
    float* __restrict__ kvo, const int* __restrict__ rowlist)
{
    extern __shared__ char smem[];
    int bx = blockIdx.x;
    if (bx < 512) {
        int m0 = (bx >> 3) * GBM, n0 = (bx & 7) * GBN;
        gemm_core(Ahi, Alo, WqT, bqkv, q, nullptr, m0, n0, DIM, smem);
    } else {
        bx -= 512;
        int m0 = (bx >> 4) * GBM, n0 = (bx & 15) * GBN;
        gemm_core(Ahi, Alo, WqT + (size_t)DIM * KDIM,
                  bqkv + DIM, kvo, rowlist, m0, n0, 2 * DIM, smem);
    }
}

// ---------------------------------------------------------------------------
// Output projection GEMM
// ---------------------------------------------------------------------------
__global__ __launch_bounds__(128, 2) void gemm_proj(
    const __half* __restrict__ Ahi, const __half* __restrict__ Alo,
    const __half* __restrict__ BT,
    const float* __restrict__ bias, float* __restrict__ C)
{
    extern __shared__ char smem[];
    int m0 = blockIdx.y * GBM, n0 = blockIdx.x * GBN;
    gemm_core(Ahi, Alo, BT, bias, C, nullptr, m0, n0, DIM, smem);
}

// ---------------------------------------------------------------------------
// Prepass: elementwise fp32 -> (hi, lo) fp16 split (x only)
// ---------------------------------------------------------------------------
__global__ __launch_bounds__(256) void split_f16(
    const float* __restrict__ in, __half* __restrict__ hi,
    __half* __restrict__ lo, int n4)
{
    int i = blockIdx.x * 256 + threadIdx.x;
    if (i >= n4) return;
    float4 x = ((const float4*)in)[i];
    __half hx = __float2half_rn(x.x), hy = __float2half_rn(x.y);
    __half hz = __float2half_rn(x.z), hw = __float2half_rn(x.w);
    __half lx = __float2half_rn(x.x - __half2float(hx));
    __half ly = __float2half_rn(x.y - __half2float(hy));
    __half lz = __float2half_rn(x.z - __half2float(hz));
    __half lw = __float2half_rn(x.w - __half2float(hw));
    ((__half2*)hi)[i * 2]     = __halves2half2(hx, hy);
    ((__half2*)hi)[i * 2 + 1] = __halves2half2(hz, hw);
    ((__half2*)lo)[i * 2]     = __halves2half2(lx, ly);
    ((__half2*)lo)[i * 2 + 1] = __halves2half2(lz, lw);
}

// ---------------------------------------------------------------------------
// Prepass: W[K][N] fp32 -> W^T [N][K] fp16 (single precision level)
// ---------------------------------------------------------------------------
__global__ __launch_bounds__(256) void transpose_f16(
    const float* __restrict__ W, __half* __restrict__ T, int K, int N)
{
    __shared__ float t[32][33];
    const int kb = blockIdx.y * 32, nb = blockIdx.x * 32;
    const int tx = threadIdx.x, ty = threadIdx.y;
    #pragma unroll
    for (int s = 0; s < 32; s += 8)
        t[ty + s][tx] = W[(size_t)(kb + ty + s) * N + nb + tx];
    __syncthreads();
    #pragma unroll
    for (int s = 0; s < 32; s += 8) {
        int nn = nb + ty + s, kk = kb + tx;
        T[(size_t)nn * K + kk] = __float2half_rn(t[tx][ty + s]);
    }
}

// ---------------------------------------------------------------------------
// Prepass: compact KV row list
// ---------------------------------------------------------------------------
__global__ void build_rowlist(const int* __restrict__ mapping,
                              int* __restrict__ rowlist)
{
    int i = blockIdx.x * 256 + threadIdx.x;
    if (i >= KVROWS) return;
    int b = i >> 10, r = i & 1023, seg = r >> 6, j = r & 63;
    rowlist[i] = b * SEQ + mapping[seg * 256 + 4 * j];
}

// ---------------------------------------------------------------------------
// Attention kernel (Round 10 structure; fp16 hi/lo epilogue)
// ---------------------------------------------------------------------------
#define TILE_STRIDE 65
#define TILE_FLOATS (64 * TILE_STRIDE)
#define ATTN_SMEM_BYTES ((4 * TILE_FLOATS + 128) * 4)

__global__ __launch_bounds__(256) void attn_kernel(
    const float* __restrict__ q, const float* __restrict__ kv,
    const int* __restrict__ mapping,
    __half* __restrict__ out_hi, __half* __restrict__ out_lo)
{
    extern __shared__ float sm[];
    float* Qs   = sm;
    float* Ks   = sm + TILE_FLOATS;
    float* Vs   = sm + 2 * TILE_FLOATS;
    float* Ss   = sm + 3 * TILE_FLOATS;
    float* cmax = sm + 4 * TILE_FLOATS;
    float* lsum = sm + 4 * TILE_FLOATS + 64;

    __shared__ int qrow[64];
    __shared__ int seg_s;

    const int t = threadIdx.x;
    const int n = blockIdx.x;
    const int h = blockIdx.y;
    const int b = blockIdx.z;

    if (t < 64) {
        int qr = mapping[n * 64 + t];
        qrow[t] = qr;
        if (t == 0) seg_s = qr >> 8;
    }
    __syncthreads();

    const float scale = 0.125f;
    const int hoff = h * HDIM;
    const size_t kvrow0 = ((size_t)b * 1024 + seg_s * 64) * (2 * DIM);

    #pragma unroll
    for (int p = 0; p < 4; p++) {
        int idx = t + 256 * p;
        int m = idx >> 4, d = (idx & 15) * 4;
        float4 qv = *(const float4*)(q + ((size_t)b * SEQ + qrow[m]) * DIM + hoff + d);
        float4 kvv = *(const float4*)(kv + kvrow0 + (size_t)m * 2 * DIM + hoff + d);
        float4 vv  = *(const float4*)(kv + kvrow0 + (size_t)m * 2 * DIM + DIM + hoff + d);
        float* qp = Qs + m * TILE_STRIDE + d;
        qp[0] = qv.x * scale; qp[1] = qv.y * scale;
        qp[2] = qv.z * scale; qp[3] = qv.w * scale;
        float* kp = Ks + m * TILE_STRIDE + d;
        kp[0] = kvv.x; kp[1] = kvv.y; kp[2] = kvv.z; kp[3] = kvv.w;
        float* vp = Vs + m * TILE_STRIDE + d;
        vp[0] = vv.x; vp[1] = vv.y; vp[2] = vv.z; vp[3] = vv.w;
    }
    __syncthreads();

    {
        int tm = t >> 4, ts = t & 15;
        float sc[4][4];
        #pragma unroll
        for (int i = 0; i < 4; i++)
            #pragma unroll
            for (int j = 0; j < 4; j++)
                sc[i][j] = 0.0f;
        #pragma unroll
        for (int d = 0; d < 64; d++) {
            float qv[4], kvr[4];
            #pragma unroll
            for (int i = 0; i < 4; i++)
                qv[i] = Qs[(tm * 4 + i) * TILE_STRIDE + d];
            #pragma unroll
            for (int j = 0; j < 4; j++)
                kvr[j] = Ks[(ts + 16 * j) * TILE_STRIDE + d];
            #pragma unroll
            for (int i = 0; i < 4; i++)
                #pragma unroll
                for (int j = 0; j < 4; j++)
                    sc[i][j] += qv[i] * kvr[j];
        }
        #pragma unroll
        for (int i = 0; i < 4; i++)
            #pragma unroll
            for (int j = 0; j < 4; j++)
                Ss[(tm * 4 + i) * TILE_STRIDE + ts + 16 * j] = sc[i][j];
    }
    __syncthreads();

    {
        int s = t >> 2, mq0 = (t & 3) * 16;
        float mx = -1e30f;
        #pragma unroll
        for (int m = 0; m < 16; m++)
            mx = fmaxf(mx, Ss[(mq0 + m) * TILE_STRIDE + s]);
        mx = fmaxf(mx, __shfl_xor_sync(0xFFFFFFFF, mx, 1));
        mx = fmaxf(mx, __shfl_xor_sync(0xFFFFFFFF, mx, 2));
        if ((t & 3) == 0) cmax[s] = mx;
    }
    __syncthreads();

    {
        int m = t >> 2, s0 = (t & 3) * 16;
        float sum = 0.0f;
        #pragma unroll
        for (int s = 0; s < 16; s++) {
            float e = __expf(Ss[m * TILE_STRIDE + s0 + s] - cmax[s0 + s]);
            Ss[m * TILE_STRIDE + s0 + s] = e;
            sum += e;
        }
        sum += __shfl_xor_sync(0xFFFFFFFF, sum, 1);
        sum += __shfl_xor_sync(0xFFFFFFFF, sum, 2);
        if ((t & 3) == 0) lsum[m] = 1e-6f + sum;
    }
    __syncthreads();

    {
        int tm = t >> 4, td = t & 15;
        float acc[4][4];
        #pragma unroll
        for (int i = 0; i < 4; i++)
            #pragma unroll
            for (int j = 0; j < 4; j++)
                acc[i][j] = 0.0f;
        #pragma unroll
        for (int s = 0; s < 64; s++) {
            float pv[4], vv[4];
            #pragma unroll
            for (int i = 0; i < 4; i++)
                pv[i] = Ss[(tm * 4 + i) * TILE_STRIDE + s];
            #pragma unroll
            for (int j = 0; j < 4; j++)
                vv[j] = Vs[s * TILE_STRIDE + td + 16 * j];
            #pragma unroll
            for (int i = 0; i < 4; i++)
                #pragma unroll
                for (int j = 0; j < 4; j++)
                    acc[i][j] += pv[i] * vv[j];
        }
        #pragma unroll
        for (int i = 0; i < 4; i++) {
            float inv = 1.0f / lsum[tm * 4 + i];
            size_t orow = ((size_t)b * SEQ + n * 64 + tm * 4 + i) * DIM + hoff;
            #pragma unroll
            for (int j = 0; j < 4; j++) {
                float val = acc[i][j] * inv;
                __half hv = __float2half_rn(val);
                out_hi[orow + td + 16 * j] = hv;
                out_lo[orow + td + 16 * j] =
                    __float2half_rn(val - __half2float(hv));
            }
        }
    }
}

// ---------------------------------------------------------------------------
// Launch
// ---------------------------------------------------------------------------
extern "C" void kernel_launch(void* const* d_in, const int* in_sizes, int n_in,
                              void* d_out, int out_size)
{
    const float* x     = (const float*)d_in[0];
    const float* Wqkv  = (const float*)d_in[1];
    const float* bqkv  = (const float*)d_in[2];
    const float* Wproj = (const float*)d_in[3];
    const float* bproj = (const float*)d_in[4];
    const int*   mapping = (const int*)d_in[5];
    float* out = (float*)d_out;

    float *q, *kv;
    int* rowlist;
    __half *ahi, *alo, *wqT, *wpT;
    cudaGetSymbolAddress((void**)&q,   g_q);
    cudaGetSymbolAddress((void**)&kv,  g_kv);
    cudaGetSymbolAddress((void**)&rowlist, g_rowlist);
    cudaGetSymbolAddress((void**)&ahi, g_ahi);
    cudaGetSymbolAddress((void**)&alo, g_alo);
    cudaGetSymbolAddress((void**)&wqT, g_wqT);
    cudaGetSymbolAddress((void**)&wpT, g_wpT);

    cudaFuncSetAttribute(attn_kernel,
                         cudaFuncAttributeMaxDynamicSharedMemorySize, ATTN_SMEM_BYTES);
    cudaFuncSetAttribute(gemm_qkv_fused,
                         cudaFuncAttributeMaxDynamicSharedMemorySize, GEMM_SMEM);
    cudaFuncSetAttribute(gemm_proj,
                         cudaFuncAttributeMaxDynamicSharedMemorySize, GEMM_SMEM);

    const int n4 = MROWS * DIM / 4;

    // Prepasses
    split_f16<<<(n4 + 255) / 256, 256>>>(x, ahi, alo, n4);
    transpose_f16<<<dim3(QKV_N / 32, DIM / 32), dim3(32, 8)>>>(Wqkv, wqT, DIM, QKV_N);
    transpose_f16<<<dim3(DIM / 32, DIM / 32), dim3(32, 8)>>>(Wproj, wpT, DIM, DIM);
    build_rowlist<<<KVROWS / 256, 256>>>(mapping, rowlist);

    // 1) Fused Q + KV projection
    gemm_qkv_fused<<<768, 128, GEMM_SMEM>>>(
        ahi, alo, wqT, bqkv, q, kv, rowlist);

    // 2) Hilbert block attention -> fp16 hi/lo
    attn_kernel<<<dim3(NBLK, NHEAD, BATCH), 256, ATTN_SMEM_BYTES>>>(
        q, kv, mapping, ahi, alo);

    // 3) Output projection
    gemm_proj<<<dim3(DIM / GBN, MROWS / GBM), 128, GEMM_SMEM>>>(
        ahi, alo, wpT, bproj, out);
}

// round 14
// speedup vs baseline: 6.8154x; 1.3729x over previous
#include <cuda_runtime.h>
#include <cuda_bf16.h>
#include <cuda_fp16.h>
#include <cstdint>

// ---------------------------------------------------------------------------
// Problem constants
// ---------------------------------------------------------------------------
#define BATCH 2
#define SEQ   4096
#define DIM   1024
#define NHEAD 16
#define HDIM  64
#define NBLK  64
#define QKV_N 3072
#define MROWS (BATCH * SEQ)          // 8192
#define KVROWS 2048                  // 2 batches * 16 segs * 64 keys

// ---------------------------------------------------------------------------
// Scratch (static device globals; no cudaMalloc allowed)
// ---------------------------------------------------------------------------
__device__ float g_q[(size_t)MROWS * DIM];                // 32 MB
__device__ float g_kv[(size_t)KVROWS * 2 * DIM];          // 16 MB (K|V compact)
__device__ __half g_a16[(size_t)MROWS * DIM];             // activations fp16
__device__ __half g_wqT[(size_t)QKV_N * DIM];             // Wqkv^T fp16
__device__ __half g_wpT[(size_t)DIM * DIM];               // Wproj^T fp16
__device__ int g_rowlist[KVROWS];

// ---------------------------------------------------------------------------
// Helpers (baseline compute_100-safe PTX)
// ---------------------------------------------------------------------------
__device__ __forceinline__ uint32_t smem_u32(const void* p) {
    uint32_t a;
    asm("{ .reg .u64 t; cvta.to.shared.u64 t, %1; cvt.u32.u64 %0, t; }"
        : "=r"(a) : "l"(p));
    return a;
}

#define LDSM_X4(r0, r1, r2, r3, addr)                                         \
    asm volatile("ldmatrix.sync.aligned.m8n8.x4.shared.b16 {%0,%1,%2,%3}, [%4];" \
                 : "=r"(r0), "=r"(r1), "=r"(r2), "=r"(r3) : "r"(addr))

#define MMA16816F(c, a0, a1, a2, a3, b0, b1)                                  \
    asm volatile("mma.sync.aligned.m16n8k16.row.col.f32.f16.f16.f32 "         \
                 "{%0,%1,%2,%3}, {%4,%5,%6,%7}, {%8,%9}, {%0,%1,%2,%3};"      \
                 : "+f"((c)[0]), "+f"((c)[1]), "+f"((c)[2]), "+f"((c)[3])     \
                 : "r"(a0), "r"(a1), "r"(a2), "r"(a3), "r"(b0), "r"(b1))

#define CP_ASYNC16(sm, gm)                                                    \
    asm volatile("cp.async.cg.shared.global [%0], [%1], 16;"                  \
                 :: "r"(sm), "l"(gm))
#define CP_COMMIT()  asm volatile("cp.async.commit_group;" ::: "memory")
#define CP_WAIT0()   asm volatile("cp.async.wait_group 0;" ::: "memory")

// ---------------------------------------------------------------------------
// GEMM tile geometry: 2 tiles per buffer (A, B)
// ---------------------------------------------------------------------------
#define GBM 128
#define GBN 128
#define GBK 32
#define SP 40
#define TILE_B (128 * SP * 2)        // 10240 B per tile
#define BUF_B  (2 * TILE_B)          // A, B
#define GEMM_SMEM (2 * BUF_B)        // 40960 B
#define KDIM 1024

// 1-pass fp16 GEMM core: C = A[rows][K] * B[N,K]^T + bias  (fp32 accum)
__device__ __forceinline__ void gemm_core(
    const __half* __restrict__ A, const __half* __restrict__ BT,
    const float* __restrict__ bias, float* __restrict__ C,
    const int* __restrict__ Arows,
    int m0, int n0, int N, char* smem)
{
    const uint32_t sb = smem_u32(smem);
    const int tid  = threadIdx.x;
    const int wid  = tid >> 5;
    const int lane = tid & 31;
    const int warp_m = wid & 1;
    const int warp_n = wid >> 1;

    float acc[4][8][4];
    #pragma unroll
    for (int i = 0; i < 4; i++)
        #pragma unroll
        for (int j = 0; j < 8; j++)
            #pragma unroll
            for (int q = 0; q < 4; q++)
                acc[i][j][q] = 0.0f;

    const int rbase = tid >> 2;
    const int c4    = tid & 3;
    int arow4[4];
    #pragma unroll
    for (int p = 0; p < 4; p++) {
        int r = m0 + rbase + 32 * p;
        arow4[p] = Arows ? Arows[r] : r;
    }
    const __half* bp = BT + (size_t)(n0 + rbase) * KDIM + c4 * 8;
    const uint32_t so0 = rbase * (SP * 2) + c4 * 16;

#define CPA_TILES(buf, k0) do {                                               \
    uint32_t _b = sb + (buf) * BUF_B;                                         \
    _Pragma("unroll")                                                         \
    for (int p = 0; p < 4; p++) {                                             \
        uint32_t _so = so0 + p * (32 * SP * 2);                               \
        CP_ASYNC16(_b + 0 * TILE_B + _so,                                     \
                   A + (size_t)arow4[p] * KDIM + c4 * 8 + (k0));              \
        CP_ASYNC16(_b + 1 * TILE_B + _so, bp + (size_t)p * 32 * KDIM + (k0)); \
    } } while (0)

    const int a_lrow = (lane & 7) + ((lane >> 3) & 1) * 8;
    const int a_lcol = ((lane >> 4) & 1) * 8;
    const int b_lrow = (lane & 7) + ((lane >> 4) & 1) * 8;
    const int b_lcol = ((lane >> 3) & 1) * 8;

    const int niter = KDIM / GBK;

    CPA_TILES(0, 0);
    CP_COMMIT();
    CP_WAIT0();
    __syncthreads();

    for (int it = 0; it < niter; it++) {
        const uint32_t bufb = sb + (it & 1) * BUF_B;

        if (it + 1 < niter) {
            CPA_TILES((it + 1) & 1, (it + 1) * GBK);
            CP_COMMIT();
        }

        #pragma unroll
        for (int ks = 0; ks < 2; ks++) {
            uint32_t ah[4][4], bb[8][2];

            #pragma unroll
            for (int i = 0; i < 4; i++) {
                int arow = warp_m * 64 + i * 16 + a_lrow;
                uint32_t ad = bufb + 0 * TILE_B +
                              arow * (SP * 2) + (ks * 16 + a_lcol) * 2;
                LDSM_X4(ah[i][0], ah[i][1], ah[i][2], ah[i][3], ad);
            }
            #pragma unroll
            for (int jp = 0; jp < 4; jp++) {
                int nrow = warp_n * 64 + jp * 16 + b_lrow;
                uint32_t bd = bufb + 1 * TILE_B +
                              nrow * (SP * 2) + (ks * 16 + b_lcol) * 2;
                LDSM_X4(bb[jp * 2][0], bb[jp * 2][1],
                        bb[jp * 2 + 1][0], bb[jp * 2 + 1][1], bd);
            }
            #pragma unroll
            for (int i = 0; i < 4; i++)
                #pragma unroll
                for (int j = 0; j < 8; j++)
                    MMA16816F(acc[i][j], ah[i][0], ah[i][1], ah[i][2], ah[i][3],
                              bb[j][0], bb[j][1]);
        }

        if (it + 1 < niter) {
            CP_WAIT0();
            __syncthreads();
        }
    }

    const int g  = lane >> 2;
    const int tq = lane & 3;
    #pragma unroll
    for (int i = 0; i < 4; i++) {
        #pragma unroll
        for (int j = 0; j < 8; j++) {
            int col = n0 + warp_n * 64 + j * 8 + tq * 2;
            float2 bz = *(const float2*)(bias + col);
            int row_a = m0 + warp_m * 64 + i * 16 + g;
            float2 o0 = { acc[i][j][0] + bz.x, acc[i][j][1] + bz.y };
            float2 o1 = { acc[i][j][2] + bz.x, acc[i][j][3] + bz.y };
            *(float2*)(C + (size_t)row_a * N + col) = o0;
            *(float2*)(C + (size_t)(row_a + 8) * N + col) = o1;
        }
    }
#undef CPA_TILES
}

// ---------------------------------------------------------------------------
// Fused Q + KV projection (768 blocks)
// ---------------------------------------------------------------------------
__global__ __launch_bounds__(128, 2) void gemm_qkv_fused(
    const __half* __restrict__ A, const __half* __restrict__ WqT,
    const float* __restrict__ bqkv, float* __restrict__ q,
    float* __restrict__ kvo, const int* __restrict__ rowlist)
{
    extern __shared__ char smem[];
    int bx = blockIdx.x;
    if (bx < 512) {
        int m0 = (bx >> 3) * GBM, n0 = (bx & 7) * GBN;
        gemm_core(A, WqT, bqkv, q, nullptr, m0, n0, DIM, smem);
    } else {
        bx -= 512;
        int m0 = (bx >> 4) * GBM, n0 = (bx & 15) * GBN;
        gemm_core(A, WqT + (size_t)DIM * KDIM,
                  bqkv + DIM, kvo, rowlist, m0, n0, 2 * DIM, smem);
    }
}

// ---------------------------------------------------------------------------
// Output projection GEMM
// ---------------------------------------------------------------------------
__global__ __launch_bounds__(128, 2) void gemm_proj(
    const __half* __restrict__ A, const __half* __restrict__ BT,
    const float* __restrict__ bias, float* __restrict__ C)
{
    extern __shared__ char smem[];
    int m0 = blockIdx.y * GBM, n0 = blockIdx.x * GBN;
    gemm_core(A, BT, bias, C, nullptr, m0, n0, DIM, smem);
}

// ---------------------------------------------------------------------------
// Prepass: elementwise fp32 -> fp16 cast (x only)
// ---------------------------------------------------------------------------
__global__ __launch_bounds__(256) void cast_f16(
    const float* __restrict__ in, __half* __restrict__ o16, int n4)
{
    int i = blockIdx.x * 256 + threadIdx.x;
    if (i >= n4) return;
    float4 x = ((const float4*)in)[i];
    ((__half2*)o16)[i * 2]     = __halves2half2(__float2half_rn(x.x),
                                                __float2half_rn(x.y));
    ((__half2*)o16)[i * 2 + 1] = __halves2half2(__float2half_rn(x.z),
                                                __float2half_rn(x.w));
}

// ---------------------------------------------------------------------------
// Prepass: W[K][N] fp32 -> W^T [N][K] fp16
// ---------------------------------------------------------------------------
__global__ __launch_bounds__(256) void transpose_f16(
    const float* __restrict__ W, __half* __restrict__ T, int K, int N)
{
    __shared__ float t[32][33];
    const int kb = blockIdx.y * 32, nb = blockIdx.x * 32;
    const int tx = threadIdx.x, ty = threadIdx.y;
    #pragma unroll
    for (int s = 0; s < 32; s += 8)
        t[ty + s][tx] = W[(size_t)(kb + ty + s) * N + nb + tx];
    __syncthreads();
    #pragma unroll
    for (int s = 0; s < 32; s += 8) {
        int nn = nb + ty + s, kk = kb + tx;
        T[(size_t)nn * K + kk] = __float2half_rn(t[tx][ty + s]);
    }
}

// ---------------------------------------------------------------------------
// Prepass: compact KV row list
// ---------------------------------------------------------------------------
__global__ void build_rowlist(const int* __restrict__ mapping,
                              int* __restrict__ rowlist)
{
    int i = blockIdx.x * 256 + threadIdx.x;
    if (i >= KVROWS) return;
    int b = i >> 10, r = i & 1023, seg = r >> 6, j = r & 63;
    rowlist[i] = b * SEQ + mapping[seg * 256 + 4 * j];
}

// ---------------------------------------------------------------------------
// Attention kernel (Round 10 structure; single fp16 epilogue)
// ---------------------------------------------------------------------------
#define TILE_STRIDE 65
#define TILE_FLOATS (64 * TILE_STRIDE)
#define ATTN_SMEM_BYTES ((4 * TILE_FLOATS + 128) * 4)

__global__ __launch_bounds__(256) void attn_kernel(
    const float* __restrict__ q, const float* __restrict__ kv,
    const int* __restrict__ mapping, __half* __restrict__ out16)
{
    extern __shared__ float sm[];
    float* Qs   = sm;
    float* Ks   = sm + TILE_FLOATS;
    float* Vs   = sm + 2 * TILE_FLOATS;
    float* Ss   = sm + 3 * TILE_FLOATS;
    float* cmax = sm + 4 * TILE_FLOATS;
    float* lsum = sm + 4 * TILE_FLOATS + 64;

    __shared__ int qrow[64];
    __shared__ int seg_s;

    const int t = threadIdx.x;
    const int n = blockIdx.x;
    const int h = blockIdx.y;
    const int b = blockIdx.z;

    if (t < 64) {
        int qr = mapping[n * 64 + t];
        qrow[t] = qr;
        if (t == 0) seg_s = qr >> 8;
    }
    __syncthreads();

    const float scale = 0.125f;
    const int hoff = h * HDIM;
    const size_t kvrow0 = ((size_t)b * 1024 + seg_s * 64) * (2 * DIM);

    #pragma unroll
    for (int p = 0; p < 4; p++) {
        int idx = t + 256 * p;
        int m = idx >> 4, d = (idx & 15) * 4;
        float4 qv = *(const float4*)(q + ((size_t)b * SEQ + qrow[m]) * DIM + hoff + d);
        float4 kvv = *(const float4*)(kv + kvrow0 + (size_t)m * 2 * DIM + hoff + d);
        float4 vv  = *(const float4*)(kv + kvrow0 + (size_t)m * 2 * DIM + DIM + hoff + d);
        float* qp = Qs + m * TILE_STRIDE + d;
        qp[0] = qv.x * scale; qp[1] = qv.y * scale;
        qp[2] = qv.z * scale; qp[3] = qv.w * scale;
        float* kp = Ks + m * TILE_STRIDE + d;
        kp[0] = kvv.x; kp[1] = kvv.y; kp[2] = kvv.z; kp[3] = kvv.w;
        float* vp = Vs + m * TILE_STRIDE + d;
        vp[0] = vv.x; vp[1] = vv.y; vp[2] = vv.z; vp[3] = vv.w;
    }
    __syncthreads();

    {
        int tm = t >> 4, ts = t & 15;
        float sc[4][4];
        #pragma unroll
        for (int i = 0; i < 4; i++)
            #pragma unroll
            for (int j = 0; j < 4; j++)
                sc[i][j] = 0.0f;
        #pragma unroll
        for (int d = 0; d < 64; d++) {
            float qv[4], kvr[4];
            #pragma unroll
            for (int i = 0; i < 4; i++)
                qv[i] = Qs[(tm * 4 + i) * TILE_STRIDE + d];
            #pragma unroll
            for (int j = 0; j < 4; j++)
                kvr[j] = Ks[(ts + 16 * j) * TILE_STRIDE + d];
            #pragma unroll
            for (int i = 0; i < 4; i++)
                #pragma unroll
                for (int j = 0; j < 4; j++)
                    sc[i][j] += qv[i] * kvr[j];
        }
        #pragma unroll
        for (int i = 0; i < 4; i++)
            #pragma unroll
            for (int j = 0; j < 4; j++)
                Ss[(tm * 4 + i) * TILE_STRIDE + ts + 16 * j] = sc[i][j];
    }
    __syncthreads();

    {
        int s = t >> 2, mq0 = (t & 3) * 16;
        float mx = -1e30f;
        #pragma unroll
        for (int m = 0; m < 16; m++)
            mx = fmaxf(mx, Ss[(mq0 + m) * TILE_STRIDE + s]);
        mx = fmaxf(mx, __shfl_xor_sync(0xFFFFFFFF, mx, 1));
        mx = fmaxf(mx, __shfl_xor_sync(0xFFFFFFFF, mx, 2));
        if ((t & 3) == 0) cmax[s] = mx;
    }
    __syncthreads();

    {
        int m = t >> 2, s0 = (t & 3) * 16;
        float sum = 0.0f;
        #pragma unroll
        for (int s = 0; s < 16; s++) {
            float e = __expf(Ss[m * TILE_STRIDE + s0 + s] - cmax[s0 + s]);
            Ss[m * TILE_STRIDE + s0 + s] = e;
            sum += e;
        }
        sum += __shfl_xor_sync(0xFFFFFFFF, sum, 1);
        sum += __shfl_xor_sync(0xFFFFFFFF, sum, 2);
        if ((t & 3) == 0) lsum[m] = 1e-6f + sum;
    }
    __syncthreads();

    {
        int tm = t >> 4, td = t & 15;
        float acc[4][4];
        #pragma unroll
        for (int i = 0; i < 4; i++)
            #pragma unroll
            for (int j = 0; j < 4; j++)
                acc[i][j] = 0.0f;
        #pragma unroll
        for (int s = 0; s < 64; s++) {
            float pv[4], vv[4];
            #pragma unroll
            for (int i = 0; i < 4; i++)
                pv[i] = Ss[(tm * 4 + i) * TILE_STRIDE + s];
            #pragma unroll
            for (int j = 0; j < 4; j++)
                vv[j] = Vs[s * TILE_STRIDE + td + 16 * j];
            #pragma unroll
            for (int i = 0; i < 4; i++)
                #pragma unroll
                for (int j = 0; j < 4; j++)
                    acc[i][j] += pv[i] * vv[j];
        }
        #pragma unroll
        for (int i = 0; i < 4; i++) {
            float inv = 1.0f / lsum[tm * 4 + i];
            size_t orow = ((size_t)b * SEQ + n * 64 + tm * 4 + i) * DIM + hoff;
            #pragma unroll
            for (int j = 0; j < 4; j++)
                out16[orow + td + 16 * j] = __float2half_rn(acc[i][j] * inv);
        }
    }
}

// ---------------------------------------------------------------------------
// Launch
// ---------------------------------------------------------------------------
extern "C" void kernel_launch(void* const* d_in, const int* in_sizes, int n_in,
                              void* d_out, int out_size)
{
    const float* x     = (const float*)d_in[0];
    const float* Wqkv  = (const float*)d_in[1];
    const float* bqkv  = (const float*)d_in[2];
    const float* Wproj = (const float*)d_in[3];
    const float* bproj = (const float*)d_in[4];
    const int*   mapping = (const int*)d_in[5];
    float* out = (float*)d_out;

    float *q, *kv;
    int* rowlist;
    __half *a16, *wqT, *wpT;
    cudaGetSymbolAddress((void**)&q,   g_q);
    cudaGetSymbolAddress((void**)&kv,  g_kv);
    cudaGetSymbolAddress((void**)&rowlist, g_rowlist);
    cudaGetSymbolAddress((void**)&a16, g_a16);
    cudaGetSymbolAddress((void**)&wqT, g_wqT);
    cudaGetSymbolAddress((void**)&wpT, g_wpT);

    cudaFuncSetAttribute(attn_kernel,
                         cudaFuncAttributeMaxDynamicSharedMemorySize, ATTN_SMEM_BYTES);
    cudaFuncSetAttribute(gemm_qkv_fused,
                         cudaFuncAttributeMaxDynamicSharedMemorySize, GEMM_SMEM);
    cudaFuncSetAttribute(gemm_proj,
                         cudaFuncAttributeMaxDynamicSharedMemorySize, GEMM_SMEM);

    const int n4 = MROWS * DIM / 4;

    // Prepasses
    cast_f16<<<(n4 + 255) / 256, 256>>>(x, a16, n4);
    transpose_f16<<<dim3(QKV_N / 32, DIM / 32), dim3(32, 8)>>>(Wqkv, wqT, DIM, QKV_N);
    transpose_f16<<<dim3(DIM / 32, DIM / 32), dim3(32, 8)>>>(Wproj, wpT, DIM, DIM);
    build_rowlist<<<KVROWS / 256, 256>>>(mapping, rowlist);

    // 1) Fused Q + KV projection (1-pass fp16)
    gemm_qkv_fused<<<768, 128, GEMM_SMEM>>>(a16, wqT, bqkv, q, kv, rowlist);

    // 2) Hilbert block attention -> fp16 (overwrites g_a16)
    attn_kernel<<<dim3(NBLK, NHEAD, BATCH), 256, ATTN_SMEM_BYTES>>>(
        q, kv, mapping, a16);

    // 3) Output projection (1-pass fp16)
    gemm_proj<<<dim3(DIM / GBN, MROWS / GBM), 128, GEMM_SMEM>>>(
        a16, wpT, bproj, out);
}

// round 15
// speedup vs baseline: 7.2121x; 1.0582x over previous
#include <cuda_runtime.h>
#include <cuda_bf16.h>
#include <cuda_fp16.h>
#include <cstdint>

// ---------------------------------------------------------------------------
// Problem constants
// ---------------------------------------------------------------------------
#define BATCH 2
#define SEQ   4096
#define DIM   1024
#define NHEAD 16
#define HDIM  64
#define NBLK  64
#define QKV_N 3072
#define MROWS (BATCH * SEQ)          // 8192
#define KVROWS 2048                  // 2 batches * 16 segs * 64 keys

// ---------------------------------------------------------------------------
// Scratch (static device globals; no cudaMalloc allowed)
// ---------------------------------------------------------------------------
__device__ float g_q[(size_t)MROWS * DIM];                // 32 MB
__device__ float g_kv[(size_t)KVROWS * 2 * DIM];          // 16 MB (K|V compact)
__device__ __half g_a16[(size_t)MROWS * DIM];             // activations fp16
__device__ __half g_wqT[(size_t)QKV_N * DIM];             // Wqkv^T fp16
__device__ __half g_wpT[(size_t)DIM * DIM];               // Wproj^T fp16
__device__ int g_rowlist[KVROWS];

// ---------------------------------------------------------------------------
// Helpers (baseline compute_100-safe PTX)
// ---------------------------------------------------------------------------
__device__ __forceinline__ uint32_t smem_u32(const void* p) {
    uint32_t a;
    asm("{ .reg .u64 t; cvta.to.shared.u64 t, %1; cvt.u32.u64 %0, t; }"
        : "=r"(a) : "l"(p));
    return a;
}

#define LDSM_X4(r0, r1, r2, r3, addr)                                         \
    asm volatile("ldmatrix.sync.aligned.m8n8.x4.shared.b16 {%0,%1,%2,%3}, [%4];" \
                 : "=r"(r0), "=r"(r1), "=r"(r2), "=r"(r3) : "r"(addr))

#define MMA16816F(c, a0, a1, a2, a3, b0, b1)                                  \
    asm volatile("mma.sync.aligned.m16n8k16.row.col.f32.f16.f16.f32 "         \
                 "{%0,%1,%2,%3}, {%4,%5,%6,%7}, {%8,%9}, {%0,%1,%2,%3};"      \
                 : "+f"((c)[0]), "+f"((c)[1]), "+f"((c)[2]), "+f"((c)[3])     \
                 : "r"(a0), "r"(a1), "r"(a2), "r"(a3), "r"(b0), "r"(b1))

#define CP_ASYNC16(sm, gm)                                                    \
    asm volatile("cp.async.cg.shared.global [%0], [%1], 16;"                  \
                 :: "r"(sm), "l"(gm))
#define CP_COMMIT()  asm volatile("cp.async.commit_group;" ::: "memory")
#define CP_WAIT0()   asm volatile("cp.async.wait_group 0;" ::: "memory")

// ---------------------------------------------------------------------------
// GEMM tile geometry: 2 tiles per buffer (A, B)   (validated Round 14)
// ---------------------------------------------------------------------------
#define GBM 128
#define GBN 128
#define GBK 32
#define SP 40
#define TILE_B (128 * SP * 2)        // 10240 B per tile
#define BUF_B  (2 * TILE_B)          // A, B
#define GEMM_SMEM (2 * BUF_B)        // 40960 B
#define KDIM 1024

// 1-pass fp16 GEMM core: C = A[rows][K] * B[N,K]^T + bias  (fp32 accum)
__device__ __forceinline__ void gemm_core(
    const __half* __restrict__ A, const __half* __restrict__ BT,
    const float* __restrict__ bias, float* __restrict__ C,
    const int* __restrict__ Arows,
    int m0, int n0, int N, char* smem)
{
    const uint32_t sb = smem_u32(smem);
    const int tid  = threadIdx.x;
    const int wid  = tid >> 5;
    const int lane = tid & 31;
    const int warp_m = wid & 1;
    const int warp_n = wid >> 1;

    float acc[4][8][4];
    #pragma unroll
    for (int i = 0; i < 4; i++)
        #pragma unroll
        for (int j = 0; j < 8; j++)
            #pragma unroll
            for (int q = 0; q < 4; q++)
                acc[i][j][q] = 0.0f;

    const int rbase = tid >> 2;
    const int c4    = tid & 3;
    int arow4[4];
    #pragma unroll
    for (int p = 0; p < 4; p++) {
        int r = m0 + rbase + 32 * p;
        arow4[p] = Arows ? Arows[r] : r;
    }
    const __half* bp = BT + (size_t)(n0 + rbase) * KDIM + c4 * 8;
    const uint32_t so0 = rbase * (SP * 2) + c4 * 16;

#define CPA_TILES(buf, k0) do {                                               \
    uint32_t _b = sb + (buf) * BUF_B;                                         \
    _Pragma("unroll")                                                         \
    for (int p = 0; p < 4; p++) {                                             \
        uint32_t _so = so0 + p * (32 * SP * 2);                               \
        CP_ASYNC16(_b + 0 * TILE_B + _so,                                     \
                   A + (size_t)arow4[p] * KDIM + c4 * 8 + (k0));              \
        CP_ASYNC16(_b + 1 * TILE_B + _so, bp + (size_t)p * 32 * KDIM + (k0)); \
    } } while (0)

    const int a_lrow = (lane & 7) + ((lane >> 3) & 1) * 8;
    const int a_lcol = ((lane >> 4) & 1) * 8;
    const int b_lrow = (lane & 7) + ((lane >> 4) & 1) * 8;
    const int b_lcol = ((lane >> 3) & 1) * 8;

    const int niter = KDIM / GBK;

    CPA_TILES(0, 0);
    CP_COMMIT();
    CP_WAIT0();
    __syncthreads();

    for (int it = 0; it < niter; it++) {
        const uint32_t bufb = sb + (it & 1) * BUF_B;

        if (it + 1 < niter) {
            CPA_TILES((it + 1) & 1, (it + 1) * GBK);
            CP_COMMIT();
        }

        #pragma unroll
        for (int ks = 0; ks < 2; ks++) {
            uint32_t ah[4][4], bb[8][2];

            #pragma unroll
            for (int i = 0; i < 4; i++) {
                int arow = warp_m * 64 + i * 16 + a_lrow;
                uint32_t ad = bufb + 0 * TILE_B +
                              arow * (SP * 2) + (ks * 16 + a_lcol) * 2;
                LDSM_X4(ah[i][0], ah[i][1], ah[i][2], ah[i][3], ad);
            }
            #pragma unroll
            for (int jp = 0; jp < 4; jp++) {
                int nrow = warp_n * 64 + jp * 16 + b_lrow;
                uint32_t bd = bufb + 1 * TILE_B +
                              nrow * (SP * 2) + (ks * 16 + b_lcol) * 2;
                LDSM_X4(bb[jp * 2][0], bb[jp * 2][1],
                        bb[jp * 2 + 1][0], bb[jp * 2 + 1][1], bd);
            }
            #pragma unroll
            for (int i = 0; i < 4; i++)
                #pragma unroll
                for (int j = 0; j < 8; j++)
                    MMA16816F(acc[i][j], ah[i][0], ah[i][1], ah[i][2], ah[i][3],
                              bb[j][0], bb[j][1]);
        }

        if (it + 1 < niter) {
            CP_WAIT0();
            __syncthreads();
        }
    }

    const int g  = lane >> 2;
    const int tq = lane & 3;
    #pragma unroll
    for (int i = 0; i < 4; i++) {
        #pragma unroll
        for (int j = 0; j < 8; j++) {
            int col = n0 + warp_n * 64 + j * 8 + tq * 2;
            float2 bz = *(const float2*)(bias + col);
            int row_a = m0 + warp_m * 64 + i * 16 + g;
            float2 o0 = { acc[i][j][0] + bz.x, acc[i][j][1] + bz.y };
            float2 o1 = { acc[i][j][2] + bz.x, acc[i][j][3] + bz.y };
            *(float2*)(C + (size_t)row_a * N + col) = o0;
            *(float2*)(C + (size_t)(row_a + 8) * N + col) = o1;
        }
    }
#undef CPA_TILES
}

// ---------------------------------------------------------------------------
// Fused Q + KV projection (768 blocks)
// ---------------------------------------------------------------------------
__global__ __launch_bounds__(128, 2) void gemm_qkv_fused(
    const __half* __restrict__ A, const __half* __restrict__ WqT,
    const float* __restrict__ bqkv, float* __restrict__ q,
    float* __restrict__ kvo, const int* __restrict__ rowlist)
{
    extern __shared__ char smem[];
    int bx = blockIdx.x;
    if (bx < 512) {
        int m0 = (bx >> 3) * GBM, n0 = (bx & 7) * GBN;
        gemm_core(A, WqT, bqkv, q, nullptr, m0, n0, DIM, smem);
    } else {
        bx -= 512;
        int m0 = (bx >> 4) * GBM, n0 = (bx & 15) * GBN;
        gemm_core(A, WqT + (size_t)DIM * KDIM,
                  bqkv + DIM, kvo, rowlist, m0, n0, 2 * DIM, smem);
    }
}

// ---------------------------------------------------------------------------
// Output projection GEMM
// ---------------------------------------------------------------------------
__global__ __launch_bounds__(128, 2) void gemm_proj(
    const __half* __restrict__ A, const __half* __restrict__ BT,
    const float* __restrict__ bias, float* __restrict__ C)
{
    extern __shared__ char smem[];
    int m0 = blockIdx.y * GBM, n0 = blockIdx.x * GBN;
    gemm_core(A, BT, bias, C, nullptr, m0, n0, DIM, smem);
}

// ---------------------------------------------------------------------------
// Mega prepass: one launch, 4 independent sections, uniform 256 threads.
//   [0, 8192):          cast x fp32 -> fp16            (8192*256 float4)
//   [8192, 11264):      transpose Wqkv -> wqT fp16     (96 x 32 tiles)
//   [11264, 12288):     transpose Wproj -> wpT fp16    (32 x 32 tiles)
//   [12288, 12296):     build rowlist                  (8*256 entries)
// ---------------------------------------------------------------------------
#define PRE_CAST_BLKS 8192
#define PRE_WQ_BLKS   (96 * 32)
#define PRE_WP_BLKS   (32 * 32)
#define PRE_RL_BLKS   (KVROWS / 256)
#define PRE_TOTAL (PRE_CAST_BLKS + PRE_WQ_BLKS + PRE_WP_BLKS + PRE_RL_BLKS)

__device__ __forceinline__ void transpose_tile(
    const float* __restrict__ W, __half* __restrict__ T,
    int K, int N, int bxl, int nbx, float (*t)[33])
{
    const int nb = (bxl % nbx) * 32;
    const int kb = (bxl / nbx) * 32;
    const int tx = threadIdx.x & 31;
    const int ty = threadIdx.x >> 5;          // 0..7
    #pragma unroll
    for (int s = 0; s < 32; s += 8)
        t[ty + s][tx] = W[(size_t)(kb + ty + s) * N + nb + tx];
    __syncthreads();
    #pragma unroll
    for (int s = 0; s < 32; s += 8) {
        int nn = nb + ty + s, kk = kb + tx;
        T[(size_t)nn * K + kk] = __float2half_rn(t[tx][ty + s]);
    }
}

__global__ __launch_bounds__(256) void prepass_all(
    const float* __restrict__ x, __half* __restrict__ a16,
    const float* __restrict__ Wqkv, __half* __restrict__ wqT,
    const float* __restrict__ Wproj, __half* __restrict__ wpT,
    const int* __restrict__ mapping, int* __restrict__ rowlist)
{
    __shared__ float t[32][33];
    const int bx = blockIdx.x;
    if (bx < PRE_CAST_BLKS) {
        int i = bx * 256 + threadIdx.x;
        float4 v = ((const float4*)x)[i];
        ((__half2*)a16)[i * 2]     = __halves2half2(__float2half_rn(v.x),
                                                    __float2half_rn(v.y));
        ((__half2*)a16)[i * 2 + 1] = __halves2half2(__float2half_rn(v.z),
                                                    __float2half_rn(v.w));
    } else if (bx < PRE_CAST_BLKS + PRE_WQ_BLKS) {
        transpose_tile(Wqkv, wqT, DIM, QKV_N, bx - PRE_CAST_BLKS, 96, t);
    } else if (bx < PRE_CAST_BLKS + PRE_WQ_BLKS + PRE_WP_BLKS) {
        transpose_tile(Wproj, wpT, DIM, DIM,
                       bx - PRE_CAST_BLKS - PRE_WQ_BLKS, 32, t);
    } else {
        int i = (bx - PRE_CAST_BLKS - PRE_WQ_BLKS - PRE_WP_BLKS) * 256
                + threadIdx.x;
        int b = i >> 10, r = i & 1023, seg = r >> 6, j = r & 63;
        rowlist[i] = b * SEQ + mapping[seg * 256 + 4 * j];
    }
}

// ---------------------------------------------------------------------------
// Attention kernel: 3-tile smem (S overlays K after scores) -> 50.4 KB
// -> 4 blocks/SM. Column-max softmax, 4x4 micro-tiles, fp16 epilogue.
// ---------------------------------------------------------------------------
#define TILE_STRIDE 65
#define TILE_FLOATS (64 * TILE_STRIDE)
#define ATTN_SMEM_BYTES ((3 * TILE_FLOATS + 128) * 4)   // 50432 B

__global__ __launch_bounds__(256) void attn_kernel(
    const float* __restrict__ q, const float* __restrict__ kv,
    const int* __restrict__ mapping, __half* __restrict__ out16)
{
    extern __shared__ float sm[];
    float* Qs   = sm;
    float* Ks   = sm + TILE_FLOATS;
    float* Vs   = sm + 2 * TILE_FLOATS;
    float* Ss   = Ks;                          // S overlays K (dead after scores)
    float* cmax = sm + 3 * TILE_FLOATS;
    float* lsum = sm + 3 * TILE_FLOATS + 64;

    __shared__ int qrow[64];
    __shared__ int seg_s;

    const int t = threadIdx.x;
    const int n = blockIdx.x;
    const int h = blockIdx.y;
    const int b = blockIdx.z;

    if (t < 64) {
        int qr = mapping[n * 64 + t];
        qrow[t] = qr;
        if (t == 0) seg_s = qr >> 8;
    }
    __syncthreads();

    const float scale = 0.125f;
    const int hoff = h * HDIM;
    const size_t kvrow0 = ((size_t)b * 1024 + seg_s * 64) * (2 * DIM);

    #pragma unroll
    for (int p = 0; p < 4; p++) {
        int idx = t + 256 * p;
        int m = idx >> 4, d = (idx & 15) * 4;
        float4 qv = *(const float4*)(q + ((size_t)b * SEQ + qrow[m]) * DIM + hoff + d);
        float4 kvv = *(const float4*)(kv + kvrow0 + (size_t)m * 2 * DIM + hoff + d);
        float4 vv  = *(const float4*)(kv + kvrow0 + (size_t)m * 2 * DIM + DIM + hoff + d);
        float* qp = Qs + m * TILE_STRIDE + d;
        qp[0] = qv.x * scale; qp[1] = qv.y * scale;
        qp[2] = qv.z * scale; qp[3] = qv.w * scale;
        float* kp = Ks + m * TILE_STRIDE + d;
        kp[0] = kvv.x; kp[1] = kvv.y; kp[2] = kvv.z; kp[3] = kvv.w;
        float* vp = Vs + m * TILE_STRIDE + d;
        vp[0] = vv.x; vp[1] = vv.y; vp[2] = vv.z; vp[3] = vv.w;
    }
    __syncthreads();

    // Scores fully in registers; then sync; then write S into K's tile.
    {
        int tm = t >> 4, ts = t & 15;
        float sc[4][4];
        #pragma unroll
        for (int i = 0; i < 4; i++)
            #pragma unroll
            for (int j = 0; j < 4; j++)
                sc[i][j] = 0.0f;
        #pragma unroll
        for (int d = 0; d < 64; d++) {
            float qv[4], kvr[4];
            #pragma unroll
            for (int i = 0; i < 4; i++)
                qv[i] = Qs[(tm * 4 + i) * TILE_STRIDE + d];
            #pragma unroll
            for (int j = 0; j < 4; j++)
                kvr[j] = Ks[(ts + 16 * j) * TILE_STRIDE + d];
            #pragma unroll
            for (int i = 0; i < 4; i++)
                #pragma unroll
                for (int j = 0; j < 4; j++)
                    sc[i][j] += qv[i] * kvr[j];
        }
        __syncthreads();   // all K reads complete before S overwrites K
        #pragma unroll
        for (int i = 0; i < 4; i++)
            #pragma unroll
            for (int j = 0; j < 4; j++)
                Ss[(tm * 4 + i) * TILE_STRIDE + ts + 16 * j] = sc[i][j];
    }
    __syncthreads();

    {
        int s = t >> 2, mq0 = (t & 3) * 16;
        float mx = -1e30f;
        #pragma unroll
        for (int m = 0; m < 16; m++)
            mx = fmaxf(mx, Ss[(mq0 + m) * TILE_STRIDE + s]);
        mx = fmaxf(mx, __shfl_xor_sync(0xFFFFFFFF, mx, 1));
        mx = fmaxf(mx, __shfl_xor_sync(0xFFFFFFFF, mx, 2));
        if ((t & 3) == 0) cmax[s] = mx;
    }
    __syncthreads();

    {
        int m = t >> 2, s0 = (t & 3) * 16;
        float sum = 0.0f;
        #pragma unroll
        for (int s = 0; s < 16; s++) {
            float e = __expf(Ss[m * TILE_STRIDE + s0 + s] - cmax[s0 + s]);
            Ss[m * TILE_STRIDE + s0 + s] = e;
            sum += e;
        }
        sum += __shfl_xor_sync(0xFFFFFFFF, sum, 1);
        sum += __shfl_xor_sync(0xFFFFFFFF, sum, 2);
        if ((t & 3) == 0) lsum[m] = 1e-6f + sum;
    }
    __syncthreads();

    {
        int tm = t >> 4, td = t & 15;
        float acc[4][4];
        #pragma unroll
        for (int i = 0; i < 4; i++)
            #pragma unroll
            for (int j = 0; j < 4; j++)
                acc[i][j] = 0.0f;
        #pragma unroll
        for (int s = 0; s < 64; s++) {
            float pv[4], vv[4];
            #pragma unroll
            for (int i = 0; i < 4; i++)
                pv[i] = Ss[(tm * 4 + i) * TILE_STRIDE + s];
            #pragma unroll
            for (int j = 0; j < 4; j++)
                vv[j] = Vs[s * TILE_STRIDE + td + 16 * j];
            #pragma unroll
            for (int i = 0; i < 4; i++)
                #pragma unroll
                for (int j = 0; j < 4; j++)
                    acc[i][j] += pv[i] * vv[j];
        }
        #pragma unroll
        for (int i = 0; i < 4; i++) {
            float inv = 1.0f / lsum[tm * 4 + i];
            size_t orow = ((size_t)b * SEQ + n * 64 + tm * 4 + i) * DIM + hoff;
            #pragma unroll
            for (int j = 0; j < 4; j++)
                out16[orow + td + 16 * j] = __float2half_rn(acc[i][j] * inv);
        }
    }
}

// ---------------------------------------------------------------------------
// Launch
// ---------------------------------------------------------------------------
extern "C" void kernel_launch(void* const* d_in, const int* in_sizes, int n_in,
                              void* d_out, int out_size)
{
    const float* x     = (const float*)d_in[0];
    const float* Wqkv  = (const float*)d_in[1];
    const float* bqkv  = (const float*)d_in[2];
    const float* Wproj = (const float*)d_in[3];
    const float* bproj = (const float*)d_in[4];
    const int*   mapping = (const int*)d_in[5];
    float* out = (float*)d_out;

    float *q, *kv;
    int* rowlist;
    __half *a16, *wqT, *wpT;
    cudaGetSymbolAddress((void**)&q,   g_q);
    cudaGetSymbolAddress((void**)&kv,  g_kv);
    cudaGetSymbolAddress((void**)&rowlist, g_rowlist);
    cudaGetSymbolAddress((void**)&a16, g_a16);
    cudaGetSymbolAddress((void**)&wqT, g_wqT);
    cudaGetSymbolAddress((void**)&wpT, g_wpT);

    cudaFuncSetAttribute(attn_kernel,
                         cudaFuncAttributeMaxDynamicSharedMemorySize, ATTN_SMEM_BYTES);
    cudaFuncSetAttribute(gemm_qkv_fused,
                         cudaFuncAttributeMaxDynamicSharedMemorySize, GEMM_SMEM);
    cudaFuncSetAttribute(gemm_proj,
                         cudaFuncAttributeMaxDynamicSharedMemorySize, GEMM_SMEM);

    // 0) All prepasses in one launch
    prepass_all<<<PRE_TOTAL, 256>>>(x, a16, Wqkv, wqT, Wproj, wpT,
                                    mapping, rowlist);

    // 1) Fused Q + KV projection (1-pass fp16)
    gemm_qkv_fused<<<768, 128, GEMM_SMEM>>>(a16, wqT, bqkv, q, kv, rowlist);

    // 2) Hilbert block attention -> fp16 (overwrites g_a16)
    attn_kernel<<<dim3(NBLK, NHEAD, BATCH), 256, ATTN_SMEM_BYTES>>>(
        q, kv, mapping, a16);

    // 3) Output projection (1-pass fp16)
    gemm_proj<<<dim3(DIM / GBN, MROWS / GBM), 128, GEMM_SMEM>>>(
        a16, wpT, bproj, out);
}

// round 17
// speedup vs baseline: 8.4866x; 1.1767x over previous
#include <cuda_runtime.h>
#include <cuda_bf16.h>
#include <cuda_fp16.h>
#include <cstdint>

// ---------------------------------------------------------------------------
// Problem constants
// ---------------------------------------------------------------------------
#define BATCH 2
#define SEQ   4096
#define DIM   1024
#define NHEAD 16
#define HDIM  64
#define NBLK  64
#define QKV_N 3072
#define MROWS (BATCH * SEQ)          // 8192
#define KVROWS 2048                  // 2 batches * 16 segs * 64 keys

// ---------------------------------------------------------------------------
// Scratch (static device globals; no cudaMalloc allowed)
// ---------------------------------------------------------------------------
__device__ __half g_qh[(size_t)MROWS * DIM];              // 16 MB (Q fp16)
__device__ __half g_kvh[(size_t)KVROWS * 2 * DIM];        // 8 MB  (K|V fp16)
__device__ __half g_a16[(size_t)MROWS * DIM];             // activations fp16
__device__ __half g_wqT[(size_t)QKV_N * DIM];             // Wqkv^T fp16
__device__ __half g_wpT[(size_t)DIM * DIM];               // Wproj^T fp16
__device__ int g_rowlist[KVROWS];

// ---------------------------------------------------------------------------
// Helpers (baseline compute_100-safe PTX)
// ---------------------------------------------------------------------------
__device__ __forceinline__ uint32_t smem_u32(const void* p) {
    uint32_t a;
    asm("{ .reg .u64 t; cvta.to.shared.u64 t, %1; cvt.u32.u64 %0, t; }"
        : "=r"(a) : "l"(p));
    return a;
}

#define LDSM_X4(r0, r1, r2, r3, addr)                                         \
    asm volatile("ldmatrix.sync.aligned.m8n8.x4.shared.b16 {%0,%1,%2,%3}, [%4];" \
                 : "=r"(r0), "=r"(r1), "=r"(r2), "=r"(r3) : "r"(addr))

#define MMA16816F(c, a0, a1, a2, a3, b0, b1)                                  \
    asm volatile("mma.sync.aligned.m16n8k16.row.col.f32.f16.f16.f32 "         \
                 "{%0,%1,%2,%3}, {%4,%5,%6,%7}, {%8,%9}, {%0,%1,%2,%3};"      \
                 : "+f"((c)[0]), "+f"((c)[1]), "+f"((c)[2]), "+f"((c)[3])     \
                 : "r"(a0), "r"(a1), "r"(a2), "r"(a3), "r"(b0), "r"(b1))

#define CP_ASYNC16(sm, gm)                                                    \
    asm volatile("cp.async.cg.shared.global [%0], [%1], 16;"                  \
                 :: "r"(sm), "l"(gm))
#define CP_COMMIT()  asm volatile("cp.async.commit_group;" ::: "memory")
#define CP_WAIT0()   asm volatile("cp.async.wait_group 0;" ::: "memory")

// ---------------------------------------------------------------------------
// GEMM tile geometry (validated Round 14/15)
// ---------------------------------------------------------------------------
#define GBM 128
#define GBN 128
#define GBK 32
#define SP 40
#define TILE_B (128 * SP * 2)
#define BUF_B  (2 * TILE_B)
#define GEMM_SMEM (2 * BUF_B)        // 40960 B
#define KDIM 1024

// 1-pass fp16 GEMM core, templated output type (float or __half)
template <typename CT>
__device__ __forceinline__ void gemm_core(
    const __half* __restrict__ A, const __half* __restrict__ BT,
    const float* __restrict__ bias, CT* __restrict__ C,
    const int* __restrict__ Arows,
    int m0, int n0, int N, char* smem)
{
    const uint32_t sb = smem_u32(smem);
    const int tid  = threadIdx.x;
    const int wid  = tid >> 5;
    const int lane = tid & 31;
    const int warp_m = wid & 1;
    const int warp_n = wid >> 1;

    float acc[4][8][4];
    #pragma unroll
    for (int i = 0; i < 4; i++)
        #pragma unroll
        for (int j = 0; j < 8; j++)
            #pragma unroll
            for (int q = 0; q < 4; q++)
                acc[i][j][q] = 0.0f;

    const int rbase = tid >> 2;
    const int c4    = tid & 3;
    int arow4[4];
    #pragma unroll
    for (int p = 0; p < 4; p++) {
        int r = m0 + rbase + 32 * p;
        arow4[p] = Arows ? Arows[r] : r;
    }
    const __half* bp = BT + (size_t)(n0 + rbase) * KDIM + c4 * 8;
    const uint32_t so0 = rbase * (SP * 2) + c4 * 16;

#define CPA_TILES(buf, k0) do {                                               \
    uint32_t _b = sb + (buf) * BUF_B;                                         \
    _Pragma("unroll")                                                         \
    for (int p = 0; p < 4; p++) {                                             \
        uint32_t _so = so0 + p * (32 * SP * 2);                               \
        CP_ASYNC16(_b + 0 * TILE_B + _so,                                     \
                   A + (size_t)arow4[p] * KDIM + c4 * 8 + (k0));              \
        CP_ASYNC16(_b + 1 * TILE_B + _so, bp + (size_t)p * 32 * KDIM + (k0)); \
    } } while (0)

    const int a_lrow = (lane & 7) + ((lane >> 3) & 1) * 8;
    const int a_lcol = ((lane >> 4) & 1) * 8;
    const int b_lrow = (lane & 7) + ((lane >> 4) & 1) * 8;
    const int b_lcol = ((lane >> 3) & 1) * 8;

    const int niter = KDIM / GBK;

    CPA_TILES(0, 0);
    CP_COMMIT();
    CP_WAIT0();
    __syncthreads();

    for (int it = 0; it < niter; it++) {
        const uint32_t bufb = sb + (it & 1) * BUF_B;

        if (it + 1 < niter) {
            CPA_TILES((it + 1) & 1, (it + 1) * GBK);
            CP_COMMIT();
        }

        #pragma unroll
        for (int ks = 0; ks < 2; ks++) {
            uint32_t ah[4][4], bb[8][2];

            #pragma unroll
            for (int i = 0; i < 4; i++) {
                int arow = warp_m * 64 + i * 16 + a_lrow;
                uint32_t ad = bufb + 0 * TILE_B +
                              arow * (SP * 2) + (ks * 16 + a_lcol) * 2;
                LDSM_X4(ah[i][0], ah[i][1], ah[i][2], ah[i][3], ad);
            }
            #pragma unroll
            for (int jp = 0; jp < 4; jp++) {
                int nrow = warp_n * 64 + jp * 16 + b_lrow;
                uint32_t bd = bufb + 1 * TILE_B +
                              nrow * (SP * 2) + (ks * 16 + b_lcol) * 2;
                LDSM_X4(bb[jp * 2][0], bb[jp * 2][1],
                        bb[jp * 2 + 1][0], bb[jp * 2 + 1][1], bd);
            }
            #pragma unroll
            for (int i = 0; i < 4; i++)
                #pragma unroll
                for (int j = 0; j < 8; j++)
                    MMA16816F(acc[i][j], ah[i][0], ah[i][1], ah[i][2], ah[i][3],
                              bb[j][0], bb[j][1]);
        }

        if (it + 1 < niter) {
            CP_WAIT0();
            __syncthreads();
        }
    }

    const int g  = lane >> 2;
    const int tq = lane & 3;
    #pragma unroll
    for (int i = 0; i < 4; i++) {
        #pragma unroll
        for (int j = 0; j < 8; j++) {
            int col = n0 + warp_n * 64 + j * 8 + tq * 2;
            float2 bz = *(const float2*)(bias + col);
            int row_a = m0 + warp_m * 64 + i * 16 + g;
            float v00 = acc[i][j][0] + bz.x, v01 = acc[i][j][1] + bz.y;
            float v10 = acc[i][j][2] + bz.x, v11 = acc[i][j][3] + bz.y;
            if (sizeof(CT) == 2) {
                __half2* p0 = (__half2*)((__half*)C + (size_t)row_a * N + col);
                __half2* p1 = (__half2*)((__half*)C + (size_t)(row_a + 8) * N + col);
                *p0 = __halves2half2(__float2half_rn(v00), __float2half_rn(v01));
                *p1 = __halves2half2(__float2half_rn(v10), __float2half_rn(v11));
            } else {
                float2 o0 = { v00, v01 }, o1 = { v10, v11 };
                *(float2*)((float*)C + (size_t)row_a * N + col) = o0;
                *(float2*)((float*)C + (size_t)(row_a + 8) * N + col) = o1;
            }
        }
    }
#undef CPA_TILES
}

// ---------------------------------------------------------------------------
// Fused Q + KV projection (768 blocks) -> fp16 outputs
// ---------------------------------------------------------------------------
__global__ __launch_bounds__(128, 2) void gemm_qkv_fused(
    const __half* __restrict__ A, const __half* __restrict__ WqT,
    const float* __restrict__ bqkv, __half* __restrict__ qo,
    __half* __restrict__ kvo, const int* __restrict__ rowlist)
{
    extern __shared__ char smem[];
    int bx = blockIdx.x;
    if (bx < 512) {
        int m0 = (bx >> 3) * GBM, n0 = (bx & 7) * GBN;
        gemm_core<__half>(A, WqT, bqkv, qo, nullptr, m0, n0, DIM, smem);
    } else {
        bx -= 512;
        int m0 = (bx >> 4) * GBM, n0 = (bx & 15) * GBN;
        gemm_core<__half>(A, WqT + (size_t)DIM * KDIM,
                          bqkv + DIM, kvo, rowlist, m0, n0, 2 * DIM, smem);
    }
}

// ---------------------------------------------------------------------------
// Output projection GEMM -> fp32
// ---------------------------------------------------------------------------
__global__ __launch_bounds__(128, 2) void gemm_proj(
    const __half* __restrict__ A, const __half* __restrict__ BT,
    const float* __restrict__ bias, float* __restrict__ C)
{
    extern __shared__ char smem[];
    int m0 = blockIdx.y * GBM, n0 = blockIdx.x * GBN;
    gemm_core<float>(A, BT, bias, C, nullptr, m0, n0, DIM, smem);
}

// ---------------------------------------------------------------------------
// Mega prepass (validated Round 15)
// ---------------------------------------------------------------------------
#define PRE_CAST_BLKS 8192
#define PRE_WQ_BLKS   (96 * 32)
#define PRE_WP_BLKS   (32 * 32)
#define PRE_RL_BLKS   (KVROWS / 256)
#define PRE_TOTAL (PRE_CAST_BLKS + PRE_WQ_BLKS + PRE_WP_BLKS + PRE_RL_BLKS)

__device__ __forceinline__ void transpose_tile(
    const float* __restrict__ W, __half* __restrict__ T,
    int K, int N, int bxl, int nbx, float (*t)[33])
{
    const int nb = (bxl % nbx) * 32;
    const int kb = (bxl / nbx) * 32;
    const int tx = threadIdx.x & 31;
    const int ty = threadIdx.x >> 5;
    #pragma unroll
    for (int s = 0; s < 32; s += 8)
        t[ty + s][tx] = W[(size_t)(kb + ty + s) * N + nb + tx];
    __syncthreads();
    #pragma unroll
    for (int s = 0; s < 32; s += 8) {
        int nn = nb + ty + s, kk = kb + tx;
        T[(size_t)nn * K + kk] = __float2half_rn(t[tx][ty + s]);
    }
}

__global__ __launch_bounds__(256) void prepass_all(
    const float* __restrict__ x, __half* __restrict__ a16,
    const float* __restrict__ Wqkv, __half* __restrict__ wqT,
    const float* __restrict__ Wproj, __half* __restrict__ wpT,
    const int* __restrict__ mapping, int* __restrict__ rowlist)
{
    __shared__ float t[32][33];
    const int bx = blockIdx.x;
    if (bx < PRE_CAST_BLKS) {
        int i = bx * 256 + threadIdx.x;
        float4 v = ((const float4*)x)[i];
        ((__half2*)a16)[i * 2]     = __halves2half2(__float2half_rn(v.x),
                                                    __float2half_rn(v.y));
        ((__half2*)a16)[i * 2 + 1] = __halves2half2(__float2half_rn(v.z),
                                                    __float2half_rn(v.w));
    } else if (bx < PRE_CAST_BLKS + PRE_WQ_BLKS) {
        transpose_tile(Wqkv, wqT, DIM, QKV_N, bx - PRE_CAST_BLKS, 96, t);
    } else if (bx < PRE_CAST_BLKS + PRE_WQ_BLKS + PRE_WP_BLKS) {
        transpose_tile(Wproj, wpT, DIM, DIM,
                       bx - PRE_CAST_BLKS - PRE_WQ_BLKS, 32, t);
    } else {
        int i = (bx - PRE_CAST_BLKS - PRE_WQ_BLKS - PRE_WP_BLKS) * 256
                + threadIdx.x;
        int b = i >> 10, r = i & 1023, seg = r >> 6, j = r & 63;
        rowlist[i] = b * SEQ + mapping[seg * 256 + 4 * j];
    }
}

// ---------------------------------------------------------------------------
// Tensor-core attention.
// fp16 Q/K/V tiles (stride 72 halves = 144 B -> ldmatrix conflict-free).
// S = Q*K^T via mma (fp32), column-max softmax (scale folded into exp),
// P fp16 (overlays Q), O = P*V via mma, divide by fp32 lsum, fp16 out.
// ---------------------------------------------------------------------------
#define ASP 72
#define QS_OFF 0u
#define KS_OFF 9216u
#define VT_OFF 18432u
#define SF_OFF 27648u
#define CMAX_OFF (SF_OFF + 64u * 65u * 4u)      // 44288
#define LSUM_OFF (CMAX_OFF + 256u)              // 44544
#define ATTN_SMEM_BYTES (LSUM_OFF + 256u)       // 44800

__global__ __launch_bounds__(256) void attn_kernel(
    const __half* __restrict__ q, const __half* __restrict__ kv,
    const int* __restrict__ mapping, __half* __restrict__ out16)
{
    extern __shared__ char sm[];
    const uint32_t sb = smem_u32(sm);
    float* Sf   = (float*)(sm + SF_OFF);
    float* cmax = (float*)(sm + CMAX_OFF);
    float* lsum = (float*)(sm + LSUM_OFF);
    __half* Ps  = (__half*)(sm + QS_OFF);      // overlays Q (dead after scores)

    __shared__ int qrow[64];
    __shared__ int seg_s;

    const int t = threadIdx.x;
    const int n = blockIdx.x;
    const int h = blockIdx.y;
    const int b = blockIdx.z;
    const int lane = t & 31, wid = t >> 5;
    const int warp_m = wid & 1;                 // 32 rows
    const int warp_n = wid >> 1;                // 16 cols

    if (t < 64) {
        int qr = mapping[n * 64 + t];
        qrow[t] = qr;
        if (t == 0) seg_s = qr >> 8;
    }
    __syncthreads();

    const int hoff = h * HDIM;
    const size_t kvrow0 = ((size_t)b * 1024 + seg_s * 64) * (2 * DIM);

    // Load Q, K (coalesced) and V transposed (scatter) as fp16
    #pragma unroll
    for (int u = 0; u < 2; u++) {
        int c = t + 256 * u;
        int m = c >> 3, d8 = (c & 7) * 8;
        uint4 qv = *(const uint4*)(q + ((size_t)b * SEQ + qrow[m]) * DIM + hoff + d8);
        *(uint4*)(sm + QS_OFF + m * (ASP * 2) + d8 * 2) = qv;
        uint4 kt = *(const uint4*)(kv + kvrow0 + (size_t)m * 2 * DIM + hoff + d8);
        *(uint4*)(sm + KS_OFF + m * (ASP * 2) + d8 * 2) = kt;
        uint4 vt = *(const uint4*)(kv + kvrow0 + (size_t)m * 2 * DIM + DIM + hoff + d8);
        const __half2* vh = (const __half2*)&vt;
        #pragma unroll
        for (int j = 0; j < 4; j++) {
            *(__half*)(sm + VT_OFF + (d8 + 2 * j)     * (ASP * 2) + m * 2) = __low2half(vh[j]);
            *(__half*)(sm + VT_OFF + (d8 + 2 * j + 1) * (ASP * 2) + m * 2) = __high2half(vh[j]);
        }
    }
    __syncthreads();

    const int a_lrow = (lane & 7) + ((lane >> 3) & 1) * 8;
    const int a_lcol = ((lane >> 4) & 1) * 8;
    const int b_lrow = (lane & 7) + ((lane >> 4) & 1) * 8;
    const int b_lcol = ((lane >> 3) & 1) * 8;
    const int g  = lane >> 2;
    const int tq = lane & 3;

    // ---- Score MMA: S_raw = Q * K^T ----
    {
        float sacc[2][2][4];
        #pragma unroll
        for (int i = 0; i < 2; i++)
            #pragma unroll
            for (int j = 0; j < 2; j++)
                #pragma unroll
                for (int qq = 0; qq < 4; qq++)
                    sacc[i][j][qq] = 0.0f;

        #pragma unroll
        for (int ks = 0; ks < 4; ks++) {
            uint32_t aa[2][4], bbf[4];
            #pragma unroll
            for (int i = 0; i < 2; i++) {
                uint32_t ad = sb + QS_OFF +
                    (warp_m * 32 + i * 16 + a_lrow) * (ASP * 2) +
                    (ks * 16 + a_lcol) * 2;
                LDSM_X4(aa[i][0], aa[i][1], aa[i][2], aa[i][3], ad);
            }
            uint32_t bd = sb + KS_OFF +
                (warp_n * 16 + b_lrow) * (ASP * 2) + (ks * 16 + b_lcol) * 2;
            LDSM_X4(bbf[0], bbf[1], bbf[2], bbf[3], bd);
            #pragma unroll
            for (int i = 0; i < 2; i++)
                #pragma unroll
                for (int jn = 0; jn < 2; jn++)
                    MMA16816F(sacc[i][jn], aa[i][0], aa[i][1], aa[i][2], aa[i][3],
                              bbf[jn * 2], bbf[jn * 2 + 1]);
        }
        #pragma unroll
        for (int i = 0; i < 2; i++)
            #pragma unroll
            for (int jn = 0; jn < 2; jn++) {
                int row = warp_m * 32 + i * 16 + g;
                int col = warp_n * 16 + jn * 8 + tq * 2;
                Sf[row * 65 + col]       = sacc[i][jn][0];
                Sf[row * 65 + col + 1]   = sacc[i][jn][1];
                Sf[(row + 8) * 65 + col]     = sacc[i][jn][2];
                Sf[(row + 8) * 65 + col + 1] = sacc[i][jn][3];
            }
    }
    __syncthreads();

    // Column max over queries (on raw scores)
    {
        int s = t >> 2, mq0 = (t & 3) * 16;
        float mx = -1e30f;
        #pragma unroll
        for (int m = 0; m < 16; m++)
            mx = fmaxf(mx, Sf[(mq0 + m) * 65 + s]);
        mx = fmaxf(mx, __shfl_xor_sync(0xFFFFFFFF, mx, 1));
        mx = fmaxf(mx, __shfl_xor_sync(0xFFFFFFFF, mx, 2));
        if ((t & 3) == 0) cmax[s] = mx;
    }
    __syncthreads();

    // exp((raw - cmax) * scale), P fp16 (overlays Q), row sums fp32
    {
        int m = t >> 2, s0 = (t & 3) * 16;
        float sum = 0.0f;
        #pragma unroll
        for (int s = 0; s < 16; s++) {
            float e = __expf((Sf[m * 65 + s0 + s] - cmax[s0 + s]) * 0.125f);
            Ps[m * ASP + s0 + s] = __float2half_rn(e);
            sum += e;
        }
        sum += __shfl_xor_sync(0xFFFFFFFF, sum, 1);
        sum += __shfl_xor_sync(0xFFFFFFFF, sum, 2);
        if ((t & 3) == 0) lsum[m] = 1e-6f + sum;
    }
    __syncthreads();

    // ---- Output MMA: O = P * V  (V stored transposed [d][s]) ----
    {
        float oacc[2][2][4];
        #pragma unroll
        for (int i = 0; i < 2; i++)
            #pragma unroll
            for (int j = 0; j < 2; j++)
                #pragma unroll
                for (int qq = 0; qq < 4; qq++)
                    oacc[i][j][qq] = 0.0f;

        #pragma unroll
        for (int ks = 0; ks < 4; ks++) {
            uint32_t aa[2][4], bbf[4];
            #pragma unroll
            for (int i = 0; i < 2; i++) {
                uint32_t ad = sb + QS_OFF +
                    (warp_m * 32 + i * 16 + a_lrow) * (ASP * 2) +
                    (ks * 16 + a_lcol) * 2;
                LDSM_X4(aa[i][0], aa[i][1], aa[i][2], aa[i][3], ad);
            }
            uint32_t bd = sb + VT_OFF +
                (warp_n * 16 + b_lrow) * (ASP * 2) + (ks * 16 + b_lcol) * 2;
            LDSM_X4(bbf[0], bbf[1], bbf[2], bbf[3], bd);
            #pragma unroll
            for (int i = 0; i < 2; i++)
                #pragma unroll
                for (int jn = 0; jn < 2; jn++)
                    MMA16816F(oacc[i][jn], aa[i][0], aa[i][1], aa[i][2], aa[i][3],
                              bbf[jn * 2], bbf[jn * 2 + 1]);
        }

        #pragma unroll
        for (int i = 0; i < 2; i++)
            #pragma unroll
            for (int jn = 0; jn < 2; jn++) {
                int row = warp_m * 32 + i * 16 + g;
                int col = warp_n * 16 + jn * 8 + tq * 2;
                float inv0 = 1.0f / lsum[row];
                float inv1 = 1.0f / lsum[row + 8];
                size_t o0 = ((size_t)b * SEQ + n * 64 + row) * DIM + hoff + col;
                size_t o1 = ((size_t)b * SEQ + n * 64 + row + 8) * DIM + hoff + col;
                *(__half2*)(out16 + o0) = __halves2half2(
                    __float2half_rn(oacc[i][jn][0] * inv0),
                    __float2half_rn(oacc[i][jn][1] * inv0));
                *(__half2*)(out16 + o1) = __halves2half2(
                    __float2half_rn(oacc[i][jn][2] * inv1),
                    __float2half_rn(oacc[i][jn][3] * inv1));
            }
    }
}

// ---------------------------------------------------------------------------
// Launch
// ---------------------------------------------------------------------------
extern "C" void kernel_launch(void* const* d_in, const int* in_sizes, int n_in,
                              void* d_out, int out_size)
{
    const float* x     = (const float*)d_in[0];
    const float* Wqkv  = (const float*)d_in[1];
    const float* bqkv  = (const float*)d_in[2];
    const float* Wproj = (const float*)d_in[3];
    const float* bproj = (const float*)d_in[4];
    const int*   mapping = (const int*)d_in[5];
    float* out = (float*)d_out;

    __half *qh, *kvh, *a16, *wqT, *wpT;
    int* rowlist;
    cudaGetSymbolAddress((void**)&qh,  g_qh);
    cudaGetSymbolAddress((void**)&kvh, g_kvh);
    cudaGetSymbolAddress((void**)&rowlist, g_rowlist);
    cudaGetSymbolAddress((void**)&a16, g_a16);
    cudaGetSymbolAddress((void**)&wqT, g_wqT);
    cudaGetSymbolAddress((void**)&wpT, g_wpT);

    cudaFuncSetAttribute(attn_kernel,
                         cudaFuncAttributeMaxDynamicSharedMemorySize, ATTN_SMEM_BYTES);
    cudaFuncSetAttribute(gemm_qkv_fused,
                         cudaFuncAttributeMaxDynamicSharedMemorySize, GEMM_SMEM);
    cudaFuncSetAttribute(gemm_proj,
                         cudaFuncAttributeMaxDynamicSharedMemorySize, GEMM_SMEM);

    // 0) All prepasses in one launch
    prepass_all<<<PRE_TOTAL, 256>>>(x, a16, Wqkv, wqT, Wproj, wpT,
                                    mapping, rowlist);

    // 1) Fused Q + KV projection -> fp16 q / kv
    gemm_qkv_fused<<<768, 128, GEMM_SMEM>>>(a16, wqT, bqkv, qh, kvh, rowlist);

    // 2) Tensor-core attention -> fp16 (overwrites g_a16)
    attn_kernel<<<dim3(NBLK, NHEAD, BATCH), 256, ATTN_SMEM_BYTES>>>(
        qh, kvh, mapping, a16);

    // 3) Output projection (fp32 out)
    gemm_proj<<<dim3(DIM / GBN, MROWS / GBM), 128, GEMM_SMEM>>>(
        a16, wpT, bproj, out);
}